// round 1
// baseline (speedup 1.0000x reference)
#include <cuda_runtime.h>
#include <math.h>
#include <stdint.h>

// ---------------- problem constants ----------------
#define Bb    8
#define Cc    512
#define Tt    4096
#define CHK   16
#define Hh    8
#define DHd   64
#define CD    96
#define NBOOK 8
#define NEMB  1024
#define NCH   256
#define MR    (NCH*Bb*CHK)   // 32768 rows (pass A)
#define M2    (NCH*Bb)       // 2048 rows (pass B)

// ---------------- scratch (static device memory; no allocs) ----------------
__device__ float g_pe[Cc*CHK];
__device__ float g_qln[CHK*Cc];
__device__ float g_Qc[CHK*Cc];
__device__ float g_cnorm[NBOOK*NEMB];

__device__ float g_kvin[(size_t)MR*Cc];   // kv LN rows; later reused as xD
__device__ float g_K   [(size_t)MR*Cc];
__device__ float g_V   [(size_t)MR*Cc];
__device__ float g_q   [(size_t)MR*Cc];   // q rows (pre-Wq), residual
__device__ float g_ctx [(size_t)MR*Cc];   // ctx; later reused as LN(y)
__device__ float g_y   [(size_t)MR*Cc];
__device__ float g_h   [(size_t)MR*2*Cc];
__device__ float g_zhat[(size_t)MR*Cc];
__device__ float g_rD  [(size_t)MR*CD];
__device__ float g_qD  [(size_t)MR*CD];
__device__ float g_prev[(size_t)M2*Cc];

__device__ float g_q0  [(size_t)M2*Cc];
__device__ float g_Q0  [(size_t)M2*Cc];
__device__ float g_ctx0[(size_t)M2*Cc];   // ctx0; reused as LN(y0) then xD0
__device__ float g_y0  [(size_t)M2*Cc];
__device__ float g_h0  [(size_t)M2*2*Cc];
__device__ float g_rD0 [(size_t)M2*CD];
__device__ float g_qD0 [(size_t)M2*CD];
__device__ float g_zh0 [(size_t)M2*Cc];

// ---------------- helpers ----------------
__device__ __forceinline__ float geluf(float x) {
    return 0.5f * x * (1.0f + erff(x * 0.70710678118654752440f));
}

// block = 256 threads, row of 512 elems, thread owns elems c0 and c1.
// red must be __shared__ float[8].
__device__ __forceinline__ float2 block_ln2(float x0, float x1, int c0, int c1,
                                            const float* __restrict__ g,
                                            const float* __restrict__ b,
                                            float* red)
{
    int tid = threadIdx.x, lane = tid & 31, w = tid >> 5;
    float s = x0 + x1;
#pragma unroll
    for (int o = 16; o; o >>= 1) s += __shfl_xor_sync(0xffffffffu, s, o);
    if (lane == 0) red[w] = s;
    __syncthreads();
    float tot = 0.f;
#pragma unroll
    for (int i = 0; i < 8; i++) tot += red[i];
    float mean = tot * (1.0f / 512.0f);
    float d0 = x0 - mean, d1 = x1 - mean;
    float q = d0 * d0 + d1 * d1;
#pragma unroll
    for (int o = 16; o; o >>= 1) q += __shfl_xor_sync(0xffffffffu, q, o);
    __syncthreads();
    if (lane == 0) red[w] = q;
    __syncthreads();
    float tot2 = 0.f;
#pragma unroll
    for (int i = 0; i < 8; i++) tot2 += red[i];
    float inv = rsqrtf(tot2 * (1.0f / 512.0f) + 1e-5f);
    return make_float2(d0 * inv * g[c0] + b[c0], d1 * inv * g[c1] + b[c1]);
}

// ---------------- prep kernels ----------------
// grid 16 (one per chunk-local position t), 256 threads
__global__ void prep_pe_qln_k(const float* __restrict__ lnq_g,
                              const float* __restrict__ lnq_b)
{
    __shared__ float red[8];
    int t = blockIdx.x, tid = threadIdx.x;
    int c0 = 2 * tid, c1 = c0 + 1;
    double dv = exp((double)c0 * (-log(10000.0) / 512.0));
    double ang = (double)t * dv;
    float v0 = (float)sin(ang);
    float v1 = (float)cos(ang);
    g_pe[c0 * CHK + t] = v0;
    g_pe[c1 * CHK + t] = v1;
    float2 y = block_ln2(v0, v1, c0, c1, lnq_g, lnq_b, red);
    g_qln[t * Cc + c0] = y.x;
    g_qln[t * Cc + c1] = y.y;
}

// grid 32, 256 threads: 0.5*||emb||^2 per code
__global__ void prep_cnorm_k(const float* __restrict__ books)
{
    int idx = blockIdx.x * 256 + threadIdx.x;   // 0..8191
    const float* e = books + (size_t)idx * CD;
    float s = 0.f;
#pragma unroll
    for (int d = 0; d < CD; d++) { float v = e[d]; s += v * v; }
    g_cnorm[idx] = 0.5f * s;
}

// grid 65536, 256 threads: replicate qln rows into g_q
__global__ void fillq_k()
{
    int idx = blockIdx.x * 256 + threadIdx.x;
    int n = idx >> 9, c = idx & 511;
    int t = n & 15;
    g_q[(size_t)idx] = g_qln[t * Cc + c];
}

// grid MR, 256 threads: kv = LN(qa + pe)
__global__ void kvln_k(const float* __restrict__ qa,
                       const float* __restrict__ g, const float* __restrict__ b)
{
    __shared__ float red[8];
    int n = blockIdx.x, tid = threadIdx.x;
    int s = n >> 7, bb = (n >> 4) & 7, t = n & 15;
    int tg = s * CHK + t;
    int c0 = tid, c1 = tid + 256;
    float x0 = qa[((size_t)(bb * Cc + c0)) * Tt + tg] + g_pe[c0 * CHK + t];
    float x1 = qa[((size_t)(bb * Cc + c1)) * Tt + tg] + g_pe[c1 * CHK + t];
    float2 y = block_ln2(x0, x1, c0, c1, g, b, red);
    g_kvin[(size_t)n * Cc + c0] = y.x;
    g_kvin[(size_t)n * Cc + c1] = y.y;
}

// generic row-LN: grid M, 256 threads
__global__ void ln_rows_k(const float* __restrict__ in, float* __restrict__ out,
                          const float* __restrict__ g, const float* __restrict__ b)
{
    __shared__ float red[8];
    int n = blockIdx.x, tid = threadIdx.x;
    int c0 = tid, c1 = tid + 256;
    float x0 = in[(size_t)n * Cc + c0];
    float x1 = in[(size_t)n * Cc + c1];
    float2 y = block_ln2(x0, x1, c0, c1, g, b, red);
    out[(size_t)n * Cc + c0] = y.x;
    out[(size_t)n * Cc + c1] = y.y;
}

// r = zt - y ; xD = sc * tanh(LN_tn(r)).  Pass A mapping: grid MR
__global__ void residA_k(const float* __restrict__ zt, const float* __restrict__ y,
                         float* __restrict__ xD,
                         const float* __restrict__ g, const float* __restrict__ b,
                         const float* __restrict__ scale)
{
    __shared__ float red[8];
    int n = blockIdx.x, tid = threadIdx.x;
    int s = n >> 7, bb = (n >> 4) & 7, t = n & 15;
    int tg = s * CHK + t;
    float sc = fminf(fmaxf(scale[0], 0.005f), 0.5f);
    int c0 = tid, c1 = tid + 256;
    float x0 = zt[((size_t)(bb * Cc + c0)) * Tt + tg] - y[(size_t)n * Cc + c0];
    float x1 = zt[((size_t)(bb * Cc + c1)) * Tt + tg] - y[(size_t)n * Cc + c1];
    float2 o = block_ln2(x0, x1, c0, c1, g, b, red);
    xD[(size_t)n * Cc + c0] = sc * tanhf(o.x);
    xD[(size_t)n * Cc + c1] = sc * tanhf(o.y);
}

// Pass B variant: grid M2 rows, token 0 of each chunk
__global__ void residB_k(const float* __restrict__ zt, const float* __restrict__ y,
                         float* __restrict__ xD,
                         const float* __restrict__ g, const float* __restrict__ b,
                         const float* __restrict__ scale)
{
    __shared__ float red[8];
    int n = blockIdx.x, tid = threadIdx.x;
    int s = n >> 3, bb = n & 7;
    int tg = s * CHK;
    float sc = fminf(fmaxf(scale[0], 0.005f), 0.5f);
    int c0 = tid, c1 = tid + 256;
    float x0 = zt[((size_t)(bb * Cc + c0)) * Tt + tg] - y[(size_t)n * Cc + c0];
    float x1 = zt[((size_t)(bb * Cc + c1)) * Tt + tg] - y[(size_t)n * Cc + c1];
    float2 o = block_ln2(x0, x1, c0, c1, g, b, red);
    xD[(size_t)n * Cc + c0] = sc * tanhf(o.x);
    xD[(size_t)n * Cc + c1] = sc * tanhf(o.y);
}

// q0 = LN(prev_last[s-1] + pe_0), grid M2
__global__ void q0ln_k(const float* __restrict__ g, const float* __restrict__ b)
{
    __shared__ float red[8];
    int n = blockIdx.x, tid = threadIdx.x;
    int s = n >> 3;
    int c0 = tid, c1 = tid + 256;
    float p0 = (s > 0) ? g_prev[(size_t)(n - Bb) * Cc + c0] : 0.f;
    float p1 = (s > 0) ? g_prev[(size_t)(n - Bb) * Cc + c1] : 0.f;
    float x0 = p0 + g_pe[c0 * CHK + 0];
    float x1 = p1 + g_pe[c1 * CHK + 0];
    float2 y = block_ln2(x0, x1, c0, c1, g, b, red);
    g_q0[(size_t)n * Cc + c0] = y.x;
    g_q0[(size_t)n * Cc + c1] = y.y;
}

// scatter pass A output + harvest prev_last (t==15 rows)
__global__ void scatterA_k(const float* __restrict__ zhat, float* __restrict__ out)
{
    int idx = blockIdx.x * 256 + threadIdx.x;
    int n = idx >> 9, c = idx & 511;
    int s = n >> 7, bb = (n >> 4) & 7, t = n & 15;
    float v = zhat[(size_t)idx];
    out[((size_t)(bb * Cc + c)) * Tt + s * CHK + t] = v;
    if (t == 15) g_prev[(size_t)(n >> 4) * Cc + c] = v;
}

__global__ void scatterB_k(const float* __restrict__ zh0, float* __restrict__ out)
{
    int idx = blockIdx.x * 256 + threadIdx.x;  // M2*512
    int n = idx >> 9, c = idx & 511;
    int s = n >> 3, bb = n & 7;
    out[((size_t)(bb * Cc + c)) * Tt + s * CHK] = zh0[(size_t)idx];
}

// ---------------- GEMM: C[M,N] = A[M,K] @ B (+bias +resid, act) ----------------
// TB=0: B is [K,N]; TB=1: B is [N,K]
#define GBM 128
#define GBN 128
#define GBK 8
template<int TB>
__global__ void __launch_bounds__(256) gemm_k(
    const float* __restrict__ A, const float* __restrict__ Bm,
    float* __restrict__ Cm, const float* __restrict__ bias,
    const float* __restrict__ resid, int M, int N, int K, int act)
{
    __shared__ float As[GBK][GBM];
    __shared__ float Bs[GBK][GBN];
    int tid = threadIdx.x;
    int tx = tid & 15, ty = tid >> 4;
    int m0 = blockIdx.y * GBM, n0 = blockIdx.x * GBN;
    float acc[8][8];
#pragma unroll
    for (int i = 0; i < 8; i++)
#pragma unroll
        for (int j = 0; j < 8; j++) acc[i][j] = 0.f;

    for (int k0 = 0; k0 < K; k0 += GBK) {
#pragma unroll
        for (int l = 0; l < 4; l++) {
            int e = tid + l * 256;
            int kk = e & 7, m = e >> 3;
            int gm = m0 + m;
            As[kk][m] = (gm < M) ? A[(size_t)gm * K + k0 + kk] : 0.f;
        }
        if (TB == 0) {
#pragma unroll
            for (int l = 0; l < 4; l++) {
                int e = tid + l * 256;
                int n = e & 127, kk = e >> 7;
                int gn = n0 + n;
                Bs[kk][n] = (gn < N) ? Bm[(size_t)(k0 + kk) * N + gn] : 0.f;
            }
        } else {
#pragma unroll
            for (int l = 0; l < 4; l++) {
                int e = tid + l * 256;
                int kk = e & 7, n = e >> 3;
                int gn = n0 + n;
                Bs[kk][n] = (gn < N) ? Bm[(size_t)gn * K + k0 + kk] : 0.f;
            }
        }
        __syncthreads();
#pragma unroll
        for (int kk = 0; kk < GBK; kk++) {
            float a[8], b[8];
#pragma unroll
            for (int i = 0; i < 8; i++) a[i] = As[kk][ty * 8 + i];
#pragma unroll
            for (int j = 0; j < 8; j++) b[j] = Bs[kk][tx * 8 + j];
#pragma unroll
            for (int i = 0; i < 8; i++)
#pragma unroll
                for (int j = 0; j < 8; j++) acc[i][j] = fmaf(a[i], b[j], acc[i][j]);
        }
        __syncthreads();
    }

#pragma unroll
    for (int i = 0; i < 8; i++) {
        int m = m0 + ty * 8 + i;
        if (m >= M) continue;
#pragma unroll
        for (int j = 0; j < 8; j++) {
            int n = n0 + tx * 8 + j;
            if (n >= N) continue;
            float v = acc[i][j];
            if (bias)  v += bias[n];
            if (resid) v += resid[(size_t)m * N + n];
            if (act == 1) v = geluf(v);
            Cm[(size_t)m * N + n] = v;
        }
    }
}

// ---------------- attention ----------------
// pass A: one block per (chunk,b); all 16 query rows (Q from g_Qc const rows)
__global__ void __launch_bounds__(256) attnA_k(const float* __restrict__ Kmat,
                                               const float* __restrict__ Vmat,
                                               float* __restrict__ ctx)
{
    __shared__ float sKV[16][514];
    __shared__ float sS[16 * 8 * 16];
    int blk = blockIdx.x, tid = threadIdx.x;
    size_t n0 = (size_t)blk * CHK;

    for (int e = tid; e < 16 * 512; e += 256)
        sKV[e >> 9][e & 511] = Kmat[n0 * Cc + (size_t)(e >> 9) * Cc + (e & 511)];
    __syncthreads();

    { // scores: thread = (t,k)
        int t = tid >> 4, k = tid & 15;
        const float* qrow = g_Qc + t * Cc;
#pragma unroll
        for (int h = 0; h < 8; h++) {
            float s = 0.f;
            const float* kp = &sKV[k][h * 64];
            const float* qp = qrow + h * 64;
#pragma unroll 16
            for (int d = 0; d < 64; d++) s = fmaf(qp[d], kp[d], s);
            sS[(t * 8 + h) * 16 + k] = s * 0.125f;
        }
    }
    __syncthreads();
    if (tid < 128) { // softmax per (t,h)
        float* p = &sS[tid * 16];
        float m = p[0];
#pragma unroll
        for (int k = 1; k < 16; k++) m = fmaxf(m, p[k]);
        float sum = 0.f;
#pragma unroll
        for (int k = 0; k < 16; k++) { float e = expf(p[k] - m); p[k] = e; sum += e; }
        float inv = 1.0f / sum;
#pragma unroll
        for (int k = 0; k < 16; k++) p[k] *= inv;
    }
    __syncthreads();
    for (int e = tid; e < 16 * 512; e += 256)
        sKV[e >> 9][e & 511] = Vmat[n0 * Cc + (size_t)(e >> 9) * Cc + (e & 511)];
    __syncthreads();

#pragma unroll
    for (int cc = 0; cc < 2; cc++) {
        int c = tid + cc * 256;
        int h = c >> 6;
#pragma unroll
        for (int t = 0; t < 16; t++) {
            float a = 0.f;
            const float* at = &sS[(t * 8 + h) * 16];
#pragma unroll
            for (int k = 0; k < 16; k++) a = fmaf(at[k], sKV[k][c], a);
            ctx[(n0 + t) * Cc + c] = a;
        }
    }
}

// pass B: one block per (chunk,b); only query row 0 (Q from g_Q0 per row)
__global__ void __launch_bounds__(256) attnB_k(const float* __restrict__ Kmat,
                                               const float* __restrict__ Vmat,
                                               float* __restrict__ ctx0)
{
    __shared__ float sKV[16][514];
    __shared__ float sS[8 * 16];
    int blk = blockIdx.x, tid = threadIdx.x;
    size_t n0 = (size_t)blk * CHK;

    for (int e = tid; e < 16 * 512; e += 256)
        sKV[e >> 9][e & 511] = Kmat[n0 * Cc + (size_t)(e >> 9) * Cc + (e & 511)];
    __syncthreads();

    if (tid < 128) {
        int h = tid >> 4, k = tid & 15;
        const float* qp = g_Q0 + (size_t)blk * Cc + h * 64;
        const float* kp = &sKV[k][h * 64];
        float s = 0.f;
#pragma unroll 16
        for (int d = 0; d < 64; d++) s = fmaf(qp[d], kp[d], s);
        sS[h * 16 + k] = s * 0.125f;
    }
    __syncthreads();
    if (tid < 8) {
        float* p = &sS[tid * 16];
        float m = p[0];
#pragma unroll
        for (int k = 1; k < 16; k++) m = fmaxf(m, p[k]);
        float sum = 0.f;
#pragma unroll
        for (int k = 0; k < 16; k++) { float e = expf(p[k] - m); p[k] = e; sum += e; }
        float inv = 1.0f / sum;
#pragma unroll
        for (int k = 0; k < 16; k++) p[k] *= inv;
    }
    __syncthreads();
    for (int e = tid; e < 16 * 512; e += 256)
        sKV[e >> 9][e & 511] = Vmat[n0 * Cc + (size_t)(e >> 9) * Cc + (e & 511)];
    __syncthreads();

#pragma unroll
    for (int cc = 0; cc < 2; cc++) {
        int c = tid + cc * 256;
        int h = c >> 6;
        float a = 0.f;
        const float* at = &sS[h * 16];
#pragma unroll
        for (int k = 0; k < 16; k++) a = fmaf(at[k], sKV[k][c], a);
        ctx0[(size_t)blk * Cc + c] = a;
    }
}

// ---------------- residual VQ: 32 rows/block, 256 threads ----------------
__global__ void __launch_bounds__(256) rvq_k(const float* __restrict__ rD,
                                             float* __restrict__ qD,
                                             const float* __restrict__ books)
{
    extern __shared__ float sm[];
    float* sRes   = sm;                 // 32*97
    float* sE     = sRes + 32 * 97;     // 128*97
    float* sHN    = sE + 128 * 97;      // 128
    float* sScore = sHN + 128;          // 32*32
    int*   sIdx   = (int*)(sScore + 32 * 32); // 32*32
    int*   sBest  = sIdx + 32 * 32;     // 32

    int tid = threadIdx.x;
    int tr = tid >> 5;   // 0..7  -> rows tr*4 .. tr*4+3
    int tc = tid & 31;   // 0..31 -> codes tc + 32*j
    int m0 = blockIdx.x * 32;

    for (int e = tid; e < 32 * 96; e += 256) {
        int r = e / 96, d = e - r * 96;
        sRes[r * 97 + d] = rD[(size_t)(m0 + r) * CD + d];
    }

    for (int k = 0; k < NBOOK; k++) {
        float best[4]; int bidx[4];
#pragma unroll
        for (int i = 0; i < 4; i++) { best[i] = -3.0e38f; bidx[i] = 0; }

        for (int tile = 0; tile < 8; tile++) {
            __syncthreads();
            const float* bk = books + ((size_t)k * NEMB + tile * 128) * CD;
            for (int e = tid; e < 128 * 96; e += 256) {
                int c = e / 96, d = e - c * 96;
                sE[c * 97 + d] = bk[(size_t)c * CD + d];
            }
            if (tid < 128) sHN[tid] = g_cnorm[k * NEMB + tile * 128 + tid];
            __syncthreads();

            float acc[4][4];
#pragma unroll
            for (int i = 0; i < 4; i++)
#pragma unroll
                for (int j = 0; j < 4; j++) acc[i][j] = 0.f;
            const float* r0p = &sRes[(tr * 4) * 97];
#pragma unroll 4
            for (int d = 0; d < 96; d++) {
                float a0 = r0p[0 * 97 + d], a1 = r0p[1 * 97 + d];
                float a2 = r0p[2 * 97 + d], a3 = r0p[3 * 97 + d];
#pragma unroll
                for (int j = 0; j < 4; j++) {
                    float bv = sE[(tc + 32 * j) * 97 + d];
                    acc[0][j] = fmaf(a0, bv, acc[0][j]);
                    acc[1][j] = fmaf(a1, bv, acc[1][j]);
                    acc[2][j] = fmaf(a2, bv, acc[2][j]);
                    acc[3][j] = fmaf(a3, bv, acc[3][j]);
                }
            }
#pragma unroll
            for (int i = 0; i < 4; i++)
#pragma unroll
                for (int j = 0; j < 4; j++) {
                    float sc = acc[i][j] - sHN[tc + 32 * j];
                    int code = tile * 128 + tc + 32 * j;
                    if (sc > best[i] || (sc == best[i] && code < bidx[i])) {
                        best[i] = sc; bidx[i] = code;
                    }
                }
        }
        __syncthreads();
#pragma unroll
        for (int i = 0; i < 4; i++) {
            sScore[(tr * 4 + i) * 32 + tc] = best[i];
            sIdx  [(tr * 4 + i) * 32 + tc] = bidx[i];
        }
        __syncthreads();
        if (tid < 32) {
            float bs = -3.0e38f; int bi = 0x7fffffff;
            for (int u = 0; u < 32; u++) {
                float s = sScore[tid * 32 + u]; int ii = sIdx[tid * 32 + u];
                if (s > bs || (s == bs && ii < bi)) { bs = s; bi = ii; }
            }
            sBest[tid] = bi;
        }
        __syncthreads();
        const float* bkb = books + (size_t)k * NEMB * CD;
        for (int e = tid; e < 32 * 96; e += 256) {
            int r = e / 96, d = e - r * 96;
            sRes[r * 97 + d] -= bkb[(size_t)sBest[r] * CD + d];
        }
    }
    __syncthreads();
    for (int e = tid; e < 32 * 96; e += 256) {
        int r = e / 96, d = e - r * 96;
        qD[(size_t)(m0 + r) * CD + d] =
            rD[(size_t)(m0 + r) * CD + d] - sRes[r * 97 + d];
    }
}

// ---------------- host side ----------------
static void gemm(const float* A, const float* Bm, float* Cm, const float* bias,
                 const float* resid, int M, int N, int K, int act, bool tb)
{
    dim3 grid((N + GBN - 1) / GBN, (M + GBM - 1) / GBM);
    if (tb) gemm_k<1><<<grid, 256>>>(A, Bm, Cm, bias, resid, M, N, K, act);
    else    gemm_k<0><<<grid, 256>>>(A, Bm, Cm, bias, resid, M, N, K, act);
}

template<typename T>
static T* sym(const void* s) { void* p = nullptr; cudaGetSymbolAddress(&p, s); return (T*)p; }

extern "C" void kernel_launch(void* const* d_in, const int* in_sizes, int n_in,
                              void* d_out, int out_size)
{
    const float* qa    = (const float*)d_in[0];
    const float* zt    = (const float*)d_in[1];
    const float* lnq_g = (const float*)d_in[2];
    const float* lnq_b = (const float*)d_in[3];
    const float* lnkv_g= (const float*)d_in[4];
    const float* lnkv_b= (const float*)d_in[5];
    const float* Wq    = (const float*)d_in[6];
    const float* Wk    = (const float*)d_in[7];
    const float* Wv    = (const float*)d_in[8];
    const float* Wo    = (const float*)d_in[9];
    const float* ffn_g = (const float*)d_in[10];
    const float* ffn_b = (const float*)d_in[11];
    const float* W1    = (const float*)d_in[12];
    const float* b1    = (const float*)d_in[13];
    const float* W2    = (const float*)d_in[14];
    const float* b2    = (const float*)d_in[15];
    const float* tn_g  = (const float*)d_in[16];
    const float* tn_b  = (const float*)d_in[17];
    const float* scale = (const float*)d_in[18];
    const float* Wd    = (const float*)d_in[19];
    const float* bd    = (const float*)d_in[20];
    const float* Wu    = (const float*)d_in[21];
    const float* bu    = (const float*)d_in[22];
    const float* books = (const float*)d_in[23];
    float* out = (float*)d_out;

    float* p_kvin = sym<float>(g_kvin);
    float* p_K    = sym<float>(g_K);
    float* p_V    = sym<float>(g_V);
    float* p_q    = sym<float>(g_q);
    float* p_ctx  = sym<float>(g_ctx);
    float* p_y    = sym<float>(g_y);
    float* p_h    = sym<float>(g_h);
    float* p_zhat = sym<float>(g_zhat);
    float* p_rD   = sym<float>(g_rD);
    float* p_qD   = sym<float>(g_qD);
    float* p_qln  = sym<float>(g_qln);
    float* p_Qc   = sym<float>(g_Qc);
    float* p_q0   = sym<float>(g_q0);
    float* p_Q0   = sym<float>(g_Q0);
    float* p_ctx0 = sym<float>(g_ctx0);
    float* p_y0   = sym<float>(g_y0);
    float* p_h0   = sym<float>(g_h0);
    float* p_rD0  = sym<float>(g_rD0);
    float* p_qD0  = sym<float>(g_qD0);
    float* p_zh0  = sym<float>(g_zh0);

    size_t rvq_smem = (size_t)(32 * 97 + 128 * 97 + 128 + 32 * 32) * 4
                    + (size_t)(32 * 32 + 32) * 4;
    cudaFuncSetAttribute(rvq_k, cudaFuncAttributeMaxDynamicSharedMemorySize,
                         (int)rvq_smem);

    // ---- prep ----
    prep_pe_qln_k<<<16, 256>>>(lnq_g, lnq_b);
    prep_cnorm_k<<<32, 256>>>(books);
    fillq_k<<<MR * Cc / 256, 256>>>();
    kvln_k<<<MR, 256>>>(qa, lnkv_g, lnkv_b);

    // ---- pass A ----
    gemm(p_qln, Wq, p_Qc, nullptr, nullptr, 16, 512, 512, 0, false);
    gemm(p_kvin, Wk, p_K, nullptr, nullptr, MR, 512, 512, 0, false);
    gemm(p_kvin, Wv, p_V, nullptr, nullptr, MR, 512, 512, 0, false);
    attnA_k<<<M2, 256>>>(p_K, p_V, p_ctx);
    gemm(p_ctx, Wo, p_y, nullptr, p_q, MR, 512, 512, 0, false);
    ln_rows_k<<<MR, 256>>>(p_y, p_ctx, ffn_g, ffn_b);
    gemm(p_ctx, W1, p_h, b1, nullptr, MR, 1024, 512, 1, false);
    gemm(p_h, W2, p_y, b2, p_y, MR, 512, 1024, 0, false);
    residA_k<<<MR, 256>>>(zt, p_y, p_kvin, tn_g, tn_b, scale);
    gemm(p_kvin, Wd, p_rD, bd, nullptr, MR, 96, 512, 0, true);
    rvq_k<<<MR / 32, 256, rvq_smem>>>(p_rD, p_qD, books);
    gemm(p_qD, Wu, p_zhat, bu, p_y, MR, 512, 96, 0, true);
    scatterA_k<<<MR * Cc / 256, 256>>>(p_zhat, out);

    // ---- pass B (token 0 of every chunk, using prev_last from pass A) ----
    q0ln_k<<<M2, 256>>>(lnq_g, lnq_b);
    gemm(p_q0, Wq, p_Q0, nullptr, nullptr, M2, 512, 512, 0, false);
    attnB_k<<<M2, 256>>>(p_K, p_V, p_ctx0);
    gemm(p_ctx0, Wo, p_y0, nullptr, p_q0, M2, 512, 512, 0, false);
    ln_rows_k<<<M2, 256>>>(p_y0, p_ctx0, ffn_g, ffn_b);
    gemm(p_ctx0, W1, p_h0, b1, nullptr, M2, 1024, 512, 1, false);
    gemm(p_h0, W2, p_y0, b2, p_y0, M2, 512, 1024, 0, false);
    residB_k<<<M2, 256>>>(zt, p_y0, p_ctx0, tn_g, tn_b, scale);
    gemm(p_ctx0, Wd, p_rD0, bd, nullptr, M2, 96, 512, 0, true);
    rvq_k<<<M2 / 32, 256, rvq_smem>>>(p_rD0, p_qD0, books);
    gemm(p_qD0, Wu, p_zh0, bu, p_y0, M2, 512, 96, 0, true);
    scatterB_k<<<M2 * Cc / 256, 256>>>(p_zh0, out);
}

// round 4
// speedup vs baseline: 1.0388x; 1.0388x over previous
#include <cuda_runtime.h>
#include <math.h>
#include <stdint.h>

// ---------------- problem constants ----------------
#define Bb    8
#define Cc    512
#define Tt    4096
#define CHK   16
#define Hh    8
#define DHd   64
#define CD    96
#define NBOOK 8
#define NEMB  1024
#define NCH   256
#define MR    (NCH*Bb*CHK)   // 32768 rows (pass A)
#define M2    (NCH*Bb)       // 2048 rows (pass B)

// ---------------- scratch (static device memory; no allocs) ----------------
__device__ float g_pe[Cc*CHK];
__device__ float g_qln[CHK*Cc];
__device__ float g_Qc[CHK*Cc];
__device__ float g_cnorm[NBOOK*NEMB];

__device__ float g_kvin[(size_t)MR*Cc];   // kv LN rows; later reused as xD
__device__ float g_K   [(size_t)MR*Cc];
__device__ float g_V   [(size_t)MR*Cc];
__device__ float g_q   [(size_t)MR*Cc];   // q rows (pre-Wq), residual
__device__ float g_ctx [(size_t)MR*Cc];   // ctx; later reused as LN(y)
__device__ float g_y   [(size_t)MR*Cc];
__device__ float g_h   [(size_t)MR*2*Cc];
__device__ float g_zhat[(size_t)MR*Cc];
__device__ float g_rD  [(size_t)MR*CD];
__device__ float g_qD  [(size_t)MR*CD];
__device__ float g_prev[(size_t)M2*Cc];

__device__ float g_q0  [(size_t)M2*Cc];
__device__ float g_Q0  [(size_t)M2*Cc];
__device__ float g_ctx0[(size_t)M2*Cc];
__device__ float g_y0  [(size_t)M2*Cc];
__device__ float g_h0  [(size_t)M2*2*Cc];
__device__ float g_rD0 [(size_t)M2*CD];
__device__ float g_qD0 [(size_t)M2*CD];
__device__ float g_zh0 [(size_t)M2*Cc];

// ---------------- helpers ----------------
__device__ __forceinline__ float geluf(float x) {
    return 0.5f * x * (1.0f + erff(x * 0.70710678118654752440f));
}

__device__ __forceinline__ uint32_t f2tf32(float v) {
    uint32_t o;
    asm("cvt.rna.tf32.f32 %0, %1;" : "=r"(o) : "f"(v));
    return o;
}

__device__ __forceinline__ void mma_tf32(float* c, const uint32_t* a, const uint32_t* b) {
    asm volatile(
        "mma.sync.aligned.m16n8k8.row.col.f32.tf32.tf32.f32 "
        "{%0,%1,%2,%3}, {%4,%5,%6,%7}, {%8,%9}, {%0,%1,%2,%3};"
        : "+f"(c[0]), "+f"(c[1]), "+f"(c[2]), "+f"(c[3])
        : "r"(a[0]), "r"(a[1]), "r"(a[2]), "r"(a[3]), "r"(b[0]), "r"(b[1]));
}

// block = 256 threads, row of 512 elems, thread owns elems c0 and c1.
__device__ __forceinline__ float2 block_ln2(float x0, float x1, int c0, int c1,
                                            const float* __restrict__ g,
                                            const float* __restrict__ b,
                                            float* red)
{
    int tid = threadIdx.x, lane = tid & 31, w = tid >> 5;
    float s = x0 + x1;
#pragma unroll
    for (int o = 16; o; o >>= 1) s += __shfl_xor_sync(0xffffffffu, s, o);
    if (lane == 0) red[w] = s;
    __syncthreads();
    float tot = 0.f;
#pragma unroll
    for (int i = 0; i < 8; i++) tot += red[i];
    float mean = tot * (1.0f / 512.0f);
    float d0 = x0 - mean, d1 = x1 - mean;
    float q = d0 * d0 + d1 * d1;
#pragma unroll
    for (int o = 16; o; o >>= 1) q += __shfl_xor_sync(0xffffffffu, q, o);
    __syncthreads();
    if (lane == 0) red[w] = q;
    __syncthreads();
    float tot2 = 0.f;
#pragma unroll
    for (int i = 0; i < 8; i++) tot2 += red[i];
    float inv = rsqrtf(tot2 * (1.0f / 512.0f) + 1e-5f);
    return make_float2(d0 * inv * g[c0] + b[c0], d1 * inv * g[c1] + b[c1]);
}

// ---------------- prep kernels ----------------
__global__ void prep_pe_qln_k(const float* __restrict__ lnq_g,
                              const float* __restrict__ lnq_b)
{
    __shared__ float red[8];
    int t = blockIdx.x, tid = threadIdx.x;
    int c0 = 2 * tid, c1 = c0 + 1;
    double dv = exp((double)c0 * (-log(10000.0) / 512.0));
    double ang = (double)t * dv;
    float v0 = (float)sin(ang);
    float v1 = (float)cos(ang);
    g_pe[c0 * CHK + t] = v0;
    g_pe[c1 * CHK + t] = v1;
    float2 y = block_ln2(v0, v1, c0, c1, lnq_g, lnq_b, red);
    g_qln[t * Cc + c0] = y.x;
    g_qln[t * Cc + c1] = y.y;
}

__global__ void prep_cnorm_k(const float* __restrict__ books)
{
    int idx = blockIdx.x * 256 + threadIdx.x;   // 0..8191
    const float* e = books + (size_t)idx * CD;
    float s = 0.f;
#pragma unroll
    for (int d = 0; d < CD; d++) { float v = e[d]; s += v * v; }
    g_cnorm[idx] = 0.5f * s;
}

__global__ void fillq_k()
{
    int idx = blockIdx.x * 256 + threadIdx.x;
    int n = idx >> 9, c = idx & 511;
    int t = n & 15;
    g_q[(size_t)idx] = g_qln[t * Cc + c];
}

__global__ void kvln_k(const float* __restrict__ qa,
                       const float* __restrict__ g, const float* __restrict__ b)
{
    __shared__ float red[8];
    int n = blockIdx.x, tid = threadIdx.x;
    int s = n >> 7, bb = (n >> 4) & 7, t = n & 15;
    int tg = s * CHK + t;
    int c0 = tid, c1 = tid + 256;
    float x0 = qa[((size_t)(bb * Cc + c0)) * Tt + tg] + g_pe[c0 * CHK + t];
    float x1 = qa[((size_t)(bb * Cc + c1)) * Tt + tg] + g_pe[c1 * CHK + t];
    float2 y = block_ln2(x0, x1, c0, c1, g, b, red);
    g_kvin[(size_t)n * Cc + c0] = y.x;
    g_kvin[(size_t)n * Cc + c1] = y.y;
}

__global__ void ln_rows_k(const float* __restrict__ in, float* __restrict__ out,
                          const float* __restrict__ g, const float* __restrict__ b)
{
    __shared__ float red[8];
    int n = blockIdx.x, tid = threadIdx.x;
    int c0 = tid, c1 = tid + 256;
    float x0 = in[(size_t)n * Cc + c0];
    float x1 = in[(size_t)n * Cc + c1];
    float2 y = block_ln2(x0, x1, c0, c1, g, b, red);
    out[(size_t)n * Cc + c0] = y.x;
    out[(size_t)n * Cc + c1] = y.y;
}

__global__ void residA_k(const float* __restrict__ zt, const float* __restrict__ y,
                         float* __restrict__ xD,
                         const float* __restrict__ g, const float* __restrict__ b,
                         const float* __restrict__ scale)
{
    __shared__ float red[8];
    int n = blockIdx.x, tid = threadIdx.x;
    int s = n >> 7, bb = (n >> 4) & 7, t = n & 15;
    int tg = s * CHK + t;
    float sc = fminf(fmaxf(scale[0], 0.005f), 0.5f);
    int c0 = tid, c1 = tid + 256;
    float x0 = zt[((size_t)(bb * Cc + c0)) * Tt + tg] - y[(size_t)n * Cc + c0];
    float x1 = zt[((size_t)(bb * Cc + c1)) * Tt + tg] - y[(size_t)n * Cc + c1];
    float2 o = block_ln2(x0, x1, c0, c1, g, b, red);
    xD[(size_t)n * Cc + c0] = sc * tanhf(o.x);
    xD[(size_t)n * Cc + c1] = sc * tanhf(o.y);
}

__global__ void residB_k(const float* __restrict__ zt, const float* __restrict__ y,
                         float* __restrict__ xD,
                         const float* __restrict__ g, const float* __restrict__ b,
                         const float* __restrict__ scale)
{
    __shared__ float red[8];
    int n = blockIdx.x, tid = threadIdx.x;
    int s = n >> 3, bb = n & 7;
    int tg = s * CHK;
    float sc = fminf(fmaxf(scale[0], 0.005f), 0.5f);
    int c0 = tid, c1 = tid + 256;
    float x0 = zt[((size_t)(bb * Cc + c0)) * Tt + tg] - y[(size_t)n * Cc + c0];
    float x1 = zt[((size_t)(bb * Cc + c1)) * Tt + tg] - y[(size_t)n * Cc + c1];
    float2 o = block_ln2(x0, x1, c0, c1, g, b, red);
    xD[(size_t)n * Cc + c0] = sc * tanhf(o.x);
    xD[(size_t)n * Cc + c1] = sc * tanhf(o.y);
}

__global__ void q0ln_k(const float* __restrict__ g, const float* __restrict__ b)
{
    __shared__ float red[8];
    int n = blockIdx.x, tid = threadIdx.x;
    int s = n >> 3;
    int c0 = tid, c1 = tid + 256;
    float p0 = (s > 0) ? g_prev[(size_t)(n - Bb) * Cc + c0] : 0.f;
    float p1 = (s > 0) ? g_prev[(size_t)(n - Bb) * Cc + c1] : 0.f;
    float x0 = p0 + g_pe[c0 * CHK + 0];
    float x1 = p1 + g_pe[c1 * CHK + 0];
    float2 y = block_ln2(x0, x1, c0, c1, g, b, red);
    g_q0[(size_t)n * Cc + c0] = y.x;
    g_q0[(size_t)n * Cc + c1] = y.y;
}

__global__ void scatterA_k(const float* __restrict__ zhat, float* __restrict__ out)
{
    int idx = blockIdx.x * 256 + threadIdx.x;
    int n = idx >> 9, c = idx & 511;
    int s = n >> 7, bb = (n >> 4) & 7, t = n & 15;
    float v = zhat[(size_t)idx];
    out[((size_t)(bb * Cc + c)) * Tt + s * CHK + t] = v;
    if (t == 15) g_prev[(size_t)(n >> 4) * Cc + c] = v;
}

__global__ void scatterB_k(const float* __restrict__ zh0, float* __restrict__ out)
{
    int idx = blockIdx.x * 256 + threadIdx.x;  // M2*512
    int n = idx >> 9, c = idx & 511;
    int s = n >> 3, bb = n & 7;
    out[((size_t)(bb * Cc + c)) * Tt + s * CHK] = zh0[(size_t)idx];
}

// ---------------- split-tf32 (3xTF32) tensor-core GEMM ----------------
// C[M,N] = A[M,K] @ B (+bias +resid, act). TB=0: B is [K,N]; TB=1: B is [N,K].
// Each fp32 value split into hi=tf32(x), lo=tf32(x-hi); product via
// Ah*Bh + Ah*Bl + Al*Bh -> ~fp32 accuracy on the tensor pipe.
// Tile 128x128x16; 256 threads = 8 warps; warp computes 64x32 via m16n8k8.
#define TBM 128
#define TBN 128
#define TBK 16
template<int TB>
__global__ void __launch_bounds__(256) gemm_tc_k(
    const float* __restrict__ A, const float* __restrict__ Bm,
    float* __restrict__ Cm, const float* __restrict__ bias,
    const float* __restrict__ resid, int M, int N, int K, int act)
{
    __shared__ uint32_t Ah[TBM][20];
    __shared__ uint32_t Al[TBM][20];
    __shared__ uint32_t Bh[TBK][136];
    __shared__ uint32_t Bl[TBK][136];

    int tid = threadIdx.x;
    int wid = tid >> 5, lane = tid & 31;
    int g = lane >> 2, tg = lane & 3;
    int wm = (wid >> 2) * 64, wn = (wid & 3) * 32;
    int m0 = blockIdx.y * TBM, n0 = blockIdx.x * TBN;

    float acc[4][4][4];
#pragma unroll
    for (int i = 0; i < 4; i++)
#pragma unroll
        for (int j = 0; j < 4; j++)
#pragma unroll
            for (int r = 0; r < 4; r++) acc[i][j][r] = 0.f;

    for (int k0 = 0; k0 < K; k0 += TBK) {
        // stage A (128x16)
#pragma unroll
        for (int l = 0; l < 8; l++) {
            int e = tid + l * 256;
            int kk = e & 15, m = e >> 4;
            int gm = m0 + m;
            float v = (gm < M) ? A[(size_t)gm * K + k0 + kk] : 0.f;
            uint32_t hi = f2tf32(v);
            Ah[m][kk] = hi;
            Al[m][kk] = f2tf32(v - __uint_as_float(hi));
        }
        // stage B (16x128)
        if (TB == 0) {
#pragma unroll
            for (int l = 0; l < 8; l++) {
                int e = tid + l * 256;
                int n = e & 127, kk = e >> 7;
                int gn = n0 + n;
                float v = (gn < N) ? Bm[(size_t)(k0 + kk) * N + gn] : 0.f;
                uint32_t hi = f2tf32(v);
                Bh[kk][n] = hi;
                Bl[kk][n] = f2tf32(v - __uint_as_float(hi));
            }
        } else {
#pragma unroll
            for (int l = 0; l < 8; l++) {
                int e = tid + l * 256;
                int kk = e & 15, n = e >> 4;
                int gn = n0 + n;
                float v = (gn < N) ? Bm[(size_t)gn * K + k0 + kk] : 0.f;
                uint32_t hi = f2tf32(v);
                Bh[kk][n] = hi;
                Bl[kk][n] = f2tf32(v - __uint_as_float(hi));
            }
        }
        __syncthreads();

#pragma unroll
        for (int ks = 0; ks < 2; ks++) {
            uint32_t ah[4][4], al[4][4], bh[4][2], bl[4][2];
#pragma unroll
            for (int mf = 0; mf < 4; mf++) {
                int row = wm + mf * 16;
                ah[mf][0] = Ah[row + g][ks * 8 + tg];
                ah[mf][1] = Ah[row + g + 8][ks * 8 + tg];
                ah[mf][2] = Ah[row + g][ks * 8 + tg + 4];
                ah[mf][3] = Ah[row + g + 8][ks * 8 + tg + 4];
                al[mf][0] = Al[row + g][ks * 8 + tg];
                al[mf][1] = Al[row + g + 8][ks * 8 + tg];
                al[mf][2] = Al[row + g][ks * 8 + tg + 4];
                al[mf][3] = Al[row + g + 8][ks * 8 + tg + 4];
            }
#pragma unroll
            for (int nf = 0; nf < 4; nf++) {
                int nn = wn + nf * 8 + g;
                bh[nf][0] = Bh[ks * 8 + tg][nn];
                bh[nf][1] = Bh[ks * 8 + tg + 4][nn];
                bl[nf][0] = Bl[ks * 8 + tg][nn];
                bl[nf][1] = Bl[ks * 8 + tg + 4][nn];
            }
#pragma unroll
            for (int mf = 0; mf < 4; mf++)
#pragma unroll
                for (int nf = 0; nf < 4; nf++) {
                    mma_tf32(acc[mf][nf], ah[mf], bl[nf]);
                    mma_tf32(acc[mf][nf], al[mf], bh[nf]);
                    mma_tf32(acc[mf][nf], ah[mf], bh[nf]);
                }
        }
        __syncthreads();
    }

    // epilogue
#pragma unroll
    for (int mf = 0; mf < 4; mf++) {
        int mA = m0 + wm + mf * 16 + g;
        int mB = mA + 8;
#pragma unroll
        for (int nf = 0; nf < 4; nf++) {
            int nc = n0 + wn + nf * 8 + 2 * tg;
#pragma unroll
            for (int half = 0; half < 2; half++) {
                int m = half ? mB : mA;
                if (m >= M) continue;
                float v0 = acc[mf][nf][half * 2 + 0];
                float v1 = acc[mf][nf][half * 2 + 1];
                if (nc < N) {
                    if (bias)  v0 += bias[nc];
                    if (resid) v0 += resid[(size_t)m * N + nc];
                    if (act == 1) v0 = geluf(v0);
                    Cm[(size_t)m * N + nc] = v0;
                }
                if (nc + 1 < N) {
                    if (bias)  v1 += bias[nc + 1];
                    if (resid) v1 += resid[(size_t)m * N + nc + 1];
                    if (act == 1) v1 = geluf(v1);
                    Cm[(size_t)m * N + nc + 1] = v1;
                }
            }
        }
    }
}

// ---------------- attention ----------------
__global__ void __launch_bounds__(256) attnA_k(const float* __restrict__ Kmat,
                                               const float* __restrict__ Vmat,
                                               float* __restrict__ ctx)
{
    __shared__ float sKV[16][514];
    __shared__ float sS[16 * 8 * 16];
    int blk = blockIdx.x, tid = threadIdx.x;
    size_t n0 = (size_t)blk * CHK;

    for (int e = tid; e < 16 * 512; e += 256)
        sKV[e >> 9][e & 511] = Kmat[n0 * Cc + (size_t)(e >> 9) * Cc + (e & 511)];
    __syncthreads();

    {
        int t = tid >> 4, k = tid & 15;
        const float* qrow = g_Qc + t * Cc;
#pragma unroll
        for (int h = 0; h < 8; h++) {
            float s = 0.f;
            const float* kp = &sKV[k][h * 64];
            const float* qp = qrow + h * 64;
#pragma unroll 16
            for (int d = 0; d < 64; d++) s = fmaf(qp[d], kp[d], s);
            sS[(t * 8 + h) * 16 + k] = s * 0.125f;
        }
    }
    __syncthreads();
    if (tid < 128) {
        float* p = &sS[tid * 16];
        float m = p[0];
#pragma unroll
        for (int k = 1; k < 16; k++) m = fmaxf(m, p[k]);
        float sum = 0.f;
#pragma unroll
        for (int k = 0; k < 16; k++) { float e = expf(p[k] - m); p[k] = e; sum += e; }
        float inv = 1.0f / sum;
#pragma unroll
        for (int k = 0; k < 16; k++) p[k] *= inv;
    }
    __syncthreads();
    for (int e = tid; e < 16 * 512; e += 256)
        sKV[e >> 9][e & 511] = Vmat[n0 * Cc + (size_t)(e >> 9) * Cc + (e & 511)];
    __syncthreads();

#pragma unroll
    for (int cc = 0; cc < 2; cc++) {
        int c = tid + cc * 256;
        int h = c >> 6;
#pragma unroll
        for (int t = 0; t < 16; t++) {
            float a = 0.f;
            const float* at = &sS[(t * 8 + h) * 16];
#pragma unroll
            for (int k = 0; k < 16; k++) a = fmaf(at[k], sKV[k][c], a);
            ctx[(n0 + t) * Cc + c] = a;
        }
    }
}

__global__ void __launch_bounds__(256) attnB_k(const float* __restrict__ Kmat,
                                               const float* __restrict__ Vmat,
                                               float* __restrict__ ctx0)
{
    __shared__ float sKV[16][514];
    __shared__ float sS[8 * 16];
    int blk = blockIdx.x, tid = threadIdx.x;
    size_t n0 = (size_t)blk * CHK;

    for (int e = tid; e < 16 * 512; e += 256)
        sKV[e >> 9][e & 511] = Kmat[n0 * Cc + (size_t)(e >> 9) * Cc + (e & 511)];
    __syncthreads();

    if (tid < 128) {
        int h = tid >> 4, k = tid & 15;
        const float* qp = g_Q0 + (size_t)blk * Cc + h * 64;
        const float* kp = &sKV[k][h * 64];
        float s = 0.f;
#pragma unroll 16
        for (int d = 0; d < 64; d++) s = fmaf(qp[d], kp[d], s);
        sS[h * 16 + k] = s * 0.125f;
    }
    __syncthreads();
    if (tid < 8) {
        float* p = &sS[tid * 16];
        float m = p[0];
#pragma unroll
        for (int k = 1; k < 16; k++) m = fmaxf(m, p[k]);
        float sum = 0.f;
#pragma unroll
        for (int k = 0; k < 16; k++) { float e = expf(p[k] - m); p[k] = e; sum += e; }
        float inv = 1.0f / sum;
#pragma unroll
        for (int k = 0; k < 16; k++) p[k] *= inv;
    }
    __syncthreads();
    for (int e = tid; e < 16 * 512; e += 256)
        sKV[e >> 9][e & 511] = Vmat[n0 * Cc + (size_t)(e >> 9) * Cc + (e & 511)];
    __syncthreads();

#pragma unroll
    for (int cc = 0; cc < 2; cc++) {
        int c = tid + cc * 256;
        int h = c >> 6;
        float a = 0.f;
        const float* at = &sS[h * 16];
#pragma unroll
        for (int k = 0; k < 16; k++) a = fmaf(at[k], sKV[k][c], a);
        ctx0[(size_t)blk * Cc + c] = a;
    }
}

// ---------------- residual VQ: 64 rows/block, 256 threads ----------------
__global__ void __launch_bounds__(256) rvq_k(const float* __restrict__ rD,
                                             float* __restrict__ qD,
                                             const float* __restrict__ books)
{
    extern __shared__ float sm[];
    float* sRes   = sm;                 // 64*97
    float* sE     = sRes + 64 * 97;     // 128*97
    float* sHN    = sE + 128 * 97;      // 128
    float* sScore = sHN + 128;          // 64*32
    int*   sIdx   = (int*)(sScore + 64 * 32); // 64*32
    int*   sBest  = sIdx + 64 * 32;     // 64

    int tid = threadIdx.x;
    int tr = tid >> 5;   // 0..7  -> rows tr*8 .. tr*8+7
    int tc = tid & 31;   // 0..31 -> codes tc + 32*j
    int m0 = blockIdx.x * 64;

    for (int e = tid; e < 64 * 96; e += 256) {
        int r = e / 96, d = e - r * 96;
        sRes[r * 97 + d] = rD[(size_t)(m0 + r) * CD + d];
    }

    for (int k = 0; k < NBOOK; k++) {
        float best[8]; int bidx[8];
#pragma unroll
        for (int i = 0; i < 8; i++) { best[i] = -3.0e38f; bidx[i] = 0; }

        for (int tile = 0; tile < 8; tile++) {
            __syncthreads();
            const float* bk = books + ((size_t)k * NEMB + tile * 128) * CD;
            for (int e = tid; e < 128 * 96; e += 256) {
                int c = e / 96, d = e - c * 96;
                sE[c * 97 + d] = bk[(size_t)c * CD + d];
            }
            if (tid < 128) sHN[tid] = g_cnorm[k * NEMB + tile * 128 + tid];
            __syncthreads();

            float acc[8][4];
#pragma unroll
            for (int i = 0; i < 8; i++)
#pragma unroll
                for (int j = 0; j < 4; j++) acc[i][j] = 0.f;
            const float* rp = &sRes[(tr * 8) * 97];
#pragma unroll 2
            for (int d = 0; d < 96; d++) {
                float a0 = rp[0 * 97 + d], a1 = rp[1 * 97 + d];
                float a2 = rp[2 * 97 + d], a3 = rp[3 * 97 + d];
                float a4 = rp[4 * 97 + d], a5 = rp[5 * 97 + d];
                float a6 = rp[6 * 97 + d], a7 = rp[7 * 97 + d];
#pragma unroll
                for (int j = 0; j < 4; j++) {
                    float bv = sE[(tc + 32 * j) * 97 + d];
                    acc[0][j] = fmaf(a0, bv, acc[0][j]);
                    acc[1][j] = fmaf(a1, bv, acc[1][j]);
                    acc[2][j] = fmaf(a2, bv, acc[2][j]);
                    acc[3][j] = fmaf(a3, bv, acc[3][j]);
                    acc[4][j] = fmaf(a4, bv, acc[4][j]);
                    acc[5][j] = fmaf(a5, bv, acc[5][j]);
                    acc[6][j] = fmaf(a6, bv, acc[6][j]);
                    acc[7][j] = fmaf(a7, bv, acc[7][j]);
                }
            }
#pragma unroll
            for (int i = 0; i < 8; i++)
#pragma unroll
                for (int j = 0; j < 4; j++) {
                    float sc = acc[i][j] - sHN[tc + 32 * j];
                    int code = tile * 128 + tc + 32 * j;
                    if (sc > best[i] || (sc == best[i] && code < bidx[i])) {
                        best[i] = sc; bidx[i] = code;
                    }
                }
        }
        __syncthreads();
#pragma unroll
        for (int i = 0; i < 8; i++) {
            sScore[(tr * 8 + i) * 32 + tc] = best[i];
            sIdx  [(tr * 8 + i) * 32 + tc] = bidx[i];
        }
        __syncthreads();
        if (tid < 64) {
            float bs = -3.0e38f; int bi = 0x7fffffff;
            for (int u = 0; u < 32; u++) {
                float s = sScore[tid * 32 + u]; int ii = sIdx[tid * 32 + u];
                if (s > bs || (s == bs && ii < bi)) { bs = s; bi = ii; }
            }
            sBest[tid] = bi;
        }
        __syncthreads();
        const float* bkb = books + (size_t)k * NEMB * CD;
        for (int e = tid; e < 64 * 96; e += 256) {
            int r = e / 96, d = e - r * 96;
            sRes[r * 97 + d] -= bkb[(size_t)sBest[r] * CD + d];
        }
    }
    __syncthreads();
    for (int e = tid; e < 64 * 96; e += 256) {
        int r = e / 96, d = e - r * 96;
        qD[(size_t)(m0 + r) * CD + d] =
            rD[(size_t)(m0 + r) * CD + d] - sRes[r * 97 + d];
    }
}

// ---------------- host side ----------------
static void gemm(const float* A, const float* Bm, float* Cm, const float* bias,
                 const float* resid, int M, int N, int K, int act, bool tb)
{
    dim3 grid((N + TBN - 1) / TBN, (M + TBM - 1) / TBM);
    if (tb) gemm_tc_k<1><<<grid, 256>>>(A, Bm, Cm, bias, resid, M, N, K, act);
    else    gemm_tc_k<0><<<grid, 256>>>(A, Bm, Cm, bias, resid, M, N, K, act);
}

template<typename T>
static T* sym(const void* s) { void* p = nullptr; cudaGetSymbolAddress(&p, s); return (T*)p; }

extern "C" void kernel_launch(void* const* d_in, const int* in_sizes, int n_in,
                              void* d_out, int out_size)
{
    const float* qa    = (const float*)d_in[0];
    const float* zt    = (const float*)d_in[1];
    const float* lnq_g = (const float*)d_in[2];
    const float* lnq_b = (const float*)d_in[3];
    const float* lnkv_g= (const float*)d_in[4];
    const float* lnkv_b= (const float*)d_in[5];
    const float* Wq    = (const float*)d_in[6];
    const float* Wk    = (const float*)d_in[7];
    const float* Wv    = (const float*)d_in[8];
    const float* Wo    = (const float*)d_in[9];
    const float* ffn_g = (const float*)d_in[10];
    const float* ffn_b = (const float*)d_in[11];
    const float* W1    = (const float*)d_in[12];
    const float* b1    = (const float*)d_in[13];
    const float* W2    = (const float*)d_in[14];
    const float* b2    = (const float*)d_in[15];
    const float* tn_g  = (const float*)d_in[16];
    const float* tn_b  = (const float*)d_in[17];
    const float* scale = (const float*)d_in[18];
    const float* Wd    = (const float*)d_in[19];
    const float* bd    = (const float*)d_in[20];
    const float* Wu    = (const float*)d_in[21];
    const float* bu    = (const float*)d_in[22];
    const float* books = (const float*)d_in[23];
    float* out = (float*)d_out;

    float* p_kvin = sym<float>(g_kvin);
    float* p_K    = sym<float>(g_K);
    float* p_V    = sym<float>(g_V);
    float* p_q    = sym<float>(g_q);
    float* p_ctx  = sym<float>(g_ctx);
    float* p_y    = sym<float>(g_y);
    float* p_h    = sym<float>(g_h);
    float* p_zhat = sym<float>(g_zhat);
    float* p_rD   = sym<float>(g_rD);
    float* p_qD   = sym<float>(g_qD);
    float* p_qln  = sym<float>(g_qln);
    float* p_Qc   = sym<float>(g_Qc);
    float* p_q0   = sym<float>(g_q0);
    float* p_Q0   = sym<float>(g_Q0);
    float* p_ctx0 = sym<float>(g_ctx0);
    float* p_y0   = sym<float>(g_y0);
    float* p_h0   = sym<float>(g_h0);
    float* p_rD0  = sym<float>(g_rD0);
    float* p_qD0  = sym<float>(g_qD0);
    float* p_zh0  = sym<float>(g_zh0);

    size_t rvq_smem = (size_t)(64 * 97 + 128 * 97 + 128 + 64 * 32) * 4
                    + (size_t)(64 * 32 + 64) * 4;
    cudaFuncSetAttribute(rvq_k, cudaFuncAttributeMaxDynamicSharedMemorySize,
                         (int)rvq_smem);

    // ---- prep ----
    prep_pe_qln_k<<<16, 256>>>(lnq_g, lnq_b);
    prep_cnorm_k<<<32, 256>>>(books);
    fillq_k<<<MR * Cc / 256, 256>>>();
    kvln_k<<<MR, 256>>>(qa, lnkv_g, lnkv_b);

    // ---- pass A ----
    gemm(p_qln, Wq, p_Qc, nullptr, nullptr, 16, 512, 512, 0, false);
    gemm(p_kvin, Wk, p_K, nullptr, nullptr, MR, 512, 512, 0, false);
    gemm(p_kvin, Wv, p_V, nullptr, nullptr, MR, 512, 512, 0, false);
    attnA_k<<<M2, 256>>>(p_K, p_V, p_ctx);
    gemm(p_ctx, Wo, p_y, nullptr, p_q, MR, 512, 512, 0, false);
    ln_rows_k<<<MR, 256>>>(p_y, p_ctx, ffn_g, ffn_b);
    gemm(p_ctx, W1, p_h, b1, nullptr, MR, 1024, 512, 1, false);
    gemm(p_h, W2, p_y, b2, p_y, MR, 512, 1024, 0, false);
    residA_k<<<MR, 256>>>(zt, p_y, p_kvin, tn_g, tn_b, scale);
    gemm(p_kvin, Wd, p_rD, bd, nullptr, MR, 96, 512, 0, true);
    rvq_k<<<MR / 64, 256, rvq_smem>>>(p_rD, p_qD, books);
    gemm(p_qD, Wu, p_zhat, bu, p_y, MR, 512, 96, 0, true);
    scatterA_k<<<MR * Cc / 256, 256>>>(p_zhat, out);

    // ---- pass B (token 0 of every chunk, using prev_last from pass A) ----
    q0ln_k<<<M2, 256>>>(lnq_g, lnq_b);
    gemm(p_q0, Wq, p_Q0, nullptr, nullptr, M2, 512, 512, 0, false);
    attnB_k<<<M2, 256>>>(p_K, p_V, p_ctx0);
    gemm(p_ctx0, Wo, p_y0, nullptr, p_q0, M2, 512, 512, 0, false);
    ln_rows_k<<<M2, 256>>>(p_y0, p_ctx0, ffn_g, ffn_b);
    gemm(p_ctx0, W1, p_h0, b1, nullptr, M2, 1024, 512, 1, false);
    gemm(p_h0, W2, p_y0, b2, p_y0, M2, 512, 1024, 0, false);
    residB_k<<<M2, 256>>>(zt, p_y0, p_ctx0, tn_g, tn_b, scale);
    gemm(p_ctx0, Wd, p_rD0, bd, nullptr, M2, 96, 512, 0, true);
    rvq_k<<<M2 / 64, 256, rvq_smem>>>(p_rD0, p_qD0, books);
    gemm(p_qD0, Wu, p_zh0, bu, p_y0, M2, 512, 96, 0, true);
    scatterB_k<<<M2 * Cc / 256, 256>>>(p_zh0, out);
}

// round 5
// speedup vs baseline: 1.1571x; 1.1139x over previous
#include <cuda_runtime.h>
#include <cuda_bf16.h>
#include <math.h>
#include <stdint.h>

// ---------------- problem constants ----------------
#define Bb    8
#define Cc    512
#define Tt    4096
#define CHK   16
#define Hh    8
#define DHd   64
#define CD    96
#define NBOOK 8
#define NEMB  1024
#define NCH   256
#define MR    (NCH*Bb*CHK)   // 32768 rows (pass A)
#define M2    (NCH*Bb)       // 2048 rows (pass B)

// ---------------- scratch (static device memory; no allocs) ----------------
__device__ float g_pe[Cc*CHK];
__device__ float g_qln[CHK*Cc];
__device__ float g_Qc[CHK*Cc];
__device__ float g_cnorm[NBOOK*NEMB];

__device__ float g_kvin[(size_t)MR*Cc];
__device__ float g_K   [(size_t)MR*Cc];
__device__ float g_V   [(size_t)MR*Cc];
__device__ float g_q   [(size_t)MR*Cc];
__device__ float g_ctx [(size_t)MR*Cc];
__device__ float g_y   [(size_t)MR*Cc];
__device__ float g_h   [(size_t)MR*2*Cc];
__device__ float g_zhat[(size_t)MR*Cc];
__device__ float g_rD  [(size_t)MR*CD];
__device__ float g_qD  [(size_t)MR*CD];
__device__ float g_prev[(size_t)M2*Cc];

__device__ float g_q0  [(size_t)M2*Cc];
__device__ float g_Q0  [(size_t)M2*Cc];
__device__ float g_ctx0[(size_t)M2*Cc];
__device__ float g_y0  [(size_t)M2*Cc];
__device__ float g_h0  [(size_t)M2*2*Cc];
__device__ float g_rD0 [(size_t)M2*CD];
__device__ float g_qD0 [(size_t)M2*CD];
__device__ float g_zh0 [(size_t)M2*Cc];

// ---------------- helpers ----------------
__device__ __forceinline__ float geluf(float x) {
    return 0.5f * x * (1.0f + erff(x * 0.70710678118654752440f));
}

__device__ __forceinline__ void mma_bf16(float* c, const uint32_t* a, const uint32_t* b) {
    asm volatile(
        "mma.sync.aligned.m16n8k16.row.col.f32.bf16.bf16.f32 "
        "{%0,%1,%2,%3}, {%4,%5,%6,%7}, {%8,%9}, {%0,%1,%2,%3};"
        : "+f"(c[0]), "+f"(c[1]), "+f"(c[2]), "+f"(c[3])
        : "r"(a[0]), "r"(a[1]), "r"(a[2]), "r"(a[3]), "r"(b[0]), "r"(b[1]));
}

// split v0,v1 into packed bf16 hi/lo words (elem0 in low 16 bits)
__device__ __forceinline__ void split2(float v0, float v1, uint32_t& hi, uint32_t& lo) {
    __nv_bfloat16 h0 = __float2bfloat16(v0);
    __nv_bfloat16 h1 = __float2bfloat16(v1);
    __nv_bfloat16 l0 = __float2bfloat16(v0 - __bfloat162float(h0));
    __nv_bfloat16 l1 = __float2bfloat16(v1 - __bfloat162float(h1));
    hi = (uint32_t)__bfloat16_as_ushort(h0) | ((uint32_t)__bfloat16_as_ushort(h1) << 16);
    lo = (uint32_t)__bfloat16_as_ushort(l0) | ((uint32_t)__bfloat16_as_ushort(l1) << 16);
}

// block = 256 threads, row of 512 elems, thread owns elems c0 and c1.
__device__ __forceinline__ float2 block_ln2(float x0, float x1, int c0, int c1,
                                            const float* __restrict__ g,
                                            const float* __restrict__ b,
                                            float* red)
{
    int tid = threadIdx.x, lane = tid & 31, w = tid >> 5;
    float s = x0 + x1;
#pragma unroll
    for (int o = 16; o; o >>= 1) s += __shfl_xor_sync(0xffffffffu, s, o);
    if (lane == 0) red[w] = s;
    __syncthreads();
    float tot = 0.f;
#pragma unroll
    for (int i = 0; i < 8; i++) tot += red[i];
    float mean = tot * (1.0f / 512.0f);
    float d0 = x0 - mean, d1 = x1 - mean;
    float q = d0 * d0 + d1 * d1;
#pragma unroll
    for (int o = 16; o; o >>= 1) q += __shfl_xor_sync(0xffffffffu, q, o);
    __syncthreads();
    if (lane == 0) red[w] = q;
    __syncthreads();
    float tot2 = 0.f;
#pragma unroll
    for (int i = 0; i < 8; i++) tot2 += red[i];
    float inv = rsqrtf(tot2 * (1.0f / 512.0f) + 1e-5f);
    return make_float2(d0 * inv * g[c0] + b[c0], d1 * inv * g[c1] + b[c1]);
}

// ---------------- prep kernels ----------------
__global__ void prep_pe_qln_k(const float* __restrict__ lnq_g,
                              const float* __restrict__ lnq_b)
{
    __shared__ float red[8];
    int t = blockIdx.x, tid = threadIdx.x;
    int c0 = 2 * tid, c1 = c0 + 1;
    double dv = exp((double)c0 * (-log(10000.0) / 512.0));
    double ang = (double)t * dv;
    float v0 = (float)sin(ang);
    float v1 = (float)cos(ang);
    g_pe[c0 * CHK + t] = v0;
    g_pe[c1 * CHK + t] = v1;
    float2 y = block_ln2(v0, v1, c0, c1, lnq_g, lnq_b, red);
    g_qln[t * Cc + c0] = y.x;
    g_qln[t * Cc + c1] = y.y;
}

__global__ void prep_cnorm_k(const float* __restrict__ books)
{
    int idx = blockIdx.x * 256 + threadIdx.x;   // 0..8191
    const float* e = books + (size_t)idx * CD;
    float s = 0.f;
#pragma unroll
    for (int d = 0; d < CD; d++) { float v = e[d]; s += v * v; }
    g_cnorm[idx] = 0.5f * s;
}

__global__ void fillq_k()
{
    int idx = blockIdx.x * 256 + threadIdx.x;
    int n = idx >> 9, c = idx & 511;
    int t = n & 15;
    g_q[(size_t)idx] = g_qln[t * Cc + c];
}

__global__ void kvln_k(const float* __restrict__ qa,
                       const float* __restrict__ g, const float* __restrict__ b)
{
    __shared__ float red[8];
    int n = blockIdx.x, tid = threadIdx.x;
    int s = n >> 7, bb = (n >> 4) & 7, t = n & 15;
    int tg = s * CHK + t;
    int c0 = tid, c1 = tid + 256;
    float x0 = qa[((size_t)(bb * Cc + c0)) * Tt + tg] + g_pe[c0 * CHK + t];
    float x1 = qa[((size_t)(bb * Cc + c1)) * Tt + tg] + g_pe[c1 * CHK + t];
    float2 y = block_ln2(x0, x1, c0, c1, g, b, red);
    g_kvin[(size_t)n * Cc + c0] = y.x;
    g_kvin[(size_t)n * Cc + c1] = y.y;
}

__global__ void ln_rows_k(const float* __restrict__ in, float* __restrict__ out,
                          const float* __restrict__ g, const float* __restrict__ b)
{
    __shared__ float red[8];
    int n = blockIdx.x, tid = threadIdx.x;
    int c0 = tid, c1 = tid + 256;
    float x0 = in[(size_t)n * Cc + c0];
    float x1 = in[(size_t)n * Cc + c1];
    float2 y = block_ln2(x0, x1, c0, c1, g, b, red);
    out[(size_t)n * Cc + c0] = y.x;
    out[(size_t)n * Cc + c1] = y.y;
}

__global__ void residA_k(const float* __restrict__ zt, const float* __restrict__ y,
                         float* __restrict__ xD,
                         const float* __restrict__ g, const float* __restrict__ b,
                         const float* __restrict__ scale)
{
    __shared__ float red[8];
    int n = blockIdx.x, tid = threadIdx.x;
    int s = n >> 7, bb = (n >> 4) & 7, t = n & 15;
    int tg = s * CHK + t;
    float sc = fminf(fmaxf(scale[0], 0.005f), 0.5f);
    int c0 = tid, c1 = tid + 256;
    float x0 = zt[((size_t)(bb * Cc + c0)) * Tt + tg] - y[(size_t)n * Cc + c0];
    float x1 = zt[((size_t)(bb * Cc + c1)) * Tt + tg] - y[(size_t)n * Cc + c1];
    float2 o = block_ln2(x0, x1, c0, c1, g, b, red);
    xD[(size_t)n * Cc + c0] = sc * tanhf(o.x);
    xD[(size_t)n * Cc + c1] = sc * tanhf(o.y);
}

__global__ void residB_k(const float* __restrict__ zt, const float* __restrict__ y,
                         float* __restrict__ xD,
                         const float* __restrict__ g, const float* __restrict__ b,
                         const float* __restrict__ scale)
{
    __shared__ float red[8];
    int n = blockIdx.x, tid = threadIdx.x;
    int s = n >> 3, bb = n & 7;
    int tg = s * CHK;
    float sc = fminf(fmaxf(scale[0], 0.005f), 0.5f);
    int c0 = tid, c1 = tid + 256;
    float x0 = zt[((size_t)(bb * Cc + c0)) * Tt + tg] - y[(size_t)n * Cc + c0];
    float x1 = zt[((size_t)(bb * Cc + c1)) * Tt + tg] - y[(size_t)n * Cc + c1];
    float2 o = block_ln2(x0, x1, c0, c1, g, b, red);
    xD[(size_t)n * Cc + c0] = sc * tanhf(o.x);
    xD[(size_t)n * Cc + c1] = sc * tanhf(o.y);
}

__global__ void q0ln_k(const float* __restrict__ g, const float* __restrict__ b)
{
    __shared__ float red[8];
    int n = blockIdx.x, tid = threadIdx.x;
    int s = n >> 3;
    int c0 = tid, c1 = tid + 256;
    float p0 = (s > 0) ? g_prev[(size_t)(n - Bb) * Cc + c0] : 0.f;
    float p1 = (s > 0) ? g_prev[(size_t)(n - Bb) * Cc + c1] : 0.f;
    float x0 = p0 + g_pe[c0 * CHK + 0];
    float x1 = p1 + g_pe[c1 * CHK + 0];
    float2 y = block_ln2(x0, x1, c0, c1, g, b, red);
    g_q0[(size_t)n * Cc + c0] = y.x;
    g_q0[(size_t)n * Cc + c1] = y.y;
}

__global__ void scatterA_k(const float* __restrict__ zhat, float* __restrict__ out)
{
    int idx = blockIdx.x * 256 + threadIdx.x;
    int n = idx >> 9, c = idx & 511;
    int s = n >> 7, bb = (n >> 4) & 7, t = n & 15;
    float v = zhat[(size_t)idx];
    out[((size_t)(bb * Cc + c)) * Tt + s * CHK + t] = v;
    if (t == 15) g_prev[(size_t)(n >> 4) * Cc + c] = v;
}

__global__ void scatterB_k(const float* __restrict__ zh0, float* __restrict__ out)
{
    int idx = blockIdx.x * 256 + threadIdx.x;  // M2*512
    int n = idx >> 9, c = idx & 511;
    int s = n >> 3, bb = n & 7;
    out[((size_t)(bb * Cc + c)) * Tt + s * CHK] = zh0[(size_t)idx];
}

// ---------------- split-bf16 (3xBF16) tensor-core GEMM ----------------
// C[M,N] = A[M,K] @ B (+bias +resid, act). TB=0: B is [K,N]; TB=1: B is [N,K].
// x = hi + lo (both bf16); A*B ~= Ah*Bh + Ah*Bl + Al*Bh (fp32 accum).
// Tile 128x128x16; 256 threads = 8 warps; warp computes 64x32 via m16n8k16.
// Smem: packed bf16x2 along k; row stride 12 words -> conflict-free frags.
#define TBM 128
#define TBN 128
#define TBK 16
template<int TB>
__global__ void __launch_bounds__(256) gemm_tc_k(
    const float* __restrict__ A, const float* __restrict__ Bm,
    float* __restrict__ Cm, const float* __restrict__ bias,
    const float* __restrict__ resid, int M, int N, int K, int act)
{
    __shared__ uint32_t Ah[TBM][12];
    __shared__ uint32_t Al[TBM][12];
    __shared__ uint32_t Bh[TBN][12];
    __shared__ uint32_t Bl[TBN][12];

    int tid = threadIdx.x;
    int wid = tid >> 5, lane = tid & 31;
    int g = lane >> 2, tg = lane & 3;
    int wm = (wid >> 2) * 64, wn = (wid & 3) * 32;
    int m0 = blockIdx.y * TBM, n0 = blockIdx.x * TBN;

    float acc[4][4][4];
#pragma unroll
    for (int i = 0; i < 4; i++)
#pragma unroll
        for (int j = 0; j < 4; j++)
#pragma unroll
            for (int r = 0; r < 4; r++) acc[i][j][r] = 0.f;

    for (int k0 = 0; k0 < K; k0 += TBK) {
        // stage A (128 rows x 8 packed words)
#pragma unroll
        for (int l = 0; l < 4; l++) {
            int e = tid + l * 256;
            int m = e >> 3, j = e & 7;
            int gm = m0 + m;
            float v0 = 0.f, v1 = 0.f;
            if (gm < M) {
                const float* ap = A + (size_t)gm * K + k0 + 2 * j;
                v0 = ap[0]; v1 = ap[1];
            }
            uint32_t hi, lo;
            split2(v0, v1, hi, lo);
            Ah[m][j] = hi; Al[m][j] = lo;
        }
        // stage B (128 cols x 8 packed words along k)
#pragma unroll
        for (int l = 0; l < 4; l++) {
            int e = tid + l * 256;
            int n, j;
            float v0 = 0.f, v1 = 0.f;
            if (TB == 0) {
                j = e >> 7; n = e & 127;
                int gn = n0 + n;
                if (gn < N) {
                    v0 = Bm[(size_t)(k0 + 2 * j) * N + gn];
                    v1 = Bm[(size_t)(k0 + 2 * j + 1) * N + gn];
                }
            } else {
                j = e & 7; n = e >> 3;
                int gn = n0 + n;
                if (gn < N) {
                    const float* bp = Bm + (size_t)gn * K + k0 + 2 * j;
                    v0 = bp[0]; v1 = bp[1];
                }
            }
            uint32_t hi, lo;
            split2(v0, v1, hi, lo);
            Bh[n][j] = hi; Bl[n][j] = lo;
        }
        __syncthreads();

        uint32_t ah[4][4], al[4][4], bh[4][2], bl[4][2];
#pragma unroll
        for (int mf = 0; mf < 4; mf++) {
            int row = wm + mf * 16;
            ah[mf][0] = Ah[row + g][tg];
            ah[mf][1] = Ah[row + g + 8][tg];
            ah[mf][2] = Ah[row + g][tg + 4];
            ah[mf][3] = Ah[row + g + 8][tg + 4];
            al[mf][0] = Al[row + g][tg];
            al[mf][1] = Al[row + g + 8][tg];
            al[mf][2] = Al[row + g][tg + 4];
            al[mf][3] = Al[row + g + 8][tg + 4];
        }
#pragma unroll
        for (int nf = 0; nf < 4; nf++) {
            int nn = wn + nf * 8 + g;
            bh[nf][0] = Bh[nn][tg];
            bh[nf][1] = Bh[nn][tg + 4];
            bl[nf][0] = Bl[nn][tg];
            bl[nf][1] = Bl[nn][tg + 4];
        }
#pragma unroll
        for (int mf = 0; mf < 4; mf++)
#pragma unroll
            for (int nf = 0; nf < 4; nf++) {
                mma_bf16(acc[mf][nf], ah[mf], bl[nf]);
                mma_bf16(acc[mf][nf], al[mf], bh[nf]);
                mma_bf16(acc[mf][nf], ah[mf], bh[nf]);
            }
        __syncthreads();
    }

    // epilogue (same c-frag mapping as m16n8k8)
#pragma unroll
    for (int mf = 0; mf < 4; mf++) {
        int mA = m0 + wm + mf * 16 + g;
        int mB = mA + 8;
#pragma unroll
        for (int nf = 0; nf < 4; nf++) {
            int nc = n0 + wn + nf * 8 + 2 * tg;
#pragma unroll
            for (int half = 0; half < 2; half++) {
                int m = half ? mB : mA;
                if (m >= M) continue;
                float v0 = acc[mf][nf][half * 2 + 0];
                float v1 = acc[mf][nf][half * 2 + 1];
                if (nc < N) {
                    if (bias)  v0 += bias[nc];
                    if (resid) v0 += resid[(size_t)m * N + nc];
                    if (act == 1) v0 = geluf(v0);
                    Cm[(size_t)m * N + nc] = v0;
                }
                if (nc + 1 < N) {
                    if (bias)  v1 += bias[nc + 1];
                    if (resid) v1 += resid[(size_t)m * N + nc + 1];
                    if (act == 1) v1 = geluf(v1);
                    Cm[(size_t)m * N + nc + 1] = v1;
                }
            }
        }
    }
}

// ---------------- attention ----------------
__global__ void __launch_bounds__(256) attnA_k(const float* __restrict__ Kmat,
                                               const float* __restrict__ Vmat,
                                               float* __restrict__ ctx)
{
    __shared__ float sKV[16][514];
    __shared__ float sS[16 * 8 * 16];
    int blk = blockIdx.x, tid = threadIdx.x;
    size_t n0 = (size_t)blk * CHK;

    for (int e = tid; e < 16 * 512; e += 256)
        sKV[e >> 9][e & 511] = Kmat[n0 * Cc + (size_t)(e >> 9) * Cc + (e & 511)];
    __syncthreads();

    {
        int t = tid >> 4, k = tid & 15;
        const float* qrow = g_Qc + t * Cc;
#pragma unroll
        for (int h = 0; h < 8; h++) {
            float s = 0.f;
            const float* kp = &sKV[k][h * 64];
            const float* qp = qrow + h * 64;
#pragma unroll 16
            for (int d = 0; d < 64; d++) s = fmaf(qp[d], kp[d], s);
            sS[(t * 8 + h) * 16 + k] = s * 0.125f;
        }
    }
    __syncthreads();
    if (tid < 128) {
        float* p = &sS[tid * 16];
        float m = p[0];
#pragma unroll
        for (int k = 1; k < 16; k++) m = fmaxf(m, p[k]);
        float sum = 0.f;
#pragma unroll
        for (int k = 0; k < 16; k++) { float e = expf(p[k] - m); p[k] = e; sum += e; }
        float inv = 1.0f / sum;
#pragma unroll
        for (int k = 0; k < 16; k++) p[k] *= inv;
    }
    __syncthreads();
    for (int e = tid; e < 16 * 512; e += 256)
        sKV[e >> 9][e & 511] = Vmat[n0 * Cc + (size_t)(e >> 9) * Cc + (e & 511)];
    __syncthreads();

#pragma unroll
    for (int cc = 0; cc < 2; cc++) {
        int c = tid + cc * 256;
        int h = c >> 6;
#pragma unroll
        for (int t = 0; t < 16; t++) {
            float a = 0.f;
            const float* at = &sS[(t * 8 + h) * 16];
#pragma unroll
            for (int k = 0; k < 16; k++) a = fmaf(at[k], sKV[k][c], a);
            ctx[(n0 + t) * Cc + c] = a;
        }
    }
}

__global__ void __launch_bounds__(256) attnB_k(const float* __restrict__ Kmat,
                                               const float* __restrict__ Vmat,
                                               float* __restrict__ ctx0)
{
    __shared__ float sKV[16][514];
    __shared__ float sS[8 * 16];
    int blk = blockIdx.x, tid = threadIdx.x;
    size_t n0 = (size_t)blk * CHK;

    for (int e = tid; e < 16 * 512; e += 256)
        sKV[e >> 9][e & 511] = Kmat[n0 * Cc + (size_t)(e >> 9) * Cc + (e & 511)];
    __syncthreads();

    if (tid < 128) {
        int h = tid >> 4, k = tid & 15;
        const float* qp = g_Q0 + (size_t)blk * Cc + h * 64;
        const float* kp = &sKV[k][h * 64];
        float s = 0.f;
#pragma unroll 16
        for (int d = 0; d < 64; d++) s = fmaf(qp[d], kp[d], s);
        sS[h * 16 + k] = s * 0.125f;
    }
    __syncthreads();
    if (tid < 8) {
        float* p = &sS[tid * 16];
        float m = p[0];
#pragma unroll
        for (int k = 1; k < 16; k++) m = fmaxf(m, p[k]);
        float sum = 0.f;
#pragma unroll
        for (int k = 0; k < 16; k++) { float e = expf(p[k] - m); p[k] = e; sum += e; }
        float inv = 1.0f / sum;
#pragma unroll
        for (int k = 0; k < 16; k++) p[k] *= inv;
    }
    __syncthreads();
    for (int e = tid; e < 16 * 512; e += 256)
        sKV[e >> 9][e & 511] = Vmat[n0 * Cc + (size_t)(e >> 9) * Cc + (e & 511)];
    __syncthreads();

#pragma unroll
    for (int cc = 0; cc < 2; cc++) {
        int c = tid + cc * 256;
        int h = c >> 6;
        float a = 0.f;
        const float* at = &sS[h * 16];
#pragma unroll
        for (int k = 0; k < 16; k++) a = fmaf(at[k], sKV[k][c], a);
        ctx0[(size_t)blk * Cc + c] = a;
    }
}

// ---------------- residual VQ: 64 rows/block, 256 threads ----------------
__global__ void __launch_bounds__(256) rvq_k(const float* __restrict__ rD,
                                             float* __restrict__ qD,
                                             const float* __restrict__ books)
{
    extern __shared__ float sm[];
    float* sRes   = sm;                 // 64*97
    float* sE     = sRes + 64 * 97;     // 128*97
    float* sHN    = sE + 128 * 97;      // 128
    float* sScore = sHN + 128;          // 64*32
    int*   sIdx   = (int*)(sScore + 64 * 32); // 64*32
    int*   sBest  = sIdx + 64 * 32;     // 64

    int tid = threadIdx.x;
    int tr = tid >> 5;   // 0..7  -> rows tr*8 .. tr*8+7
    int tc = tid & 31;   // 0..31 -> codes tc + 32*j
    int m0 = blockIdx.x * 64;

    for (int e = tid; e < 64 * 96; e += 256) {
        int r = e / 96, d = e - r * 96;
        sRes[r * 97 + d] = rD[(size_t)(m0 + r) * CD + d];
    }

    for (int k = 0; k < NBOOK; k++) {
        float best[8]; int bidx[8];
#pragma unroll
        for (int i = 0; i < 8; i++) { best[i] = -3.0e38f; bidx[i] = 0; }

        for (int tile = 0; tile < 8; tile++) {
            __syncthreads();
            const float* bk = books + ((size_t)k * NEMB + tile * 128) * CD;
            for (int e = tid; e < 128 * 96; e += 256) {
                int c = e / 96, d = e - c * 96;
                sE[c * 97 + d] = bk[(size_t)c * CD + d];
            }
            if (tid < 128) sHN[tid] = g_cnorm[k * NEMB + tile * 128 + tid];
            __syncthreads();

            float acc[8][4];
#pragma unroll
            for (int i = 0; i < 8; i++)
#pragma unroll
                for (int j = 0; j < 4; j++) acc[i][j] = 0.f;
            const float* rp = &sRes[(tr * 8) * 97];
#pragma unroll 2
            for (int d = 0; d < 96; d++) {
                float a0 = rp[0 * 97 + d], a1 = rp[1 * 97 + d];
                float a2 = rp[2 * 97 + d], a3 = rp[3 * 97 + d];
                float a4 = rp[4 * 97 + d], a5 = rp[5 * 97 + d];
                float a6 = rp[6 * 97 + d], a7 = rp[7 * 97 + d];
#pragma unroll
                for (int j = 0; j < 4; j++) {
                    float bv = sE[(tc + 32 * j) * 97 + d];
                    acc[0][j] = fmaf(a0, bv, acc[0][j]);
                    acc[1][j] = fmaf(a1, bv, acc[1][j]);
                    acc[2][j] = fmaf(a2, bv, acc[2][j]);
                    acc[3][j] = fmaf(a3, bv, acc[3][j]);
                    acc[4][j] = fmaf(a4, bv, acc[4][j]);
                    acc[5][j] = fmaf(a5, bv, acc[5][j]);
                    acc[6][j] = fmaf(a6, bv, acc[6][j]);
                    acc[7][j] = fmaf(a7, bv, acc[7][j]);
                }
            }
#pragma unroll
            for (int i = 0; i < 8; i++)
#pragma unroll
                for (int j = 0; j < 4; j++) {
                    float sc = acc[i][j] - sHN[tc + 32 * j];
                    int code = tile * 128 + tc + 32 * j;
                    if (sc > best[i] || (sc == best[i] && code < bidx[i])) {
                        best[i] = sc; bidx[i] = code;
                    }
                }
        }
        __syncthreads();
#pragma unroll
        for (int i = 0; i < 8; i++) {
            sScore[(tr * 8 + i) * 32 + tc] = best[i];
            sIdx  [(tr * 8 + i) * 32 + tc] = bidx[i];
        }
        __syncthreads();
        if (tid < 64) {
            float bs = -3.0e38f; int bi = 0x7fffffff;
            for (int u = 0; u < 32; u++) {
                float s = sScore[tid * 32 + u]; int ii = sIdx[tid * 32 + u];
                if (s > bs || (s == bs && ii < bi)) { bs = s; bi = ii; }
            }
            sBest[tid] = bi;
        }
        __syncthreads();
        const float* bkb = books + (size_t)k * NEMB * CD;
        for (int e = tid; e < 64 * 96; e += 256) {
            int r = e / 96, d = e - r * 96;
            sRes[r * 97 + d] -= bkb[(size_t)sBest[r] * CD + d];
        }
    }
    __syncthreads();
    for (int e = tid; e < 64 * 96; e += 256) {
        int r = e / 96, d = e - r * 96;
        qD[(size_t)(m0 + r) * CD + d] =
            rD[(size_t)(m0 + r) * CD + d] - sRes[r * 97 + d];
    }
}

// ---------------- host side ----------------
static void gemm(const float* A, const float* Bm, float* Cm, const float* bias,
                 const float* resid, int M, int N, int K, int act, bool tb)
{
    dim3 grid((N + TBN - 1) / TBN, (M + TBM - 1) / TBM);
    if (tb) gemm_tc_k<1><<<grid, 256>>>(A, Bm, Cm, bias, resid, M, N, K, act);
    else    gemm_tc_k<0><<<grid, 256>>>(A, Bm, Cm, bias, resid, M, N, K, act);
}

template<typename T>
static T* sym(const void* s) { void* p = nullptr; cudaGetSymbolAddress(&p, s); return (T*)p; }

extern "C" void kernel_launch(void* const* d_in, const int* in_sizes, int n_in,
                              void* d_out, int out_size)
{
    const float* qa    = (const float*)d_in[0];
    const float* zt    = (const float*)d_in[1];
    const float* lnq_g = (const float*)d_in[2];
    const float* lnq_b = (const float*)d_in[3];
    const float* lnkv_g= (const float*)d_in[4];
    const float* lnkv_b= (const float*)d_in[5];
    const float* Wq    = (const float*)d_in[6];
    const float* Wk    = (const float*)d_in[7];
    const float* Wv    = (const float*)d_in[8];
    const float* Wo    = (const float*)d_in[9];
    const float* ffn_g = (const float*)d_in[10];
    const float* ffn_b = (const float*)d_in[11];
    const float* W1    = (const float*)d_in[12];
    const float* b1    = (const float*)d_in[13];
    const float* W2    = (const float*)d_in[14];
    const float* b2    = (const float*)d_in[15];
    const float* tn_g  = (const float*)d_in[16];
    const float* tn_b  = (const float*)d_in[17];
    const float* scale = (const float*)d_in[18];
    const float* Wd    = (const float*)d_in[19];
    const float* bd    = (const float*)d_in[20];
    const float* Wu    = (const float*)d_in[21];
    const float* bu    = (const float*)d_in[22];
    const float* books = (const float*)d_in[23];
    float* out = (float*)d_out;

    float* p_kvin = sym<float>(g_kvin);
    float* p_K    = sym<float>(g_K);
    float* p_V    = sym<float>(g_V);
    float* p_q    = sym<float>(g_q);
    float* p_ctx  = sym<float>(g_ctx);
    float* p_y    = sym<float>(g_y);
    float* p_h    = sym<float>(g_h);
    float* p_zhat = sym<float>(g_zhat);
    float* p_rD   = sym<float>(g_rD);
    float* p_qD   = sym<float>(g_qD);
    float* p_qln  = sym<float>(g_qln);
    float* p_Qc   = sym<float>(g_Qc);
    float* p_q0   = sym<float>(g_q0);
    float* p_Q0   = sym<float>(g_Q0);
    float* p_ctx0 = sym<float>(g_ctx0);
    float* p_y0   = sym<float>(g_y0);
    float* p_h0   = sym<float>(g_h0);
    float* p_rD0  = sym<float>(g_rD0);
    float* p_qD0  = sym<float>(g_qD0);
    float* p_zh0  = sym<float>(g_zh0);

    size_t rvq_smem = (size_t)(64 * 97 + 128 * 97 + 128 + 64 * 32) * 4
                    + (size_t)(64 * 32 + 64) * 4;
    cudaFuncSetAttribute(rvq_k, cudaFuncAttributeMaxDynamicSharedMemorySize,
                         (int)rvq_smem);

    // ---- prep ----
    prep_pe_qln_k<<<16, 256>>>(lnq_g, lnq_b);
    prep_cnorm_k<<<32, 256>>>(books);
    fillq_k<<<MR * Cc / 256, 256>>>();
    kvln_k<<<MR, 256>>>(qa, lnkv_g, lnkv_b);

    // ---- pass A ----
    gemm(p_qln, Wq, p_Qc, nullptr, nullptr, 16, 512, 512, 0, false);
    gemm(p_kvin, Wk, p_K, nullptr, nullptr, MR, 512, 512, 0, false);
    gemm(p_kvin, Wv, p_V, nullptr, nullptr, MR, 512, 512, 0, false);
    attnA_k<<<M2, 256>>>(p_K, p_V, p_ctx);
    gemm(p_ctx, Wo, p_y, nullptr, p_q, MR, 512, 512, 0, false);
    ln_rows_k<<<MR, 256>>>(p_y, p_ctx, ffn_g, ffn_b);
    gemm(p_ctx, W1, p_h, b1, nullptr, MR, 1024, 512, 1, false);
    gemm(p_h, W2, p_y, b2, p_y, MR, 512, 1024, 0, false);
    residA_k<<<MR, 256>>>(zt, p_y, p_kvin, tn_g, tn_b, scale);
    gemm(p_kvin, Wd, p_rD, bd, nullptr, MR, 96, 512, 0, true);
    rvq_k<<<MR / 64, 256, rvq_smem>>>(p_rD, p_qD, books);
    gemm(p_qD, Wu, p_zhat, bu, p_y, MR, 512, 96, 0, true);
    scatterA_k<<<MR * Cc / 256, 256>>>(p_zhat, out);

    // ---- pass B (token 0 of every chunk, using prev_last from pass A) ----
    q0ln_k<<<M2, 256>>>(lnq_g, lnq_b);
    gemm(p_q0, Wq, p_Q0, nullptr, nullptr, M2, 512, 512, 0, false);
    attnB_k<<<M2, 256>>>(p_K, p_V, p_ctx0);
    gemm(p_ctx0, Wo, p_y0, nullptr, p_q0, M2, 512, 512, 0, false);
    ln_rows_k<<<M2, 256>>>(p_y0, p_ctx0, ffn_g, ffn_b);
    gemm(p_ctx0, W1, p_h0, b1, nullptr, M2, 1024, 512, 1, false);
    gemm(p_h0, W2, p_y0, b2, p_y0, M2, 512, 1024, 0, false);
    residB_k<<<M2, 256>>>(zt, p_y0, p_ctx0, tn_g, tn_b, scale);
    gemm(p_ctx0, Wd, p_rD0, bd, nullptr, M2, 96, 512, 0, true);
    rvq_k<<<M2 / 64, 256, rvq_smem>>>(p_rD0, p_qD0, books);
    gemm(p_qD0, Wu, p_zh0, bu, p_y0, M2, 512, 96, 0, true);
    scatterB_k<<<M2 * Cc / 256, 256>>>(p_zh0, out);
}

// round 7
// speedup vs baseline: 1.5091x; 1.3041x over previous
#include <cuda_runtime.h>
#include <cuda_bf16.h>
#include <math.h>
#include <stdint.h>

typedef unsigned short u16;

// ---------------- problem constants ----------------
#define Bb    8
#define Cc    512
#define Tt    4096
#define CHK   16
#define CD    96
#define NBOOK 8
#define NEMB  1024
#define NCH   256
#define MR    (NCH*Bb*CHK)   // 32768
#define M2    (NCH*Bb)       // 2048

// ---------------- fp32 scratch ----------------
__device__ float g_pe[Cc*CHK];
__device__ float g_qln[CHK*Cc];
__device__ float g_Qc[CHK*Cc];
__device__ float g_cnorm[NBOOK*NEMB];
__device__ float g_K   [(size_t)MR*Cc];
__device__ float g_V   [(size_t)MR*Cc];
__device__ float g_y   [(size_t)MR*Cc];
__device__ float g_rD  [(size_t)MR*CD];
__device__ float g_zhat[(size_t)MR*Cc];
__device__ float g_prev[(size_t)M2*Cc];
__device__ float g_q0  [(size_t)M2*Cc];
__device__ float g_Q0  [(size_t)M2*Cc];
__device__ float g_y0  [(size_t)M2*Cc];
__device__ float g_rD0 [(size_t)M2*CD];
__device__ float g_zh0 [(size_t)M2*Cc];

// ---------------- bf16 hi/lo scratch (activations) ----------------
__device__ __align__(16) u16 u_qlnh[CHK*Cc],  u_qlnl[CHK*Cc];
__device__ __align__(16) u16 u_kvh [(size_t)MR*Cc],  u_kvl [(size_t)MR*Cc];
__device__ __align__(16) u16 u_ctxh[(size_t)MR*Cc],  u_ctxl[(size_t)MR*Cc];
__device__ __align__(16) u16 u_lnh [(size_t)MR*Cc],  u_lnl [(size_t)MR*Cc];
__device__ __align__(16) u16 u_hh  [(size_t)MR*2*Cc],u_hl  [(size_t)MR*2*Cc];
__device__ __align__(16) u16 u_xdh [(size_t)MR*Cc],  u_xdl [(size_t)MR*Cc];
__device__ __align__(16) u16 u_qdh [(size_t)MR*CD],  u_qdl [(size_t)MR*CD];
__device__ __align__(16) u16 u_q0h [(size_t)M2*Cc],  u_q0l [(size_t)M2*Cc];
__device__ __align__(16) u16 u_ctx0h[(size_t)M2*Cc], u_ctx0l[(size_t)M2*Cc];
__device__ __align__(16) u16 u_ln0h[(size_t)M2*Cc],  u_ln0l[(size_t)M2*Cc];
__device__ __align__(16) u16 u_h0h [(size_t)M2*2*Cc],u_h0l [(size_t)M2*2*Cc];
__device__ __align__(16) u16 u_xd0h[(size_t)M2*Cc],  u_xd0l[(size_t)M2*Cc];
__device__ __align__(16) u16 u_qd0h[(size_t)M2*CD],  u_qd0l[(size_t)M2*CD];

// ---------------- bf16 hi/lo weights (all stored [N][K]) ----------------
__device__ __align__(16) u16 w_qh[Cc*Cc],  w_ql[Cc*Cc];
__device__ __align__(16) u16 w_kh[Cc*Cc],  w_kl[Cc*Cc];
__device__ __align__(16) u16 w_vh[Cc*Cc],  w_vl[Cc*Cc];
__device__ __align__(16) u16 w_oh[Cc*Cc],  w_ol[Cc*Cc];
__device__ __align__(16) u16 w_1h[2*Cc*Cc],w_1l[2*Cc*Cc];   // [1024][512]
__device__ __align__(16) u16 w_2h[2*Cc*Cc],w_2l[2*Cc*Cc];   // [512][1024]
__device__ __align__(16) u16 w_dh[CD*Cc],  w_dl[CD*Cc];     // [96][512]
__device__ __align__(16) u16 w_uh[Cc*CD],  w_ul[Cc*CD];     // [512][96]

// ---------------- helpers ----------------
__device__ __forceinline__ float geluf(float x) {
    return 0.5f * x * (1.0f + erff(x * 0.70710678118654752440f));
}
__device__ __forceinline__ void split1(float v, u16& h, u16& l) {
    __nv_bfloat16 hb = __float2bfloat16(v);
    __nv_bfloat16 lb = __float2bfloat16(v - __bfloat162float(hb));
    h = __bfloat16_as_ushort(hb);
    l = __bfloat16_as_ushort(lb);
}
__device__ __forceinline__ uint32_t smem_u32(const void* p) {
    uint32_t a;
    asm("{ .reg .u64 t; cvta.to.shared.u64 t, %1; cvt.u32.u64 %0, t; }" : "=r"(a) : "l"(p));
    return a;
}
__device__ __forceinline__ void cpa16(uint32_t dst, const void* src, int sz) {
    asm volatile("cp.async.cg.shared.global [%0], [%1], 16, %2;"
                 :: "r"(dst), "l"(src), "r"(sz) : "memory");
}
__device__ __forceinline__ void mma_bf16(float* c, const uint32_t* a, const uint32_t* b) {
    asm volatile(
        "mma.sync.aligned.m16n8k16.row.col.f32.bf16.bf16.f32 "
        "{%0,%1,%2,%3}, {%4,%5,%6,%7}, {%8,%9}, {%0,%1,%2,%3};"
        : "+f"(c[0]), "+f"(c[1]), "+f"(c[2]), "+f"(c[3])
        : "r"(a[0]), "r"(a[1]), "r"(a[2]), "r"(a[3]), "r"(b[0]), "r"(b[1]));
}

// ---------------- weight prep ----------------
// W is [K,N] row-major; out [N][K]
__global__ void wsplitT_k(const float* __restrict__ W, u16* __restrict__ oh,
                          u16* __restrict__ ol, int K, int N)
{
    int e = blockIdx.x * 256 + threadIdx.x;
    if (e >= K * N) return;
    int k = e / N, n = e - k * N;
    u16 h, l; split1(W[e], h, l);
    oh[(size_t)n * K + k] = h;
    ol[(size_t)n * K + k] = l;
}
// W already [N,K] row-major
__global__ void wsplit_k(const float* __restrict__ W, u16* __restrict__ oh,
                         u16* __restrict__ ol, int total)
{
    int e = blockIdx.x * 256 + threadIdx.x;
    if (e >= total) return;
    u16 h, l; split1(W[e], h, l);
    oh[e] = h; ol[e] = l;
}

// ---------------- LN helper (block of 256, row 512) ----------------
__device__ __forceinline__ float2 block_ln2(float x0, float x1, int c0, int c1,
                                            const float* __restrict__ g,
                                            const float* __restrict__ b,
                                            float* red)
{
    int tid = threadIdx.x, lane = tid & 31, w = tid >> 5;
    float s = x0 + x1;
#pragma unroll
    for (int o = 16; o; o >>= 1) s += __shfl_xor_sync(0xffffffffu, s, o);
    if (lane == 0) red[w] = s;
    __syncthreads();
    float tot = 0.f;
#pragma unroll
    for (int i = 0; i < 8; i++) tot += red[i];
    float mean = tot * (1.0f / 512.0f);
    float d0 = x0 - mean, d1 = x1 - mean;
    float q = d0 * d0 + d1 * d1;
#pragma unroll
    for (int o = 16; o; o >>= 1) q += __shfl_xor_sync(0xffffffffu, q, o);
    __syncthreads();
    if (lane == 0) red[w] = q;
    __syncthreads();
    float tot2 = 0.f;
#pragma unroll
    for (int i = 0; i < 8; i++) tot2 += red[i];
    float inv = rsqrtf(tot2 * (1.0f / 512.0f) + 1e-5f);
    return make_float2(d0 * inv * g[c0] + b[c0], d1 * inv * g[c1] + b[c1]);
}

// ---------------- prep kernels ----------------
__global__ void prep_pe_qln_k(const float* __restrict__ lnq_g,
                              const float* __restrict__ lnq_b)
{
    __shared__ float red[8];
    int t = blockIdx.x, tid = threadIdx.x;
    int c0 = 2 * tid, c1 = c0 + 1;
    double dv = exp((double)c0 * (-log(10000.0) / 512.0));
    double ang = (double)t * dv;
    float v0 = (float)sin(ang);
    float v1 = (float)cos(ang);
    g_pe[c0 * CHK + t] = v0;
    g_pe[c1 * CHK + t] = v1;
    float2 y = block_ln2(v0, v1, c0, c1, lnq_g, lnq_b, red);
    g_qln[t * Cc + c0] = y.x;
    g_qln[t * Cc + c1] = y.y;
    u16 h, l;
    split1(y.x, h, l); u_qlnh[t * Cc + c0] = h; u_qlnl[t * Cc + c0] = l;
    split1(y.y, h, l); u_qlnh[t * Cc + c1] = h; u_qlnl[t * Cc + c1] = l;
}

__global__ void prep_cnorm_k(const float* __restrict__ books)
{
    int idx = blockIdx.x * 256 + threadIdx.x;
    const float* e = books + (size_t)idx * CD;
    float s = 0.f;
#pragma unroll
    for (int d = 0; d < CD; d++) { float v = e[d]; s += v * v; }
    g_cnorm[idx] = 0.5f * s;
}

// ---------------- coalesced kvln: block=(s,bb), 16 tok x 512 ch ----------------
__global__ void __launch_bounds__(256) kvln2_k(const float* __restrict__ qa,
                                               const float* __restrict__ g,
                                               const float* __restrict__ b)
{
    __shared__ float tile[16][513];
    int blk = blockIdx.x, tid = threadIdx.x;
    int s = blk >> 3, bb = blk & 7;
    // load qa[bb, c, s*16 .. s*16+15] as float4s (coalesced along T)
#pragma unroll
    for (int l = 0; l < 8; l++) {
        int e = tid + l * 256;      // 0..2047
        int c = e >> 2, seg = e & 3;
        float4 v = *(const float4*)(qa + ((size_t)(bb * Cc + c)) * Tt + s * CHK + seg * 4);
        tile[seg * 4 + 0][c] = v.x;
        tile[seg * 4 + 1][c] = v.y;
        tile[seg * 4 + 2][c] = v.z;
        tile[seg * 4 + 3][c] = v.w;
    }
    __syncthreads();
    int w = tid >> 5, lane = tid & 31;
#pragma unroll
    for (int t = w; t < 16; t += 8) {
        int n = s * 128 + bb * 16 + t;
        float xs[16], sum = 0.f;
#pragma unroll
        for (int k = 0; k < 16; k++) {
            int c = lane + 32 * k;
            float x = tile[t][c] + g_pe[c * CHK + t];
            xs[k] = x; sum += x;
        }
#pragma unroll
        for (int o = 16; o; o >>= 1) sum += __shfl_xor_sync(0xffffffffu, sum, o);
        float mean = sum * (1.0f / 512.0f);
        float q = 0.f;
#pragma unroll
        for (int k = 0; k < 16; k++) { float d = xs[k] - mean; q += d * d; }
#pragma unroll
        for (int o = 16; o; o >>= 1) q += __shfl_xor_sync(0xffffffffu, q, o);
        float inv = rsqrtf(q * (1.0f / 512.0f) + 1e-5f);
#pragma unroll
        for (int k = 0; k < 16; k++) {
            int c = lane + 32 * k;
            float o2 = (xs[k] - mean) * inv * g[c] + b[c];
            u16 h, l2; split1(o2, h, l2);
            u_kvh[(size_t)n * Cc + c] = h;
            u_kvl[(size_t)n * Cc + c] = l2;
        }
    }
}

// generic row-LN with split output
__global__ void ln_rows_k(const float* __restrict__ in, u16* __restrict__ oh,
                          u16* __restrict__ ol,
                          const float* __restrict__ g, const float* __restrict__ b)
{
    __shared__ float red[8];
    int n = blockIdx.x, tid = threadIdx.x;
    int c0 = tid, c1 = tid + 256;
    float x0 = in[(size_t)n * Cc + c0];
    float x1 = in[(size_t)n * Cc + c1];
    float2 y = block_ln2(x0, x1, c0, c1, g, b, red);
    u16 h, l;
    split1(y.x, h, l); oh[(size_t)n * Cc + c0] = h; ol[(size_t)n * Cc + c0] = l;
    split1(y.y, h, l); oh[(size_t)n * Cc + c1] = h; ol[(size_t)n * Cc + c1] = l;
}

// coalesced residA: block=(s,bb)
__global__ void __launch_bounds__(256) residA2_k(const float* __restrict__ zt,
                                                 const float* __restrict__ y,
                                                 const float* __restrict__ g,
                                                 const float* __restrict__ b,
                                                 const float* __restrict__ scale)
{
    __shared__ float tile[16][513];
    int blk = blockIdx.x, tid = threadIdx.x;
    int s = blk >> 3, bb = blk & 7;
    float sc = fminf(fmaxf(scale[0], 0.005f), 0.5f);
#pragma unroll
    for (int l = 0; l < 8; l++) {
        int e = tid + l * 256;
        int c = e >> 2, seg = e & 3;
        float4 v = *(const float4*)(zt + ((size_t)(bb * Cc + c)) * Tt + s * CHK + seg * 4);
        tile[seg * 4 + 0][c] = v.x;
        tile[seg * 4 + 1][c] = v.y;
        tile[seg * 4 + 2][c] = v.z;
        tile[seg * 4 + 3][c] = v.w;
    }
    __syncthreads();
    int w = tid >> 5, lane = tid & 31;
#pragma unroll
    for (int t = w; t < 16; t += 8) {
        int n = s * 128 + bb * 16 + t;
        float xs[16], sum = 0.f;
#pragma unroll
        for (int k = 0; k < 16; k++) {
            int c = lane + 32 * k;
            float x = tile[t][c] - y[(size_t)n * Cc + c];
            xs[k] = x; sum += x;
        }
#pragma unroll
        for (int o = 16; o; o >>= 1) sum += __shfl_xor_sync(0xffffffffu, sum, o);
        float mean = sum * (1.0f / 512.0f);
        float q = 0.f;
#pragma unroll
        for (int k = 0; k < 16; k++) { float d = xs[k] - mean; q += d * d; }
#pragma unroll
        for (int o = 16; o; o >>= 1) q += __shfl_xor_sync(0xffffffffu, q, o);
        float inv = rsqrtf(q * (1.0f / 512.0f) + 1e-5f);
#pragma unroll
        for (int k = 0; k < 16; k++) {
            int c = lane + 32 * k;
            float o2 = sc * tanhf((xs[k] - mean) * inv * g[c] + b[c]);
            u16 h, l2; split1(o2, h, l2);
            u_xdh[(size_t)n * Cc + c] = h;
            u_xdl[(size_t)n * Cc + c] = l2;
        }
    }
}

// pass-B residual (token 0 rows only, small)
__global__ void residB_k(const float* __restrict__ zt, const float* __restrict__ y,
                         const float* __restrict__ g, const float* __restrict__ b,
                         const float* __restrict__ scale)
{
    __shared__ float red[8];
    int n = blockIdx.x, tid = threadIdx.x;
    int s = n >> 3, bb = n & 7;
    int tg = s * CHK;
    float sc = fminf(fmaxf(scale[0], 0.005f), 0.5f);
    int c0 = tid, c1 = tid + 256;
    float x0 = zt[((size_t)(bb * Cc + c0)) * Tt + tg] - y[(size_t)n * Cc + c0];
    float x1 = zt[((size_t)(bb * Cc + c1)) * Tt + tg] - y[(size_t)n * Cc + c1];
    float2 o = block_ln2(x0, x1, c0, c1, g, b, red);
    u16 h, l;
    split1(sc * tanhf(o.x), h, l); u_xd0h[(size_t)n * Cc + c0] = h; u_xd0l[(size_t)n * Cc + c0] = l;
    split1(sc * tanhf(o.y), h, l); u_xd0h[(size_t)n * Cc + c1] = h; u_xd0l[(size_t)n * Cc + c1] = l;
}

__global__ void q0ln_k(const float* __restrict__ g, const float* __restrict__ b)
{
    __shared__ float red[8];
    int n = blockIdx.x, tid = threadIdx.x;
    int s = n >> 3;
    int c0 = tid, c1 = tid + 256;
    float p0 = (s > 0) ? g_prev[(size_t)(n - Bb) * Cc + c0] : 0.f;
    float p1 = (s > 0) ? g_prev[(size_t)(n - Bb) * Cc + c1] : 0.f;
    float x0 = p0 + g_pe[c0 * CHK + 0];
    float x1 = p1 + g_pe[c1 * CHK + 0];
    float2 y = block_ln2(x0, x1, c0, c1, g, b, red);
    g_q0[(size_t)n * Cc + c0] = y.x;
    g_q0[(size_t)n * Cc + c1] = y.y;
    u16 h, l;
    split1(y.x, h, l); u_q0h[(size_t)n * Cc + c0] = h; u_q0l[(size_t)n * Cc + c0] = l;
    split1(y.y, h, l); u_q0h[(size_t)n * Cc + c1] = h; u_q0l[(size_t)n * Cc + c1] = l;
}

// coalesced scatter: block=(s,bb)
__global__ void __launch_bounds__(256) scatterA2_k(const float* __restrict__ zhat,
                                                   float* __restrict__ out)
{
    __shared__ float tile[16][513];
    int blk = blockIdx.x, tid = threadIdx.x;
    int s = blk >> 3, bb = blk & 7;
    int n0 = s * 128 + bb * 16;
#pragma unroll
    for (int l = 0; l < 32; l++) {
        int e = tid + l * 256;     // 0..8191
        int t = e >> 9, c = e & 511;
        float v = zhat[((size_t)(n0 + t)) * Cc + c];
        tile[t][c] = v;
        if (t == 15) g_prev[(size_t)(s * 8 + bb) * Cc + c] = v;
    }
    __syncthreads();
#pragma unroll
    for (int l = 0; l < 8; l++) {
        int e = tid + l * 256;
        int c = e >> 2, seg = e & 3;
        float4 v = make_float4(tile[seg * 4 + 0][c], tile[seg * 4 + 1][c],
                               tile[seg * 4 + 2][c], tile[seg * 4 + 3][c]);
        *(float4*)(out + ((size_t)(bb * Cc + c)) * Tt + s * CHK + seg * 4) = v;
    }
}

__global__ void scatterB_k(const float* __restrict__ zh0, float* __restrict__ out)
{
    int idx = blockIdx.x * 256 + threadIdx.x;
    int n = idx >> 9, c = idx & 511;
    int s = n >> 3, bb = n & 7;
    out[((size_t)(bb * Cc + c)) * Tt + s * CHK] = zh0[(size_t)idx];
}

// ---------------- split-bf16 GEMM with cp.async staging ----------------
// A: pre-split [M][K] (hi/lo bf16); B: pre-split [N][K]; C = A@B^T style.
// Tile 128x128, k-chunk 32, double buffered. 256 threads = 8 warps (2x4),
// warp tile 64x32 via m16n8k16. Smem/buffer: 4 mats x 128 rows x 80B = 40960B.
#define GB_SMEM (2 * 40960)

__device__ __forceinline__ void gb_stage(uint32_t sbase,
    const u16* __restrict__ Ah, const u16* __restrict__ Al,
    const u16* __restrict__ Bh, const u16* __restrict__ Bl,
    int m0, int n0, int M, int N, int K, int k0, int tid)
{
#pragma unroll
    for (int l = 0; l < 2; l++) {
        int e = tid + l * 256;
        int row = e >> 2, seg = e & 3;
        uint32_t d = sbase + row * 80 + seg * 16;
        size_t oa = (size_t)(m0 + row) * K + k0 + seg * 8;
        int szA = (m0 + row < M) ? 16 : 0;
        cpa16(d,         Ah + oa, szA);
        cpa16(d + 10240, Al + oa, szA);
        size_t ob = (size_t)(n0 + row) * K + k0 + seg * 8;
        int szB = (n0 + row < N) ? 16 : 0;
        cpa16(d + 20480, Bh + ob, szB);
        cpa16(d + 30720, Bl + ob, szB);
    }
    asm volatile("cp.async.commit_group;" ::: "memory");
}

__global__ void __launch_bounds__(256) gemm_b_k(
    const u16* __restrict__ Ah, const u16* __restrict__ Al,
    const u16* __restrict__ Bh, const u16* __restrict__ Bl,
    float* __restrict__ Cm, u16* __restrict__ Chi, u16* __restrict__ Clo,
    const float* __restrict__ bias, const float* __restrict__ resid,
    int M, int N, int K, int act, int rmode)
{
    extern __shared__ char smem[];
    uint32_t sb = smem_u32(smem);
    int tid = threadIdx.x, wid = tid >> 5, lane = tid & 31;
    int g = lane >> 2, tg = lane & 3;
    int wm = (wid >> 2) * 64, wn = (wid & 3) * 32;
    int m0 = blockIdx.y * 128, n0 = blockIdx.x * 128;

    float acc[4][4][4];
#pragma unroll
    for (int i = 0; i < 4; i++)
#pragma unroll
        for (int j = 0; j < 4; j++)
#pragma unroll
            for (int r = 0; r < 4; r++) acc[i][j][r] = 0.f;

    int nch = K >> 5;
    gb_stage(sb, Ah, Al, Bh, Bl, m0, n0, M, N, K, 0, tid);

    for (int c = 0; c < nch; c++) {
        asm volatile("cp.async.wait_group 0;" ::: "memory");
        __syncthreads();
        if (c + 1 < nch)
            gb_stage(sb + ((c + 1) & 1) * 40960, Ah, Al, Bh, Bl,
                     m0, n0, M, N, K, (c + 1) * 32, tid);

        const uint32_t* sw = (const uint32_t*)(smem + (c & 1) * 40960);
        // word offsets: Ah 0, Al 2560, Bh 5120, Bl 7680; row stride 20 words
#pragma unroll
        for (int ks = 0; ks < 2; ks++) {
            int jb = ks * 8;
            uint32_t ah[4][4], al[4][4], bh[4][2], bl[4][2];
#pragma unroll
            for (int mf = 0; mf < 4; mf++) {
                int r0 = (wm + mf * 16 + g) * 20;
                int r1 = (wm + mf * 16 + g + 8) * 20;
                ah[mf][0] = sw[r0 + jb + tg];
                ah[mf][1] = sw[r1 + jb + tg];
                ah[mf][2] = sw[r0 + jb + tg + 4];
                ah[mf][3] = sw[r1 + jb + tg + 4];
                al[mf][0] = sw[2560 + r0 + jb + tg];
                al[mf][1] = sw[2560 + r1 + jb + tg];
                al[mf][2] = sw[2560 + r0 + jb + tg + 4];
                al[mf][3] = sw[2560 + r1 + jb + tg + 4];
            }
#pragma unroll
            for (int nf = 0; nf < 4; nf++) {
                int rn = (wn + nf * 8 + g) * 20;
                bh[nf][0] = sw[5120 + rn + jb + tg];
                bh[nf][1] = sw[5120 + rn + jb + tg + 4];
                bl[nf][0] = sw[7680 + rn + jb + tg];
                bl[nf][1] = sw[7680 + rn + jb + tg + 4];
            }
#pragma unroll
            for (int mf = 0; mf < 4; mf++)
#pragma unroll
                for (int nf = 0; nf < 4; nf++) {
                    mma_bf16(acc[mf][nf], ah[mf], bl[nf]);
                    mma_bf16(acc[mf][nf], al[mf], bh[nf]);
                    mma_bf16(acc[mf][nf], ah[mf], bh[nf]);
                }
        }
    }

    // epilogue
#pragma unroll
    for (int mf = 0; mf < 4; mf++) {
        int mA = m0 + wm + mf * 16 + g;
#pragma unroll
        for (int nf = 0; nf < 4; nf++) {
            int nc = n0 + wn + nf * 8 + 2 * tg;
#pragma unroll
            for (int half = 0; half < 2; half++) {
                int m = mA + half * 8;
                if (m >= M) continue;
#pragma unroll
                for (int jj = 0; jj < 2; jj++) {
                    int nn = nc + jj;
                    if (nn >= N) continue;
                    float v = acc[mf][nf][half * 2 + jj];
                    if (bias)  v += bias[nn];
                    if (rmode == 1) v += resid[(size_t)m * N + nn];
                    else if (rmode == 2) v += resid[(size_t)(m & 15) * 512 + nn];
                    if (act == 1) v = geluf(v);
                    if (Chi) {
                        u16 h, l; split1(v, h, l);
                        Chi[(size_t)m * N + nn] = h;
                        Clo[(size_t)m * N + nn] = l;
                    } else {
                        Cm[(size_t)m * N + nn] = v;
                    }
                }
            }
        }
    }
}

// ---------------- attention ----------------
__global__ void __launch_bounds__(256) attnA_k(const float* __restrict__ Kmat,
                                               const float* __restrict__ Vmat)
{
    __shared__ float sKV[16][514];
    __shared__ float sS[16 * 8 * 16];
    int blk = blockIdx.x, tid = threadIdx.x;
    size_t n0 = (size_t)blk * CHK;

    for (int e = tid; e < 16 * 512; e += 256)
        sKV[e >> 9][e & 511] = Kmat[n0 * Cc + (size_t)(e >> 9) * Cc + (e & 511)];
    __syncthreads();
    {
        int t = tid >> 4, k = tid & 15;
        const float* qrow = g_Qc + t * Cc;
#pragma unroll
        for (int h = 0; h < 8; h++) {
            float s = 0.f;
            const float* kp = &sKV[k][h * 64];
            const float* qp = qrow + h * 64;
#pragma unroll 16
            for (int d = 0; d < 64; d++) s = fmaf(qp[d], kp[d], s);
            sS[(t * 8 + h) * 16 + k] = s * 0.125f;
        }
    }
    __syncthreads();
    if (tid < 128) {
        float* p = &sS[tid * 16];
        float m = p[0];
#pragma unroll
        for (int k = 1; k < 16; k++) m = fmaxf(m, p[k]);
        float sum = 0.f;
#pragma unroll
        for (int k = 0; k < 16; k++) { float e = expf(p[k] - m); p[k] = e; sum += e; }
        float inv = 1.0f / sum;
#pragma unroll
        for (int k = 0; k < 16; k++) p[k] *= inv;
    }
    __syncthreads();
    for (int e = tid; e < 16 * 512; e += 256)
        sKV[e >> 9][e & 511] = Vmat[n0 * Cc + (size_t)(e >> 9) * Cc + (e & 511)];
    __syncthreads();
#pragma unroll
    for (int cc = 0; cc < 2; cc++) {
        int c = tid + cc * 256;
        int h = c >> 6;
#pragma unroll
        for (int t = 0; t < 16; t++) {
            float a = 0.f;
            const float* at = &sS[(t * 8 + h) * 16];
#pragma unroll
            for (int k = 0; k < 16; k++) a = fmaf(at[k], sKV[k][c], a);
            u16 hh, ll; split1(a, hh, ll);
            u_ctxh[(n0 + t) * Cc + c] = hh;
            u_ctxl[(n0 + t) * Cc + c] = ll;
        }
    }
}

__global__ void __launch_bounds__(256) attnB_k(const float* __restrict__ Kmat,
                                               const float* __restrict__ Vmat)
{
    __shared__ float sKV[16][514];
    __shared__ float sS[8 * 16];
    int blk = blockIdx.x, tid = threadIdx.x;
    size_t n0 = (size_t)blk * CHK;

    for (int e = tid; e < 16 * 512; e += 256)
        sKV[e >> 9][e & 511] = Kmat[n0 * Cc + (size_t)(e >> 9) * Cc + (e & 511)];
    __syncthreads();
    if (tid < 128) {
        int h = tid >> 4, k = tid & 15;
        const float* qp = g_Q0 + (size_t)blk * Cc + h * 64;
        const float* kp = &sKV[k][h * 64];
        float s = 0.f;
#pragma unroll 16
        for (int d = 0; d < 64; d++) s = fmaf(qp[d], kp[d], s);
        sS[h * 16 + k] = s * 0.125f;
    }
    __syncthreads();
    if (tid < 8) {
        float* p = &sS[tid * 16];
        float m = p[0];
#pragma unroll
        for (int k = 1; k < 16; k++) m = fmaxf(m, p[k]);
        float sum = 0.f;
#pragma unroll
        for (int k = 0; k < 16; k++) { float e = expf(p[k] - m); p[k] = e; sum += e; }
        float inv = 1.0f / sum;
#pragma unroll
        for (int k = 0; k < 16; k++) p[k] *= inv;
    }
    __syncthreads();
    for (int e = tid; e < 16 * 512; e += 256)
        sKV[e >> 9][e & 511] = Vmat[n0 * Cc + (size_t)(e >> 9) * Cc + (e & 511)];
    __syncthreads();
#pragma unroll
    for (int cc = 0; cc < 2; cc++) {
        int c = tid + cc * 256;
        int h = c >> 6;
        float a = 0.f;
        const float* at = &sS[h * 16];
#pragma unroll
        for (int k = 0; k < 16; k++) a = fmaf(at[k], sKV[k][c], a);
        u16 hh, ll; split1(a, hh, ll);
        u_ctx0h[(size_t)blk * Cc + c] = hh;
        u_ctx0l[(size_t)blk * Cc + c] = ll;
    }
}

// ---------------- residual VQ ----------------
__global__ void __launch_bounds__(256) rvq_k(const float* __restrict__ rD,
                                             u16* __restrict__ qh, u16* __restrict__ ql,
                                             const float* __restrict__ books)
{
    extern __shared__ float sm[];
    float* sRes   = sm;                 // 64*97
    float* sE     = sRes + 64 * 97;     // 128*97
    float* sHN    = sE + 128 * 97;      // 128
    float* sScore = sHN + 128;          // 64*32
    int*   sIdx   = (int*)(sScore + 64 * 32);
    int*   sBest  = sIdx + 64 * 32;

    int tid = threadIdx.x;
    int tr = tid >> 5;
    int tc = tid & 31;
    int m0 = blockIdx.x * 64;

    for (int e = tid; e < 64 * 96; e += 256) {
        int r = e / 96, d = e - r * 96;
        sRes[r * 97 + d] = rD[(size_t)(m0 + r) * CD + d];
    }

    for (int k = 0; k < NBOOK; k++) {
        float best[8]; int bidx[8];
#pragma unroll
        for (int i = 0; i < 8; i++) { best[i] = -3.0e38f; bidx[i] = 0; }

        for (int tile = 0; tile < 8; tile++) {
            __syncthreads();
            const float* bk = books + ((size_t)k * NEMB + tile * 128) * CD;
            for (int e = tid; e < 128 * 96; e += 256) {
                int c = e / 96, d = e - c * 96;
                sE[c * 97 + d] = bk[(size_t)c * CD + d];
            }
            if (tid < 128) sHN[tid] = g_cnorm[k * NEMB + tile * 128 + tid];
            __syncthreads();

            float acc[8][4];
#pragma unroll
            for (int i = 0; i < 8; i++)
#pragma unroll
                for (int j = 0; j < 4; j++) acc[i][j] = 0.f;
            const float* rp = &sRes[(tr * 8) * 97];
#pragma unroll 2
            for (int d = 0; d < 96; d++) {
                float a0 = rp[0 * 97 + d], a1 = rp[1 * 97 + d];
                float a2 = rp[2 * 97 + d], a3 = rp[3 * 97 + d];
                float a4 = rp[4 * 97 + d], a5 = rp[5 * 97 + d];
                float a6 = rp[6 * 97 + d], a7 = rp[7 * 97 + d];
#pragma unroll
                for (int j = 0; j < 4; j++) {
                    float bv = sE[(tc + 32 * j) * 97 + d];
                    acc[0][j] = fmaf(a0, bv, acc[0][j]);
                    acc[1][j] = fmaf(a1, bv, acc[1][j]);
                    acc[2][j] = fmaf(a2, bv, acc[2][j]);
                    acc[3][j] = fmaf(a3, bv, acc[3][j]);
                    acc[4][j] = fmaf(a4, bv, acc[4][j]);
                    acc[5][j] = fmaf(a5, bv, acc[5][j]);
                    acc[6][j] = fmaf(a6, bv, acc[6][j]);
                    acc[7][j] = fmaf(a7, bv, acc[7][j]);
                }
            }
#pragma unroll
            for (int i = 0; i < 8; i++)
#pragma unroll
                for (int j = 0; j < 4; j++) {
                    float sc = acc[i][j] - sHN[tc + 32 * j];
                    int code = tile * 128 + tc + 32 * j;
                    if (sc > best[i] || (sc == best[i] && code < bidx[i])) {
                        best[i] = sc; bidx[i] = code;
                    }
                }
        }
        __syncthreads();
#pragma unroll
        for (int i = 0; i < 8; i++) {
            sScore[(tr * 8 + i) * 32 + tc] = best[i];
            sIdx  [(tr * 8 + i) * 32 + tc] = bidx[i];
        }
        __syncthreads();
        if (tid < 64) {
            float bs = -3.0e38f; int bi = 0x7fffffff;
            for (int u = 0; u < 32; u++) {
                float s = sScore[tid * 32 + u]; int ii = sIdx[tid * 32 + u];
                if (s > bs || (s == bs && ii < bi)) { bs = s; bi = ii; }
            }
            sBest[tid] = bi;
        }
        __syncthreads();
        const float* bkb = books + (size_t)k * NEMB * CD;
        for (int e = tid; e < 64 * 96; e += 256) {
            int r = e / 96, d = e - r * 96;
            sRes[r * 97 + d] -= bkb[(size_t)sBest[r] * CD + d];
        }
    }
    __syncthreads();
    for (int e = tid; e < 64 * 96; e += 256) {
        int r = e / 96, d = e - r * 96;
        float v = rD[(size_t)(m0 + r) * CD + d] - sRes[r * 97 + d];
        u16 h, l; split1(v, h, l);
        qh[(size_t)(m0 + r) * CD + d] = h;
        ql[(size_t)(m0 + r) * CD + d] = l;
    }
}

// ---------------- host side ----------------
template<typename T>
static T* sym(const void* s) { void* p = nullptr; cudaGetSymbolAddress(&p, s); return (T*)p; }

static void gemmb(const u16* Ah, const u16* Al, const u16* Bh, const u16* Bl,
                  float* Cm, u16* Chi, u16* Clo,
                  const float* bias, const float* resid,
                  int M, int N, int K, int act, int rmode)
{
    static bool attr = false;
    if (!attr) {
        cudaFuncSetAttribute(gemm_b_k, cudaFuncAttributeMaxDynamicSharedMemorySize, GB_SMEM);
        attr = true;
    }
    dim3 grid((N + 127) / 128, (M + 127) / 128);
    gemm_b_k<<<grid, 256, GB_SMEM>>>(Ah, Al, Bh, Bl, Cm, Chi, Clo, bias, resid,
                                     M, N, K, act, rmode);
}

extern "C" void kernel_launch(void* const* d_in, const int* in_sizes, int n_in,
                              void* d_out, int out_size)
{
    const float* qa    = (const float*)d_in[0];
    const float* zt    = (const float*)d_in[1];
    const float* lnq_g = (const float*)d_in[2];
    const float* lnq_b = (const float*)d_in[3];
    const float* lnkv_g= (const float*)d_in[4];
    const float* lnkv_b= (const float*)d_in[5];
    const float* Wq    = (const float*)d_in[6];
    const float* Wk    = (const float*)d_in[7];
    const float* Wv    = (const float*)d_in[8];
    const float* Wo    = (const float*)d_in[9];
    const float* ffn_g = (const float*)d_in[10];
    const float* ffn_b = (const float*)d_in[11];
    const float* W1    = (const float*)d_in[12];
    const float* b1    = (const float*)d_in[13];
    const float* W2    = (const float*)d_in[14];
    const float* b2    = (const float*)d_in[15];
    const float* tn_g  = (const float*)d_in[16];
    const float* tn_b  = (const float*)d_in[17];
    const float* scale = (const float*)d_in[18];
    const float* Wd    = (const float*)d_in[19];
    const float* bd    = (const float*)d_in[20];
    const float* Wu    = (const float*)d_in[21];
    const float* bu    = (const float*)d_in[22];
    const float* books = (const float*)d_in[23];
    float* out = (float*)d_out;

    // fp32 symbols
    float* p_Qc  = sym<float>(g_Qc);
    float* p_K   = sym<float>(g_K);
    float* p_V   = sym<float>(g_V);
    float* p_y   = sym<float>(g_y);
    float* p_rD  = sym<float>(g_rD);
    float* p_zh  = sym<float>(g_zhat);
    float* p_qln = sym<float>(g_qln);
    float* p_q0  = sym<float>(g_q0);
    float* p_Q0  = sym<float>(g_Q0);
    float* p_y0  = sym<float>(g_y0);
    float* p_rD0 = sym<float>(g_rD0);
    float* p_zh0 = sym<float>(g_zh0);

    // u16 symbols
    u16* qlh = sym<u16>(u_qlnh); u16* qll = sym<u16>(u_qlnl);
    u16* kvh = sym<u16>(u_kvh);  u16* kvl = sym<u16>(u_kvl);
    u16* cth = sym<u16>(u_ctxh); u16* ctl = sym<u16>(u_ctxl);
    u16* lnh = sym<u16>(u_lnh);  u16* lnl = sym<u16>(u_lnl);
    u16* hh  = sym<u16>(u_hh);   u16* hl  = sym<u16>(u_hl);
    u16* xdh = sym<u16>(u_xdh);  u16* xdl = sym<u16>(u_xdl);
    u16* qdh = sym<u16>(u_qdh);  u16* qdl = sym<u16>(u_qdl);
    u16* q0h = sym<u16>(u_q0h);  u16* q0l = sym<u16>(u_q0l);
    u16* c0h = sym<u16>(u_ctx0h);u16* c0l = sym<u16>(u_ctx0l);
    u16* l0h = sym<u16>(u_ln0h); u16* l0l = sym<u16>(u_ln0l);
    u16* h0h = sym<u16>(u_h0h);  u16* h0l = sym<u16>(u_h0l);
    u16* x0h = sym<u16>(u_xd0h); u16* x0l = sym<u16>(u_xd0l);
    u16* d0h = sym<u16>(u_qd0h); u16* d0l = sym<u16>(u_qd0l);

    u16* wqh = sym<u16>(w_qh); u16* wql = sym<u16>(w_ql);
    u16* wkh = sym<u16>(w_kh); u16* wkl = sym<u16>(w_kl);
    u16* wvh = sym<u16>(w_vh); u16* wvl = sym<u16>(w_vl);
    u16* woh = sym<u16>(w_oh); u16* wol = sym<u16>(w_ol);
    u16* w1h = sym<u16>(w_1h); u16* w1l = sym<u16>(w_1l);
    u16* w2h = sym<u16>(w_2h); u16* w2l = sym<u16>(w_2l);
    u16* wdh = sym<u16>(w_dh); u16* wdl = sym<u16>(w_dl);
    u16* wuh = sym<u16>(w_uh); u16* wul = sym<u16>(w_ul);

    size_t rvq_smem = (size_t)(64 * 97 + 128 * 97 + 128 + 64 * 32) * 4
                    + (size_t)(64 * 32 + 64) * 4;
    cudaFuncSetAttribute(rvq_k, cudaFuncAttributeMaxDynamicSharedMemorySize,
                         (int)rvq_smem);

    // ---- weight prep ----
    wsplitT_k<<<(512 * 512 + 255) / 256, 256>>>(Wq, wqh, wql, 512, 512);
    wsplitT_k<<<(512 * 512 + 255) / 256, 256>>>(Wk, wkh, wkl, 512, 512);
    wsplitT_k<<<(512 * 512 + 255) / 256, 256>>>(Wv, wvh, wvl, 512, 512);
    wsplitT_k<<<(512 * 512 + 255) / 256, 256>>>(Wo, woh, wol, 512, 512);
    wsplitT_k<<<(512 * 1024 + 255) / 256, 256>>>(W1, w1h, w1l, 512, 1024);
    wsplitT_k<<<(1024 * 512 + 255) / 256, 256>>>(W2, w2h, w2l, 1024, 512);
    wsplit_k<<<(96 * 512 + 255) / 256, 256>>>(Wd, wdh, wdl, 96 * 512);
    wsplit_k<<<(512 * 96 + 255) / 256, 256>>>(Wu, wuh, wul, 512 * 96);

    // ---- prep ----
    prep_pe_qln_k<<<16, 256>>>(lnq_g, lnq_b);
    prep_cnorm_k<<<32, 256>>>(books);
    kvln2_k<<<M2, 256>>>(qa, lnkv_g, lnkv_b);

    // ---- pass A ----
    gemmb(qlh, qll, wqh, wql, p_Qc, nullptr, nullptr, nullptr, nullptr, 16, 512, 512, 0, 0);
    gemmb(kvh, kvl, wkh, wkl, p_K, nullptr, nullptr, nullptr, nullptr, MR, 512, 512, 0, 0);
    gemmb(kvh, kvl, wvh, wvl, p_V, nullptr, nullptr, nullptr, nullptr, MR, 512, 512, 0, 0);
    attnA_k<<<M2, 256>>>(p_K, p_V);
    gemmb(cth, ctl, woh, wol, p_y, nullptr, nullptr, nullptr, p_qln, MR, 512, 512, 0, 2);
    ln_rows_k<<<MR, 256>>>(p_y, lnh, lnl, ffn_g, ffn_b);
    gemmb(lnh, lnl, w1h, w1l, nullptr, hh, hl, b1, nullptr, MR, 1024, 512, 1, 0);
    gemmb(hh, hl, w2h, w2l, p_y, nullptr, nullptr, b2, p_y, MR, 512, 1024, 0, 1);
    residA2_k<<<M2, 256>>>(zt, p_y, tn_g, tn_b, scale);
    gemmb(xdh, xdl, wdh, wdl, p_rD, nullptr, nullptr, bd, nullptr, MR, 96, 512, 0, 0);
    rvq_k<<<MR / 64, 256, rvq_smem>>>(p_rD, qdh, qdl, books);
    gemmb(qdh, qdl, wuh, wul, p_zh, nullptr, nullptr, bu, p_y, MR, 512, 96, 0, 1);
    scatterA2_k<<<M2, 256>>>(p_zh, out);

    // ---- pass B ----
    q0ln_k<<<M2, 256>>>(lnq_g, lnq_b);
    gemmb(q0h, q0l, wqh, wql, p_Q0, nullptr, nullptr, nullptr, nullptr, M2, 512, 512, 0, 0);
    attnB_k<<<M2, 256>>>(p_K, p_V);
    gemmb(c0h, c0l, woh, wol, p_y0, nullptr, nullptr, nullptr, p_q0, M2, 512, 512, 0, 1);
    ln_rows_k<<<M2, 256>>>(p_y0, l0h, l0l, ffn_g, ffn_b);
    gemmb(l0h, l0l, w1h, w1l, nullptr, h0h, h0l, b1, nullptr, M2, 1024, 512, 1, 0);
    gemmb(h0h, h0l, w2h, w2l, p_y0, nullptr, nullptr, b2, p_y0, M2, 512, 1024, 0, 1);
    residB_k<<<M2, 256>>>(zt, p_y0, tn_g, tn_b, scale);
    gemmb(x0h, x0l, wdh, wdl, p_rD0, nullptr, nullptr, bd, nullptr, M2, 96, 512, 0, 0);
    rvq_k<<<M2 / 64, 256, rvq_smem>>>(p_rD0, d0h, d0l, books);
    gemmb(d0h, d0l, wuh, wul, p_zh0, nullptr, nullptr, bu, p_y0, M2, 512, 96, 0, 1);
    scatterB_k<<<M2 * Cc / 256, 256>>>(p_zh0, out);
}

// round 8
// speedup vs baseline: 2.5961x; 1.7203x over previous
#include <cuda_runtime.h>
#include <cuda_bf16.h>
#include <math.h>
#include <stdint.h>

typedef unsigned short u16;

// ---------------- problem constants ----------------
#define Bb    8
#define Cc    512
#define Tt    4096
#define CHK   16
#define CD    96
#define NBOOK 8
#define NEMB  1024
#define NCH   256
#define MR    (NCH*Bb*CHK)   // 32768
#define M2    (NCH*Bb)       // 2048

// ---------------- fp32 scratch ----------------
__device__ float g_pe[Cc*CHK];
__device__ float g_qln[CHK*Cc];
__device__ float g_Qc[CHK*Cc];
__device__ float g_cnorm[NBOOK*NEMB];
__device__ float g_K   [(size_t)MR*Cc];
__device__ float g_V   [(size_t)MR*Cc];
__device__ float g_y   [(size_t)MR*Cc];
__device__ float g_rD  [(size_t)MR*CD];
__device__ float g_zhat[(size_t)MR*Cc];
__device__ float g_prev[(size_t)M2*Cc];
__device__ float g_q0  [(size_t)M2*Cc];
__device__ float g_Q0  [(size_t)M2*Cc];
__device__ float g_y0  [(size_t)M2*Cc];
__device__ float g_rD0 [(size_t)M2*CD];
__device__ float g_zh0 [(size_t)M2*Cc];

// ---------------- bf16 hi/lo scratch (activations) ----------------
__device__ __align__(16) u16 u_qlnh[CHK*Cc],  u_qlnl[CHK*Cc];
__device__ __align__(16) u16 u_kvh [(size_t)MR*Cc],  u_kvl [(size_t)MR*Cc];
__device__ __align__(16) u16 u_ctxh[(size_t)MR*Cc],  u_ctxl[(size_t)MR*Cc];
__device__ __align__(16) u16 u_lnh [(size_t)MR*Cc],  u_lnl [(size_t)MR*Cc];
__device__ __align__(16) u16 u_hh  [(size_t)MR*2*Cc],u_hl  [(size_t)MR*2*Cc];
__device__ __align__(16) u16 u_xdh [(size_t)MR*Cc],  u_xdl [(size_t)MR*Cc];
__device__ __align__(16) u16 u_qdh [(size_t)MR*CD],  u_qdl [(size_t)MR*CD];
__device__ __align__(16) u16 u_q0h [(size_t)M2*Cc],  u_q0l [(size_t)M2*Cc];
__device__ __align__(16) u16 u_ctx0h[(size_t)M2*Cc], u_ctx0l[(size_t)M2*Cc];
__device__ __align__(16) u16 u_ln0h[(size_t)M2*Cc],  u_ln0l[(size_t)M2*Cc];
__device__ __align__(16) u16 u_h0h [(size_t)M2*2*Cc],u_h0l [(size_t)M2*2*Cc];
__device__ __align__(16) u16 u_xd0h[(size_t)M2*Cc],  u_xd0l[(size_t)M2*Cc];
__device__ __align__(16) u16 u_qd0h[(size_t)M2*CD],  u_qd0l[(size_t)M2*CD];

// ---------------- bf16 hi/lo weights (all stored [N][K]) ----------------
__device__ __align__(16) u16 w_qh[Cc*Cc],  w_ql[Cc*Cc];
__device__ __align__(16) u16 w_kh[Cc*Cc],  w_kl[Cc*Cc];
__device__ __align__(16) u16 w_vh[Cc*Cc],  w_vl[Cc*Cc];
__device__ __align__(16) u16 w_oh[Cc*Cc],  w_ol[Cc*Cc];
__device__ __align__(16) u16 w_1h[2*Cc*Cc],w_1l[2*Cc*Cc];
__device__ __align__(16) u16 w_2h[2*Cc*Cc],w_2l[2*Cc*Cc];
__device__ __align__(16) u16 w_dh[CD*Cc],  w_dl[CD*Cc];
__device__ __align__(16) u16 w_uh[Cc*CD],  w_ul[Cc*CD];
// split books
__device__ __align__(16) u16 bk_h[NBOOK*NEMB*CD], bk_l[NBOOK*NEMB*CD];

// ---------------- helpers ----------------
__device__ __forceinline__ float geluf(float x) {
    return 0.5f * x * (1.0f + erff(x * 0.70710678118654752440f));
}
__device__ __forceinline__ void split1(float v, u16& h, u16& l) {
    __nv_bfloat16 hb = __float2bfloat16(v);
    __nv_bfloat16 lb = __float2bfloat16(v - __bfloat162float(hb));
    h = __bfloat16_as_ushort(hb);
    l = __bfloat16_as_ushort(lb);
}
__device__ __forceinline__ void split2(float v0, float v1, uint32_t& hi, uint32_t& lo) {
    u16 h0, l0, h1, l1;
    split1(v0, h0, l0); split1(v1, h1, l1);
    hi = (uint32_t)h0 | ((uint32_t)h1 << 16);
    lo = (uint32_t)l0 | ((uint32_t)l1 << 16);
}
__device__ __forceinline__ uint32_t smem_u32(const void* p) {
    uint32_t a;
    asm("{ .reg .u64 t; cvta.to.shared.u64 t, %1; cvt.u32.u64 %0, t; }" : "=r"(a) : "l"(p));
    return a;
}
__device__ __forceinline__ void cpa16(uint32_t dst, const void* src, int sz) {
    asm volatile("cp.async.cg.shared.global [%0], [%1], 16, %2;"
                 :: "r"(dst), "l"(src), "r"(sz) : "memory");
}
__device__ __forceinline__ void mma_bf16(float* c, const uint32_t* a, const uint32_t* b) {
    asm volatile(
        "mma.sync.aligned.m16n8k16.row.col.f32.bf16.bf16.f32 "
        "{%0,%1,%2,%3}, {%4,%5,%6,%7}, {%8,%9}, {%0,%1,%2,%3};"
        : "+f"(c[0]), "+f"(c[1]), "+f"(c[2]), "+f"(c[3])
        : "r"(a[0]), "r"(a[1]), "r"(a[2]), "r"(a[3]), "r"(b[0]), "r"(b[1]));
}
__device__ __forceinline__ void ldsm4(uint32_t& r0, uint32_t& r1, uint32_t& r2,
                                      uint32_t& r3, uint32_t addr) {
    asm volatile("ldmatrix.sync.aligned.m8n8.x4.shared.b16 {%0,%1,%2,%3}, [%4];"
                 : "=r"(r0), "=r"(r1), "=r"(r2), "=r"(r3) : "r"(addr));
}

// ---------------- weight prep ----------------
__global__ void wsplitT_k(const float* __restrict__ W, u16* __restrict__ oh,
                          u16* __restrict__ ol, int K, int N)
{
    int e = blockIdx.x * 256 + threadIdx.x;
    if (e >= K * N) return;
    int k = e / N, n = e - k * N;
    u16 h, l; split1(W[e], h, l);
    oh[(size_t)n * K + k] = h;
    ol[(size_t)n * K + k] = l;
}
__global__ void wsplit_k(const float* __restrict__ W, u16* __restrict__ oh,
                         u16* __restrict__ ol, int total)
{
    int e = blockIdx.x * 256 + threadIdx.x;
    if (e >= total) return;
    u16 h, l; split1(W[e], h, l);
    oh[e] = h; ol[e] = l;
}

// ---------------- LN helper ----------------
__device__ __forceinline__ float2 block_ln2(float x0, float x1, int c0, int c1,
                                            const float* __restrict__ g,
                                            const float* __restrict__ b,
                                            float* red)
{
    int tid = threadIdx.x, lane = tid & 31, w = tid >> 5;
    float s = x0 + x1;
#pragma unroll
    for (int o = 16; o; o >>= 1) s += __shfl_xor_sync(0xffffffffu, s, o);
    if (lane == 0) red[w] = s;
    __syncthreads();
    float tot = 0.f;
#pragma unroll
    for (int i = 0; i < 8; i++) tot += red[i];
    float mean = tot * (1.0f / 512.0f);
    float d0 = x0 - mean, d1 = x1 - mean;
    float q = d0 * d0 + d1 * d1;
#pragma unroll
    for (int o = 16; o; o >>= 1) q += __shfl_xor_sync(0xffffffffu, q, o);
    __syncthreads();
    if (lane == 0) red[w] = q;
    __syncthreads();
    float tot2 = 0.f;
#pragma unroll
    for (int i = 0; i < 8; i++) tot2 += red[i];
    float inv = rsqrtf(tot2 * (1.0f / 512.0f) + 1e-5f);
    return make_float2(d0 * inv * g[c0] + b[c0], d1 * inv * g[c1] + b[c1]);
}

// ---------------- prep kernels ----------------
__global__ void prep_pe_qln_k(const float* __restrict__ lnq_g,
                              const float* __restrict__ lnq_b)
{
    __shared__ float red[8];
    int t = blockIdx.x, tid = threadIdx.x;
    int c0 = 2 * tid, c1 = c0 + 1;
    double dv = exp((double)c0 * (-log(10000.0) / 512.0));
    double ang = (double)t * dv;
    float v0 = (float)sin(ang);
    float v1 = (float)cos(ang);
    g_pe[c0 * CHK + t] = v0;
    g_pe[c1 * CHK + t] = v1;
    float2 y = block_ln2(v0, v1, c0, c1, lnq_g, lnq_b, red);
    g_qln[t * Cc + c0] = y.x;
    g_qln[t * Cc + c1] = y.y;
    u16 h, l;
    split1(y.x, h, l); u_qlnh[t * Cc + c0] = h; u_qlnl[t * Cc + c0] = l;
    split1(y.y, h, l); u_qlnh[t * Cc + c1] = h; u_qlnl[t * Cc + c1] = l;
}

__global__ void prep_cnorm_k(const float* __restrict__ books)
{
    int idx = blockIdx.x * 256 + threadIdx.x;
    const float* e = books + (size_t)idx * CD;
    float s = 0.f;
#pragma unroll
    for (int d = 0; d < CD; d++) { float v = e[d]; s += v * v; }
    g_cnorm[idx] = 0.5f * s;
}

// coalesced kvln
__global__ void __launch_bounds__(256) kvln2_k(const float* __restrict__ qa,
                                               const float* __restrict__ g,
                                               const float* __restrict__ b)
{
    __shared__ float tile[16][513];
    int blk = blockIdx.x, tid = threadIdx.x;
    int s = blk >> 3, bb = blk & 7;
#pragma unroll
    for (int l = 0; l < 8; l++) {
        int e = tid + l * 256;
        int c = e >> 2, seg = e & 3;
        float4 v = *(const float4*)(qa + ((size_t)(bb * Cc + c)) * Tt + s * CHK + seg * 4);
        tile[seg * 4 + 0][c] = v.x;
        tile[seg * 4 + 1][c] = v.y;
        tile[seg * 4 + 2][c] = v.z;
        tile[seg * 4 + 3][c] = v.w;
    }
    __syncthreads();
    int w = tid >> 5, lane = tid & 31;
#pragma unroll
    for (int t = w; t < 16; t += 8) {
        int n = s * 128 + bb * 16 + t;
        float xs[16], sum = 0.f;
#pragma unroll
        for (int k = 0; k < 16; k++) {
            int c = lane + 32 * k;
            float x = tile[t][c] + g_pe[c * CHK + t];
            xs[k] = x; sum += x;
        }
#pragma unroll
        for (int o = 16; o; o >>= 1) sum += __shfl_xor_sync(0xffffffffu, sum, o);
        float mean = sum * (1.0f / 512.0f);
        float q = 0.f;
#pragma unroll
        for (int k = 0; k < 16; k++) { float d = xs[k] - mean; q += d * d; }
#pragma unroll
        for (int o = 16; o; o >>= 1) q += __shfl_xor_sync(0xffffffffu, q, o);
        float inv = rsqrtf(q * (1.0f / 512.0f) + 1e-5f);
#pragma unroll
        for (int k = 0; k < 16; k++) {
            int c = lane + 32 * k;
            float o2 = (xs[k] - mean) * inv * g[c] + b[c];
            u16 h, l2; split1(o2, h, l2);
            u_kvh[(size_t)n * Cc + c] = h;
            u_kvl[(size_t)n * Cc + c] = l2;
        }
    }
}

__global__ void ln_rows_k(const float* __restrict__ in, u16* __restrict__ oh,
                          u16* __restrict__ ol,
                          const float* __restrict__ g, const float* __restrict__ b)
{
    __shared__ float red[8];
    int n = blockIdx.x, tid = threadIdx.x;
    int c0 = tid, c1 = tid + 256;
    float x0 = in[(size_t)n * Cc + c0];
    float x1 = in[(size_t)n * Cc + c1];
    float2 y = block_ln2(x0, x1, c0, c1, g, b, red);
    u16 h, l;
    split1(y.x, h, l); oh[(size_t)n * Cc + c0] = h; ol[(size_t)n * Cc + c0] = l;
    split1(y.y, h, l); oh[(size_t)n * Cc + c1] = h; ol[(size_t)n * Cc + c1] = l;
}

__global__ void __launch_bounds__(256) residA2_k(const float* __restrict__ zt,
                                                 const float* __restrict__ y,
                                                 const float* __restrict__ g,
                                                 const float* __restrict__ b,
                                                 const float* __restrict__ scale)
{
    __shared__ float tile[16][513];
    int blk = blockIdx.x, tid = threadIdx.x;
    int s = blk >> 3, bb = blk & 7;
    float sc = fminf(fmaxf(scale[0], 0.005f), 0.5f);
#pragma unroll
    for (int l = 0; l < 8; l++) {
        int e = tid + l * 256;
        int c = e >> 2, seg = e & 3;
        float4 v = *(const float4*)(zt + ((size_t)(bb * Cc + c)) * Tt + s * CHK + seg * 4);
        tile[seg * 4 + 0][c] = v.x;
        tile[seg * 4 + 1][c] = v.y;
        tile[seg * 4 + 2][c] = v.z;
        tile[seg * 4 + 3][c] = v.w;
    }
    __syncthreads();
    int w = tid >> 5, lane = tid & 31;
#pragma unroll
    for (int t = w; t < 16; t += 8) {
        int n = s * 128 + bb * 16 + t;
        float xs[16], sum = 0.f;
#pragma unroll
        for (int k = 0; k < 16; k++) {
            int c = lane + 32 * k;
            float x = tile[t][c] - y[(size_t)n * Cc + c];
            xs[k] = x; sum += x;
        }
#pragma unroll
        for (int o = 16; o; o >>= 1) sum += __shfl_xor_sync(0xffffffffu, sum, o);
        float mean = sum * (1.0f / 512.0f);
        float q = 0.f;
#pragma unroll
        for (int k = 0; k < 16; k++) { float d = xs[k] - mean; q += d * d; }
#pragma unroll
        for (int o = 16; o; o >>= 1) q += __shfl_xor_sync(0xffffffffu, q, o);
        float inv = rsqrtf(q * (1.0f / 512.0f) + 1e-5f);
#pragma unroll
        for (int k = 0; k < 16; k++) {
            int c = lane + 32 * k;
            float o2 = sc * tanhf((xs[k] - mean) * inv * g[c] + b[c]);
            u16 h, l2; split1(o2, h, l2);
            u_xdh[(size_t)n * Cc + c] = h;
            u_xdl[(size_t)n * Cc + c] = l2;
        }
    }
}

__global__ void residB_k(const float* __restrict__ zt, const float* __restrict__ y,
                         const float* __restrict__ g, const float* __restrict__ b,
                         const float* __restrict__ scale)
{
    __shared__ float red[8];
    int n = blockIdx.x, tid = threadIdx.x;
    int s = n >> 3, bb = n & 7;
    int tg = s * CHK;
    float sc = fminf(fmaxf(scale[0], 0.005f), 0.5f);
    int c0 = tid, c1 = tid + 256;
    float x0 = zt[((size_t)(bb * Cc + c0)) * Tt + tg] - y[(size_t)n * Cc + c0];
    float x1 = zt[((size_t)(bb * Cc + c1)) * Tt + tg] - y[(size_t)n * Cc + c1];
    float2 o = block_ln2(x0, x1, c0, c1, g, b, red);
    u16 h, l;
    split1(sc * tanhf(o.x), h, l); u_xd0h[(size_t)n * Cc + c0] = h; u_xd0l[(size_t)n * Cc + c0] = l;
    split1(sc * tanhf(o.y), h, l); u_xd0h[(size_t)n * Cc + c1] = h; u_xd0l[(size_t)n * Cc + c1] = l;
}

__global__ void q0ln_k(const float* __restrict__ g, const float* __restrict__ b)
{
    __shared__ float red[8];
    int n = blockIdx.x, tid = threadIdx.x;
    int s = n >> 3;
    int c0 = tid, c1 = tid + 256;
    float p0 = (s > 0) ? g_prev[(size_t)(n - Bb) * Cc + c0] : 0.f;
    float p1 = (s > 0) ? g_prev[(size_t)(n - Bb) * Cc + c1] : 0.f;
    float x0 = p0 + g_pe[c0 * CHK + 0];
    float x1 = p1 + g_pe[c1 * CHK + 0];
    float2 y = block_ln2(x0, x1, c0, c1, g, b, red);
    g_q0[(size_t)n * Cc + c0] = y.x;
    g_q0[(size_t)n * Cc + c1] = y.y;
    u16 h, l;
    split1(y.x, h, l); u_q0h[(size_t)n * Cc + c0] = h; u_q0l[(size_t)n * Cc + c0] = l;
    split1(y.y, h, l); u_q0h[(size_t)n * Cc + c1] = h; u_q0l[(size_t)n * Cc + c1] = l;
}

__global__ void __launch_bounds__(256) scatterA2_k(const float* __restrict__ zhat,
                                                   float* __restrict__ out)
{
    __shared__ float tile[16][513];
    int blk = blockIdx.x, tid = threadIdx.x;
    int s = blk >> 3, bb = blk & 7;
    int n0 = s * 128 + bb * 16;
#pragma unroll
    for (int l = 0; l < 32; l++) {
        int e = tid + l * 256;
        int t = e >> 9, c = e & 511;
        float v = zhat[((size_t)(n0 + t)) * Cc + c];
        tile[t][c] = v;
        if (t == 15) g_prev[(size_t)(s * 8 + bb) * Cc + c] = v;
    }
    __syncthreads();
#pragma unroll
    for (int l = 0; l < 8; l++) {
        int e = tid + l * 256;
        int c = e >> 2, seg = e & 3;
        float4 v = make_float4(tile[seg * 4 + 0][c], tile[seg * 4 + 1][c],
                               tile[seg * 4 + 2][c], tile[seg * 4 + 3][c]);
        *(float4*)(out + ((size_t)(bb * Cc + c)) * Tt + s * CHK + seg * 4) = v;
    }
}

__global__ void scatterB_k(const float* __restrict__ zh0, float* __restrict__ out)
{
    int idx = blockIdx.x * 256 + threadIdx.x;
    int n = idx >> 9, c = idx & 511;
    int s = n >> 3, bb = n & 7;
    out[((size_t)(bb * Cc + c)) * Tt + s * CHK] = zh0[(size_t)idx];
}

// ---------------- split-bf16 GEMM: cp.async staging + ldmatrix frags ----------------
#define GB_SMEM (2 * 40960)

__device__ __forceinline__ void gb_stage(uint32_t sbase,
    const u16* __restrict__ Ah, const u16* __restrict__ Al,
    const u16* __restrict__ Bh, const u16* __restrict__ Bl,
    int m0, int n0, int M, int N, int K, int k0, int tid)
{
#pragma unroll
    for (int l = 0; l < 2; l++) {
        int e = tid + l * 256;
        int row = e >> 2, seg = e & 3;
        uint32_t d = sbase + row * 80 + seg * 16;
        size_t oa = (size_t)(m0 + row) * K + k0 + seg * 8;
        int szA = (m0 + row < M) ? 16 : 0;
        cpa16(d,         Ah + oa, szA);
        cpa16(d + 10240, Al + oa, szA);
        size_t ob = (size_t)(n0 + row) * K + k0 + seg * 8;
        int szB = (n0 + row < N) ? 16 : 0;
        cpa16(d + 20480, Bh + ob, szB);
        cpa16(d + 30720, Bl + ob, szB);
    }
    asm volatile("cp.async.commit_group;" ::: "memory");
}

__global__ void __launch_bounds__(256) gemm_b_k(
    const u16* __restrict__ Ah, const u16* __restrict__ Al,
    const u16* __restrict__ Bh, const u16* __restrict__ Bl,
    float* __restrict__ Cm, u16* __restrict__ Chi, u16* __restrict__ Clo,
    const float* __restrict__ bias, const float* __restrict__ resid,
    int M, int N, int K, int act, int rmode)
{
    extern __shared__ char smem[];
    uint32_t sb = smem_u32(smem);
    int tid = threadIdx.x, wid = tid >> 5, lane = tid & 31;
    int g = lane >> 2, tg = lane & 3;
    int wm = (wid >> 2) * 64, wn = (wid & 3) * 32;
    int m0 = blockIdx.y * 128, n0 = blockIdx.x * 128;

    float acc[4][4][4];
#pragma unroll
    for (int i = 0; i < 4; i++)
#pragma unroll
        for (int j = 0; j < 4; j++)
#pragma unroll
            for (int r = 0; r < 4; r++) acc[i][j][r] = 0.f;

    // ldmatrix address components (verified to reproduce the scalar frag layout)
    uint32_t aOffH = (uint32_t)(wm + (lane & 15)) * 80 + ((lane >> 4) & 1) * 16;
    uint32_t aOffL = aOffH + 10240;
    uint32_t bOffH = 20480u + (uint32_t)(wn + ((lane >> 4) & 1) * 8 + (lane & 7)) * 80
                   + ((lane >> 3) & 1) * 16;
    uint32_t bOffL = bOffH + 10240;

    int nch = K >> 5;
    gb_stage(sb, Ah, Al, Bh, Bl, m0, n0, M, N, K, 0, tid);

    for (int c = 0; c < nch; c++) {
        asm volatile("cp.async.wait_group 0;" ::: "memory");
        __syncthreads();
        if (c + 1 < nch)
            gb_stage(sb + ((c + 1) & 1) * 40960, Ah, Al, Bh, Bl,
                     m0, n0, M, N, K, (c + 1) * 32, tid);

        uint32_t sbuf = sb + (c & 1) * 40960;
#pragma unroll
        for (int ks = 0; ks < 2; ks++) {
            uint32_t kb = ks * 32;
            uint32_t bh[4][2], bl[4][2];
#pragma unroll
            for (int nfp = 0; nfp < 2; nfp++) {
                ldsm4(bh[2*nfp][0], bh[2*nfp][1], bh[2*nfp+1][0], bh[2*nfp+1][1],
                      sbuf + bOffH + nfp * 1280 + kb);
                ldsm4(bl[2*nfp][0], bl[2*nfp][1], bl[2*nfp+1][0], bl[2*nfp+1][1],
                      sbuf + bOffL + nfp * 1280 + kb);
            }
#pragma unroll
            for (int mf = 0; mf < 4; mf++) {
                uint32_t ah[4], al[4];
                ldsm4(ah[0], ah[1], ah[2], ah[3], sbuf + aOffH + mf * 1280 + kb);
                ldsm4(al[0], al[1], al[2], al[3], sbuf + aOffL + mf * 1280 + kb);
#pragma unroll
                for (int nf = 0; nf < 4; nf++) {
                    mma_bf16(acc[mf][nf], ah, bl[nf]);
                    mma_bf16(acc[mf][nf], al, bh[nf]);
                    mma_bf16(acc[mf][nf], ah, bh[nf]);
                }
            }
        }
        __syncthreads();
    }

    // epilogue
#pragma unroll
    for (int mf = 0; mf < 4; mf++) {
        int mA = m0 + wm + mf * 16 + g;
#pragma unroll
        for (int nf = 0; nf < 4; nf++) {
            int nc = n0 + wn + nf * 8 + 2 * tg;
#pragma unroll
            for (int half = 0; half < 2; half++) {
                int m = mA + half * 8;
                if (m >= M) continue;
#pragma unroll
                for (int jj = 0; jj < 2; jj++) {
                    int nn = nc + jj;
                    if (nn >= N) continue;
                    float v = acc[mf][nf][half * 2 + jj];
                    if (bias)  v += bias[nn];
                    if (rmode == 1) v += resid[(size_t)m * N + nn];
                    else if (rmode == 2) v += resid[(size_t)(m & 15) * 512 + nn];
                    if (act == 1) v = geluf(v);
                    if (Chi) {
                        u16 h, l; split1(v, h, l);
                        Chi[(size_t)m * N + nn] = h;
                        Clo[(size_t)m * N + nn] = l;
                    } else {
                        Cm[(size_t)m * N + nn] = v;
                    }
                }
            }
        }
    }
}

// ---------------- attention ----------------
__global__ void __launch_bounds__(256) attnA_k(const float* __restrict__ Kmat,
                                               const float* __restrict__ Vmat)
{
    __shared__ float sKV[16][514];
    __shared__ float sS[16 * 8 * 16];
    int blk = blockIdx.x, tid = threadIdx.x;
    size_t n0 = (size_t)blk * CHK;

    for (int e = tid; e < 16 * 512; e += 256)
        sKV[e >> 9][e & 511] = Kmat[n0 * Cc + (size_t)(e >> 9) * Cc + (e & 511)];
    __syncthreads();
    {
        int t = tid >> 4, k = tid & 15;
        const float* qrow = g_Qc + t * Cc;
#pragma unroll
        for (int h = 0; h < 8; h++) {
            float s = 0.f;
            const float* kp = &sKV[k][h * 64];
            const float* qp = qrow + h * 64;
#pragma unroll 16
            for (int d = 0; d < 64; d++) s = fmaf(qp[d], kp[d], s);
            sS[(t * 8 + h) * 16 + k] = s * 0.125f;
        }
    }
    __syncthreads();
    if (tid < 128) {
        float* p = &sS[tid * 16];
        float m = p[0];
#pragma unroll
        for (int k = 1; k < 16; k++) m = fmaxf(m, p[k]);
        float sum = 0.f;
#pragma unroll
        for (int k = 0; k < 16; k++) { float e = expf(p[k] - m); p[k] = e; sum += e; }
        float inv = 1.0f / sum;
#pragma unroll
        for (int k = 0; k < 16; k++) p[k] *= inv;
    }
    __syncthreads();
    for (int e = tid; e < 16 * 512; e += 256)
        sKV[e >> 9][e & 511] = Vmat[n0 * Cc + (size_t)(e >> 9) * Cc + (e & 511)];
    __syncthreads();
#pragma unroll
    for (int cc = 0; cc < 2; cc++) {
        int c = tid + cc * 256;
        int h = c >> 6;
#pragma unroll
        for (int t = 0; t < 16; t++) {
            float a = 0.f;
            const float* at = &sS[(t * 8 + h) * 16];
#pragma unroll
            for (int k = 0; k < 16; k++) a = fmaf(at[k], sKV[k][c], a);
            u16 hh, ll; split1(a, hh, ll);
            u_ctxh[(n0 + t) * Cc + c] = hh;
            u_ctxl[(n0 + t) * Cc + c] = ll;
        }
    }
}

__global__ void __launch_bounds__(256) attnB_k(const float* __restrict__ Kmat,
                                               const float* __restrict__ Vmat)
{
    __shared__ float sKV[16][514];
    __shared__ float sS[8 * 16];
    int blk = blockIdx.x, tid = threadIdx.x;
    size_t n0 = (size_t)blk * CHK;

    for (int e = tid; e < 16 * 512; e += 256)
        sKV[e >> 9][e & 511] = Kmat[n0 * Cc + (size_t)(e >> 9) * Cc + (e & 511)];
    __syncthreads();
    if (tid < 128) {
        int h = tid >> 4, k = tid & 15;
        const float* qp = g_Q0 + (size_t)blk * Cc + h * 64;
        const float* kp = &sKV[k][h * 64];
        float s = 0.f;
#pragma unroll 16
        for (int d = 0; d < 64; d++) s = fmaf(qp[d], kp[d], s);
        sS[h * 16 + k] = s * 0.125f;
    }
    __syncthreads();
    if (tid < 8) {
        float* p = &sS[tid * 16];
        float m = p[0];
#pragma unroll
        for (int k = 1; k < 16; k++) m = fmaxf(m, p[k]);
        float sum = 0.f;
#pragma unroll
        for (int k = 0; k < 16; k++) { float e = expf(p[k] - m); p[k] = e; sum += e; }
        float inv = 1.0f / sum;
#pragma unroll
        for (int k = 0; k < 16; k++) p[k] *= inv;
    }
    __syncthreads();
    for (int e = tid; e < 16 * 512; e += 256)
        sKV[e >> 9][e & 511] = Vmat[n0 * Cc + (size_t)(e >> 9) * Cc + (e & 511)];
    __syncthreads();
#pragma unroll
    for (int cc = 0; cc < 2; cc++) {
        int c = tid + cc * 256;
        int h = c >> 6;
        float a = 0.f;
        const float* at = &sS[h * 16];
#pragma unroll
        for (int k = 0; k < 16; k++) a = fmaf(at[k], sKV[k][c], a);
        u16 hh, ll; split1(a, hh, ll);
        u_ctx0h[(size_t)blk * Cc + c] = hh;
        u_ctx0l[(size_t)blk * Cc + c] = ll;
    }
}

// ---------------- residual VQ: tensor-core scoring ----------------
// 64 rows/block, 256 threads (8 warps). Residual fp32 in smem (exact updates);
// scoring via split-bf16 m16n8k16 MMAs against pre-split books.
// smem layout (byte offsets):
//  0      sRes fp32 [64][97]            (24832)
//  24832  sAh u16-pairs [64 rows x 208B] (13312)
//  38144  sAl
//  51456  sBh [64 codes x 208B]
//  64768  sBl
//  78080  sHN fp32 [64]
//  78336  sScore fp32 [64][8]
//  80384  sIdx  int  [64][8]
//  82432  sBest int [64]
#define RVQ_SMEM 82688

__global__ void __launch_bounds__(256) rvq_k(const float* __restrict__ rD,
                                             u16* __restrict__ qh, u16* __restrict__ ql,
                                             const float* __restrict__ books,
                                             const u16* __restrict__ bkh,
                                             const u16* __restrict__ bkl)
{
    extern __shared__ char sm[];
    float* sRes  = (float*)sm;
    uint32_t sb  = smem_u32(sm);
    const uint32_t oAh = 24832, oAl = 38144, oBh = 51456, oBl = 64768;
    float* sHN    = (float*)(sm + 78080);
    float* sScore = (float*)(sm + 78336);
    int*   sIdx   = (int*)  (sm + 80384);
    int*   sBest  = (int*)  (sm + 82432);

    int tid = threadIdx.x, wid = tid >> 5, lane = tid & 31;
    int g = lane >> 2, tg = lane & 3;
    int m0 = blockIdx.x * 64;

    for (int e = tid; e < 64 * 96; e += 256) {
        int r = e / 96, d = e - r * 96;
        sRes[r * 97 + d] = rD[(size_t)(m0 + r) * CD + d];
    }

    uint32_t aoff = (uint32_t)(lane & 15) * 208 + ((lane >> 4) & 1) * 16;
    uint32_t boff = (uint32_t)(wid * 8 + (lane & 7)) * 208 + ((lane >> 3) & 3) * 16;

    for (int k = 0; k < NBOOK; k++) {
        __syncthreads();
        // split residual to bf16 hi/lo (A operand)
        for (int e = tid; e < 64 * 48; e += 256) {
            int r = e / 48, w = e - r * 48;
            float v0 = sRes[r * 97 + 2 * w], v1 = sRes[r * 97 + 2 * w + 1];
            uint32_t hi, lo; split2(v0, v1, hi, lo);
            *(uint32_t*)(sm + oAh + r * 208 + w * 4) = hi;
            *(uint32_t*)(sm + oAl + r * 208 + w * 4) = lo;
        }
        float best[8]; int bidx[8];
#pragma unroll
        for (int s = 0; s < 8; s++) { best[s] = -3.0e38f; bidx[s] = 0x7fffffff; }

        for (int ct = 0; ct < 16; ct++) {
            __syncthreads();
            {
                const u16* srcH = bkh + ((size_t)k * NEMB + ct * 64) * CD;
                const u16* srcL = bkl + ((size_t)k * NEMB + ct * 64) * CD;
#pragma unroll
                for (int l = 0; l < 3; l++) {
                    int e = tid + l * 256;          // 0..767 : code*12 + seg
                    int c = e / 12, s2 = e - c * 12;
                    cpa16(sb + oBh + c * 208 + s2 * 16, srcH + c * 96 + s2 * 8, 16);
                    cpa16(sb + oBl + c * 208 + s2 * 16, srcL + c * 96 + s2 * 8, 16);
                }
                asm volatile("cp.async.commit_group;" ::: "memory");
                if (tid < 64) sHN[tid] = g_cnorm[k * NEMB + ct * 64 + tid];
                asm volatile("cp.async.wait_group 0;" ::: "memory");
            }
            __syncthreads();

            float acc[4][4];
#pragma unroll
            for (int i = 0; i < 4; i++)
#pragma unroll
                for (int j = 0; j < 4; j++) acc[i][j] = 0.f;

#pragma unroll
            for (int kcp = 0; kcp < 3; kcp++) {
                uint32_t bhv[4], blv[4];
                ldsm4(bhv[0], bhv[1], bhv[2], bhv[3], sb + oBh + boff + kcp * 64);
                ldsm4(blv[0], blv[1], blv[2], blv[3], sb + oBl + boff + kcp * 64);
#pragma unroll
                for (int sub = 0; sub < 2; sub++) {
                    uint32_t bh2[2] = { bhv[sub * 2], bhv[sub * 2 + 1] };
                    uint32_t bl2[2] = { blv[sub * 2], blv[sub * 2 + 1] };
                    uint32_t ka = (uint32_t)(kcp * 2 + sub) * 32;
#pragma unroll
                    for (int mf = 0; mf < 4; mf++) {
                        uint32_t ah4[4], al4[4];
                        ldsm4(ah4[0], ah4[1], ah4[2], ah4[3],
                              sb + oAh + aoff + (uint32_t)mf * 16 * 208 + ka);
                        ldsm4(al4[0], al4[1], al4[2], al4[3],
                              sb + oAl + aoff + (uint32_t)mf * 16 * 208 + ka);
                        mma_bf16(acc[mf], ah4, bl2);
                        mma_bf16(acc[mf], al4, bh2);
                        mma_bf16(acc[mf], ah4, bh2);
                    }
                }
            }
#pragma unroll
            for (int mf = 0; mf < 4; mf++)
#pragma unroll
                for (int h = 0; h < 2; h++) {
                    int s = mf * 2 + h;
#pragma unroll
                    for (int j = 0; j < 2; j++) {
                        int cl = wid * 8 + 2 * tg + j;
                        float sc = acc[mf][h * 2 + j] - sHN[cl];
                        int code = ct * 64 + cl;
                        if (sc > best[s] || (sc == best[s] && code < bidx[s])) {
                            best[s] = sc; bidx[s] = code;
                        }
                    }
                }
        }
        // reduce across tg lanes (same rows)
#pragma unroll
        for (int s = 0; s < 8; s++) {
#pragma unroll
            for (int off = 1; off <= 2; off <<= 1) {
                float os = __shfl_xor_sync(0xffffffffu, best[s], off);
                int   oi = __shfl_xor_sync(0xffffffffu, bidx[s], off);
                if (os > best[s] || (os == best[s] && oi < bidx[s])) {
                    best[s] = os; bidx[s] = oi;
                }
            }
        }
        if (tg == 0) {
#pragma unroll
            for (int mf = 0; mf < 4; mf++)
#pragma unroll
                for (int h = 0; h < 2; h++) {
                    int r = mf * 16 + 8 * h + g;
                    sScore[r * 8 + wid] = best[mf * 2 + h];
                    sIdx[r * 8 + wid]   = bidx[mf * 2 + h];
                }
        }
        __syncthreads();
        if (tid < 64) {
            float bs = -3.0e38f; int bi = 0x7fffffff;
#pragma unroll
            for (int w = 0; w < 8; w++) {
                float s2 = sScore[tid * 8 + w]; int ii = sIdx[tid * 8 + w];
                if (s2 > bs || (s2 == bs && ii < bi)) { bs = s2; bi = ii; }
            }
            sBest[tid] = bi;
        }
        __syncthreads();
        const float* bkb = books + (size_t)k * NEMB * CD;
        for (int e = tid; e < 64 * 96; e += 256) {
            int r = e / 96, d = e - r * 96;
            sRes[r * 97 + d] -= bkb[(size_t)sBest[r] * CD + d];
        }
    }
    __syncthreads();
    for (int e = tid; e < 64 * 96; e += 256) {
        int r = e / 96, d = e - r * 96;
        float v = rD[(size_t)(m0 + r) * CD + d] - sRes[r * 97 + d];
        u16 h, l; split1(v, h, l);
        qh[(size_t)(m0 + r) * CD + d] = h;
        ql[(size_t)(m0 + r) * CD + d] = l;
    }
}

// ---------------- host side ----------------
template<typename T>
static T* sym(const void* s) { void* p = nullptr; cudaGetSymbolAddress(&p, s); return (T*)p; }

static void gemmb(const u16* Ah, const u16* Al, const u16* Bh, const u16* Bl,
                  float* Cm, u16* Chi, u16* Clo,
                  const float* bias, const float* resid,
                  int M, int N, int K, int act, int rmode)
{
    static bool attr = false;
    if (!attr) {
        cudaFuncSetAttribute(gemm_b_k, cudaFuncAttributeMaxDynamicSharedMemorySize, GB_SMEM);
        attr = true;
    }
    dim3 grid((N + 127) / 128, (M + 127) / 128);
    gemm_b_k<<<grid, 256, GB_SMEM>>>(Ah, Al, Bh, Bl, Cm, Chi, Clo, bias, resid,
                                     M, N, K, act, rmode);
}

extern "C" void kernel_launch(void* const* d_in, const int* in_sizes, int n_in,
                              void* d_out, int out_size)
{
    const float* qa    = (const float*)d_in[0];
    const float* zt    = (const float*)d_in[1];
    const float* lnq_g = (const float*)d_in[2];
    const float* lnq_b = (const float*)d_in[3];
    const float* lnkv_g= (const float*)d_in[4];
    const float* lnkv_b= (const float*)d_in[5];
    const float* Wq    = (const float*)d_in[6];
    const float* Wk    = (const float*)d_in[7];
    const float* Wv    = (const float*)d_in[8];
    const float* Wo    = (const float*)d_in[9];
    const float* ffn_g = (const float*)d_in[10];
    const float* ffn_b = (const float*)d_in[11];
    const float* W1    = (const float*)d_in[12];
    const float* b1    = (const float*)d_in[13];
    const float* W2    = (const float*)d_in[14];
    const float* b2    = (const float*)d_in[15];
    const float* tn_g  = (const float*)d_in[16];
    const float* tn_b  = (const float*)d_in[17];
    const float* scale = (const float*)d_in[18];
    const float* Wd    = (const float*)d_in[19];
    const float* bd    = (const float*)d_in[20];
    const float* Wu    = (const float*)d_in[21];
    const float* bu    = (const float*)d_in[22];
    const float* books = (const float*)d_in[23];
    float* out = (float*)d_out;

    float* p_Qc  = sym<float>(g_Qc);
    float* p_K   = sym<float>(g_K);
    float* p_V   = sym<float>(g_V);
    float* p_y   = sym<float>(g_y);
    float* p_rD  = sym<float>(g_rD);
    float* p_zh  = sym<float>(g_zhat);
    float* p_qln = sym<float>(g_qln);
    float* p_q0  = sym<float>(g_q0);
    float* p_Q0  = sym<float>(g_Q0);
    float* p_y0  = sym<float>(g_y0);
    float* p_rD0 = sym<float>(g_rD0);
    float* p_zh0 = sym<float>(g_zh0);

    u16* qlh = sym<u16>(u_qlnh); u16* qll = sym<u16>(u_qlnl);
    u16* kvh = sym<u16>(u_kvh);  u16* kvl = sym<u16>(u_kvl);
    u16* cth = sym<u16>(u_ctxh); u16* ctl = sym<u16>(u_ctxl);
    u16* lnh = sym<u16>(u_lnh);  u16* lnl = sym<u16>(u_lnl);
    u16* hh  = sym<u16>(u_hh);   u16* hl  = sym<u16>(u_hl);
    u16* xdh = sym<u16>(u_xdh);  u16* xdl = sym<u16>(u_xdl);
    u16* qdh = sym<u16>(u_qdh);  u16* qdl = sym<u16>(u_qdl);
    u16* q0h = sym<u16>(u_q0h);  u16* q0l = sym<u16>(u_q0l);
    u16* c0h = sym<u16>(u_ctx0h);u16* c0l = sym<u16>(u_ctx0l);
    u16* l0h = sym<u16>(u_ln0h); u16* l0l = sym<u16>(u_ln0l);
    u16* h0h = sym<u16>(u_h0h);  u16* h0l = sym<u16>(u_h0l);
    u16* x0h = sym<u16>(u_xd0h); u16* x0l = sym<u16>(u_xd0l);
    u16* d0h = sym<u16>(u_qd0h); u16* d0l = sym<u16>(u_qd0l);

    u16* wqh = sym<u16>(w_qh); u16* wql = sym<u16>(w_ql);
    u16* wkh = sym<u16>(w_kh); u16* wkl = sym<u16>(w_kl);
    u16* wvh = sym<u16>(w_vh); u16* wvl = sym<u16>(w_vl);
    u16* woh = sym<u16>(w_oh); u16* wol = sym<u16>(w_ol);
    u16* w1h = sym<u16>(w_1h); u16* w1l = sym<u16>(w_1l);
    u16* w2h = sym<u16>(w_2h); u16* w2l = sym<u16>(w_2l);
    u16* wdh = sym<u16>(w_dh); u16* wdl = sym<u16>(w_dl);
    u16* wuh = sym<u16>(w_uh); u16* wul = sym<u16>(w_ul);
    u16* bkh = sym<u16>(bk_h); u16* bkl = sym<u16>(bk_l);

    cudaFuncSetAttribute(rvq_k, cudaFuncAttributeMaxDynamicSharedMemorySize, RVQ_SMEM);

    // ---- weight / book prep ----
    wsplitT_k<<<(512 * 512 + 255) / 256, 256>>>(Wq, wqh, wql, 512, 512);
    wsplitT_k<<<(512 * 512 + 255) / 256, 256>>>(Wk, wkh, wkl, 512, 512);
    wsplitT_k<<<(512 * 512 + 255) / 256, 256>>>(Wv, wvh, wvl, 512, 512);
    wsplitT_k<<<(512 * 512 + 255) / 256, 256>>>(Wo, woh, wol, 512, 512);
    wsplitT_k<<<(512 * 1024 + 255) / 256, 256>>>(W1, w1h, w1l, 512, 1024);
    wsplitT_k<<<(1024 * 512 + 255) / 256, 256>>>(W2, w2h, w2l, 1024, 512);
    wsplit_k<<<(96 * 512 + 255) / 256, 256>>>(Wd, wdh, wdl, 96 * 512);
    wsplit_k<<<(512 * 96 + 255) / 256, 256>>>(Wu, wuh, wul, 512 * 96);
    wsplit_k<<<(NBOOK * NEMB * CD + 255) / 256, 256>>>(books, bkh, bkl, NBOOK * NEMB * CD);

    // ---- prep ----
    prep_pe_qln_k<<<16, 256>>>(lnq_g, lnq_b);
    prep_cnorm_k<<<32, 256>>>(books);
    kvln2_k<<<M2, 256>>>(qa, lnkv_g, lnkv_b);

    // ---- pass A ----
    gemmb(qlh, qll, wqh, wql, p_Qc, nullptr, nullptr, nullptr, nullptr, 16, 512, 512, 0, 0);
    gemmb(kvh, kvl, wkh, wkl, p_K, nullptr, nullptr, nullptr, nullptr, MR, 512, 512, 0, 0);
    gemmb(kvh, kvl, wvh, wvl, p_V, nullptr, nullptr, nullptr, nullptr, MR, 512, 512, 0, 0);
    attnA_k<<<M2, 256>>>(p_K, p_V);
    gemmb(cth, ctl, woh, wol, p_y, nullptr, nullptr, nullptr, p_qln, MR, 512, 512, 0, 2);
    ln_rows_k<<<MR, 256>>>(p_y, lnh, lnl, ffn_g, ffn_b);
    gemmb(lnh, lnl, w1h, w1l, nullptr, hh, hl, b1, nullptr, MR, 1024, 512, 1, 0);
    gemmb(hh, hl, w2h, w2l, p_y, nullptr, nullptr, b2, p_y, MR, 512, 1024, 0, 1);
    residA2_k<<<M2, 256>>>(zt, p_y, tn_g, tn_b, scale);
    gemmb(xdh, xdl, wdh, wdl, p_rD, nullptr, nullptr, bd, nullptr, MR, 96, 512, 0, 0);
    rvq_k<<<MR / 64, 256, RVQ_SMEM>>>(p_rD, qdh, qdl, books, bkh, bkl);
    gemmb(qdh, qdl, wuh, wul, p_zh, nullptr, nullptr, bu, p_y, MR, 512, 96, 0, 1);
    scatterA2_k<<<M2, 256>>>(p_zh, out);

    // ---- pass B ----
    q0ln_k<<<M2, 256>>>(lnq_g, lnq_b);
    gemmb(q0h, q0l, wqh, wql, p_Q0, nullptr, nullptr, nullptr, nullptr, M2, 512, 512, 0, 0);
    attnB_k<<<M2, 256>>>(p_K, p_V);
    gemmb(c0h, c0l, woh, wol, p_y0, nullptr, nullptr, nullptr, p_q0, M2, 512, 512, 0, 1);
    ln_rows_k<<<M2, 256>>>(p_y0, l0h, l0l, ffn_g, ffn_b);
    gemmb(l0h, l0l, w1h, w1l, nullptr, h0h, h0l, b1, nullptr, M2, 1024, 512, 1, 0);
    gemmb(h0h, h0l, w2h, w2l, p_y0, nullptr, nullptr, b2, p_y0, M2, 512, 1024, 0, 1);
    residB_k<<<M2, 256>>>(zt, p_y0, tn_g, tn_b, scale);
    gemmb(x0h, x0l, wdh, wdl, p_rD0, nullptr, nullptr, bd, nullptr, M2, 96, 512, 0, 0);
    rvq_k<<<M2 / 64, 256, RVQ_SMEM>>>(p_rD0, d0h, d0l, books, bkh, bkl);
    gemmb(d0h, d0l, wuh, wul, p_zh0, nullptr, nullptr, bu, p_y0, M2, 512, 96, 0, 1);
    scatterB_k<<<M2 * Cc / 256, 256>>>(p_zh0, out);
}

// round 9
// speedup vs baseline: 2.6327x; 1.0141x over previous
#include <cuda_runtime.h>
#include <cuda_bf16.h>
#include <math.h>
#include <stdint.h>

typedef unsigned short u16;

// ---------------- problem constants ----------------
#define Bb    8
#define Cc    512
#define Tt    4096
#define CHK   16
#define CD    96
#define NBOOK 8
#define NEMB  1024
#define NCH   256
#define MR    (NCH*Bb*CHK)   // 32768
#define M2    (NCH*Bb)       // 2048

// ---------------- fp32 scratch ----------------
__device__ float g_pe[Cc*CHK];
__device__ float g_qln[CHK*Cc];
__device__ float g_Qc[CHK*Cc];
__device__ float g_cnorm[NBOOK*NEMB];
__device__ float g_K   [(size_t)MR*Cc];
__device__ float g_V   [(size_t)MR*Cc];
__device__ float g_y   [(size_t)MR*Cc];
__device__ float g_rD  [(size_t)MR*CD];
__device__ float g_zhat[(size_t)MR*Cc];
__device__ float g_prev[(size_t)M2*Cc];
__device__ float g_q0  [(size_t)M2*Cc];
__device__ float g_Q0  [(size_t)M2*Cc];
__device__ float g_y0  [(size_t)M2*Cc];
__device__ float g_rD0 [(size_t)M2*CD];
__device__ float g_zh0 [(size_t)M2*Cc];

// ---------------- bf16 hi/lo scratch (activations) ----------------
__device__ __align__(16) u16 u_qlnh[CHK*Cc],  u_qlnl[CHK*Cc];
__device__ __align__(16) u16 u_kvh [(size_t)MR*Cc],  u_kvl [(size_t)MR*Cc];
__device__ __align__(16) u16 u_ctxh[(size_t)MR*Cc],  u_ctxl[(size_t)MR*Cc];
__device__ __align__(16) u16 u_lnh [(size_t)MR*Cc],  u_lnl [(size_t)MR*Cc];
__device__ __align__(16) u16 u_hh  [(size_t)MR*2*Cc],u_hl  [(size_t)MR*2*Cc];
__device__ __align__(16) u16 u_xdh [(size_t)MR*Cc],  u_xdl [(size_t)MR*Cc];
__device__ __align__(16) u16 u_qdh [(size_t)MR*CD],  u_qdl [(size_t)MR*CD];
__device__ __align__(16) u16 u_q0h [(size_t)M2*Cc],  u_q0l [(size_t)M2*Cc];
__device__ __align__(16) u16 u_ctx0h[(size_t)M2*Cc], u_ctx0l[(size_t)M2*Cc];
__device__ __align__(16) u16 u_ln0h[(size_t)M2*Cc],  u_ln0l[(size_t)M2*Cc];
__device__ __align__(16) u16 u_h0h [(size_t)M2*2*Cc],u_h0l [(size_t)M2*2*Cc];
__device__ __align__(16) u16 u_xd0h[(size_t)M2*Cc],  u_xd0l[(size_t)M2*Cc];
__device__ __align__(16) u16 u_qd0h[(size_t)M2*CD],  u_qd0l[(size_t)M2*CD];

// ---------------- bf16 hi/lo weights (all stored [N][K]) ----------------
__device__ __align__(16) u16 w_qh[Cc*Cc],  w_ql[Cc*Cc];
__device__ __align__(16) u16 w_kh[Cc*Cc],  w_kl[Cc*Cc];
__device__ __align__(16) u16 w_vh[Cc*Cc],  w_vl[Cc*Cc];
__device__ __align__(16) u16 w_oh[Cc*Cc],  w_ol[Cc*Cc];
__device__ __align__(16) u16 w_1h[2*Cc*Cc],w_1l[2*Cc*Cc];
__device__ __align__(16) u16 w_2h[2*Cc*Cc],w_2l[2*Cc*Cc];
__device__ __align__(16) u16 w_dh[CD*Cc],  w_dl[CD*Cc];
__device__ __align__(16) u16 w_uh[Cc*CD],  w_ul[Cc*CD];
__device__ __align__(16) u16 bk_h[NBOOK*NEMB*CD], bk_l[NBOOK*NEMB*CD];

// ---------------- helpers ----------------
__device__ __forceinline__ float geluf(float x) {
    return 0.5f * x * (1.0f + erff(x * 0.70710678118654752440f));
}
__device__ __forceinline__ void split1(float v, u16& h, u16& l) {
    __nv_bfloat16 hb = __float2bfloat16(v);
    __nv_bfloat16 lb = __float2bfloat16(v - __bfloat162float(hb));
    h = __bfloat16_as_ushort(hb);
    l = __bfloat16_as_ushort(lb);
}
__device__ __forceinline__ void split2(float v0, float v1, uint32_t& hi, uint32_t& lo) {
    u16 h0, l0, h1, l1;
    split1(v0, h0, l0); split1(v1, h1, l1);
    hi = (uint32_t)h0 | ((uint32_t)h1 << 16);
    lo = (uint32_t)l0 | ((uint32_t)l1 << 16);
}
__device__ __forceinline__ uint32_t smem_u32(const void* p) {
    uint32_t a;
    asm("{ .reg .u64 t; cvta.to.shared.u64 t, %1; cvt.u32.u64 %0, t; }" : "=r"(a) : "l"(p));
    return a;
}
__device__ __forceinline__ void cpa16(uint32_t dst, const void* src, int sz) {
    asm volatile("cp.async.cg.shared.global [%0], [%1], 16, %2;"
                 :: "r"(dst), "l"(src), "r"(sz) : "memory");
}
__device__ __forceinline__ void mma_bf16(float* c, const uint32_t* a, const uint32_t* b) {
    asm volatile(
        "mma.sync.aligned.m16n8k16.row.col.f32.bf16.bf16.f32 "
        "{%0,%1,%2,%3}, {%4,%5,%6,%7}, {%8,%9}, {%0,%1,%2,%3};"
        : "+f"(c[0]), "+f"(c[1]), "+f"(c[2]), "+f"(c[3])
        : "r"(a[0]), "r"(a[1]), "r"(a[2]), "r"(a[3]), "r"(b[0]), "r"(b[1]));
}
__device__ __forceinline__ void ldsm4(uint32_t& r0, uint32_t& r1, uint32_t& r2,
                                      uint32_t& r3, uint32_t addr) {
    asm volatile("ldmatrix.sync.aligned.m8n8.x4.shared.b16 {%0,%1,%2,%3}, [%4];"
                 : "=r"(r0), "=r"(r1), "=r"(r2), "=r"(r3) : "r"(addr));
}

// ---------------- weight prep ----------------
// four 512x512 [K,N] weights -> [N][K] hi/lo in ONE launch
__global__ void wsplit4T_k(const float* __restrict__ W0, const float* __restrict__ W1,
                           const float* __restrict__ W2, const float* __restrict__ W3,
                           u16* o0h, u16* o0l, u16* o1h, u16* o1l,
                           u16* o2h, u16* o2l, u16* o3h, u16* o3l)
{
    int e = (blockIdx.x & 1023) * 256 + threadIdx.x;   // 0..262143
    int w = blockIdx.x >> 10;
    const float* W = (w == 0) ? W0 : (w == 1) ? W1 : (w == 2) ? W2 : W3;
    u16* oh = (w == 0) ? o0h : (w == 1) ? o1h : (w == 2) ? o2h : o3h;
    u16* ol = (w == 0) ? o0l : (w == 1) ? o1l : (w == 2) ? o2l : o3l;
    int k = e >> 9, n = e & 511;
    u16 h, l; split1(W[e], h, l);
    oh[(size_t)n * 512 + k] = h;
    ol[(size_t)n * 512 + k] = l;
}
__global__ void wsplitT_k(const float* __restrict__ W, u16* __restrict__ oh,
                          u16* __restrict__ ol, int K, int N)
{
    int e = blockIdx.x * 256 + threadIdx.x;
    if (e >= K * N) return;
    int k = e / N, n = e - k * N;
    u16 h, l; split1(W[e], h, l);
    oh[(size_t)n * K + k] = h;
    ol[(size_t)n * K + k] = l;
}
__global__ void wsplit_k(const float* __restrict__ W, u16* __restrict__ oh,
                         u16* __restrict__ ol, int total)
{
    int e = blockIdx.x * 256 + threadIdx.x;
    if (e >= total) return;
    u16 h, l; split1(W[e], h, l);
    oh[e] = h; ol[e] = l;
}

// ---------------- LN helper ----------------
__device__ __forceinline__ float2 block_ln2(float x0, float x1, int c0, int c1,
                                            const float* __restrict__ g,
                                            const float* __restrict__ b,
                                            float* red)
{
    int tid = threadIdx.x, lane = tid & 31, w = tid >> 5;
    float s = x0 + x1;
#pragma unroll
    for (int o = 16; o; o >>= 1) s += __shfl_xor_sync(0xffffffffu, s, o);
    if (lane == 0) red[w] = s;
    __syncthreads();
    float tot = 0.f;
#pragma unroll
    for (int i = 0; i < 8; i++) tot += red[i];
    float mean = tot * (1.0f / 512.0f);
    float d0 = x0 - mean, d1 = x1 - mean;
    float q = d0 * d0 + d1 * d1;
#pragma unroll
    for (int o = 16; o; o >>= 1) q += __shfl_xor_sync(0xffffffffu, q, o);
    __syncthreads();
    if (lane == 0) red[w] = q;
    __syncthreads();
    float tot2 = 0.f;
#pragma unroll
    for (int i = 0; i < 8; i++) tot2 += red[i];
    float inv = rsqrtf(tot2 * (1.0f / 512.0f) + 1e-5f);
    return make_float2(d0 * inv * g[c0] + b[c0], d1 * inv * g[c1] + b[c1]);
}

// ---------------- prep kernels ----------------
__global__ void prep_pe_qln_k(const float* __restrict__ lnq_g,
                              const float* __restrict__ lnq_b)
{
    __shared__ float red[8];
    int t = blockIdx.x, tid = threadIdx.x;
    int c0 = 2 * tid, c1 = c0 + 1;
    double dv = exp((double)c0 * (-log(10000.0) / 512.0));
    double ang = (double)t * dv;
    float v0 = (float)sin(ang);
    float v1 = (float)cos(ang);
    g_pe[c0 * CHK + t] = v0;
    g_pe[c1 * CHK + t] = v1;
    float2 y = block_ln2(v0, v1, c0, c1, lnq_g, lnq_b, red);
    g_qln[t * Cc + c0] = y.x;
    g_qln[t * Cc + c1] = y.y;
    u16 h, l;
    split1(y.x, h, l); u_qlnh[t * Cc + c0] = h; u_qlnl[t * Cc + c0] = l;
    split1(y.y, h, l); u_qlnh[t * Cc + c1] = h; u_qlnl[t * Cc + c1] = l;
}

__global__ void prep_cnorm_k(const float* __restrict__ books)
{
    int idx = blockIdx.x * 256 + threadIdx.x;
    const float* e = books + (size_t)idx * CD;
    float s = 0.f;
#pragma unroll
    for (int d = 0; d < CD; d++) { float v = e[d]; s += v * v; }
    g_cnorm[idx] = 0.5f * s;
}

__global__ void __launch_bounds__(256) kvln2_k(const float* __restrict__ qa,
                                               const float* __restrict__ g,
                                               const float* __restrict__ b)
{
    __shared__ float tile[16][513];
    int blk = blockIdx.x, tid = threadIdx.x;
    int s = blk >> 3, bb = blk & 7;
#pragma unroll
    for (int l = 0; l < 8; l++) {
        int e = tid + l * 256;
        int c = e >> 2, seg = e & 3;
        float4 v = *(const float4*)(qa + ((size_t)(bb * Cc + c)) * Tt + s * CHK + seg * 4);
        tile[seg * 4 + 0][c] = v.x;
        tile[seg * 4 + 1][c] = v.y;
        tile[seg * 4 + 2][c] = v.z;
        tile[seg * 4 + 3][c] = v.w;
    }
    __syncthreads();
    int w = tid >> 5, lane = tid & 31;
#pragma unroll
    for (int t = w; t < 16; t += 8) {
        int n = s * 128 + bb * 16 + t;
        float xs[16], sum = 0.f;
#pragma unroll
        for (int k = 0; k < 16; k++) {
            int c = lane + 32 * k;
            float x = tile[t][c] + g_pe[c * CHK + t];
            xs[k] = x; sum += x;
        }
#pragma unroll
        for (int o = 16; o; o >>= 1) sum += __shfl_xor_sync(0xffffffffu, sum, o);
        float mean = sum * (1.0f / 512.0f);
        float q = 0.f;
#pragma unroll
        for (int k = 0; k < 16; k++) { float d = xs[k] - mean; q += d * d; }
#pragma unroll
        for (int o = 16; o; o >>= 1) q += __shfl_xor_sync(0xffffffffu, q, o);
        float inv = rsqrtf(q * (1.0f / 512.0f) + 1e-5f);
#pragma unroll
        for (int k = 0; k < 16; k++) {
            int c = lane + 32 * k;
            float o2 = (xs[k] - mean) * inv * g[c] + b[c];
            u16 h, l2; split1(o2, h, l2);
            u_kvh[(size_t)n * Cc + c] = h;
            u_kvl[(size_t)n * Cc + c] = l2;
        }
    }
}

__global__ void ln_rows_k(const float* __restrict__ in, u16* __restrict__ oh,
                          u16* __restrict__ ol,
                          const float* __restrict__ g, const float* __restrict__ b)
{
    __shared__ float red[8];
    int n = blockIdx.x, tid = threadIdx.x;
    int c0 = tid, c1 = tid + 256;
    float x0 = in[(size_t)n * Cc + c0];
    float x1 = in[(size_t)n * Cc + c1];
    float2 y = block_ln2(x0, x1, c0, c1, g, b, red);
    u16 h, l;
    split1(y.x, h, l); oh[(size_t)n * Cc + c0] = h; ol[(size_t)n * Cc + c0] = l;
    split1(y.y, h, l); oh[(size_t)n * Cc + c1] = h; ol[(size_t)n * Cc + c1] = l;
}

__global__ void __launch_bounds__(256) residA2_k(const float* __restrict__ zt,
                                                 const float* __restrict__ y,
                                                 const float* __restrict__ g,
                                                 const float* __restrict__ b,
                                                 const float* __restrict__ scale)
{
    __shared__ float tile[16][513];
    int blk = blockIdx.x, tid = threadIdx.x;
    int s = blk >> 3, bb = blk & 7;
    float sc = fminf(fmaxf(scale[0], 0.005f), 0.5f);
#pragma unroll
    for (int l = 0; l < 8; l++) {
        int e = tid + l * 256;
        int c = e >> 2, seg = e & 3;
        float4 v = *(const float4*)(zt + ((size_t)(bb * Cc + c)) * Tt + s * CHK + seg * 4);
        tile[seg * 4 + 0][c] = v.x;
        tile[seg * 4 + 1][c] = v.y;
        tile[seg * 4 + 2][c] = v.z;
        tile[seg * 4 + 3][c] = v.w;
    }
    __syncthreads();
    int w = tid >> 5, lane = tid & 31;
#pragma unroll
    for (int t = w; t < 16; t += 8) {
        int n = s * 128 + bb * 16 + t;
        float xs[16], sum = 0.f;
#pragma unroll
        for (int k = 0; k < 16; k++) {
            int c = lane + 32 * k;
            float x = tile[t][c] - y[(size_t)n * Cc + c];
            xs[k] = x; sum += x;
        }
#pragma unroll
        for (int o = 16; o; o >>= 1) sum += __shfl_xor_sync(0xffffffffu, sum, o);
        float mean = sum * (1.0f / 512.0f);
        float q = 0.f;
#pragma unroll
        for (int k = 0; k < 16; k++) { float d = xs[k] - mean; q += d * d; }
#pragma unroll
        for (int o = 16; o; o >>= 1) q += __shfl_xor_sync(0xffffffffu, q, o);
        float inv = rsqrtf(q * (1.0f / 512.0f) + 1e-5f);
#pragma unroll
        for (int k = 0; k < 16; k++) {
            int c = lane + 32 * k;
            float o2 = sc * tanhf((xs[k] - mean) * inv * g[c] + b[c]);
            u16 h, l2; split1(o2, h, l2);
            u_xdh[(size_t)n * Cc + c] = h;
            u_xdl[(size_t)n * Cc + c] = l2;
        }
    }
}

__global__ void residB_k(const float* __restrict__ zt, const float* __restrict__ y,
                         const float* __restrict__ g, const float* __restrict__ b,
                         const float* __restrict__ scale)
{
    __shared__ float red[8];
    int n = blockIdx.x, tid = threadIdx.x;
    int s = n >> 3, bb = n & 7;
    int tg = s * CHK;
    float sc = fminf(fmaxf(scale[0], 0.005f), 0.5f);
    int c0 = tid, c1 = tid + 256;
    float x0 = zt[((size_t)(bb * Cc + c0)) * Tt + tg] - y[(size_t)n * Cc + c0];
    float x1 = zt[((size_t)(bb * Cc + c1)) * Tt + tg] - y[(size_t)n * Cc + c1];
    float2 o = block_ln2(x0, x1, c0, c1, g, b, red);
    u16 h, l;
    split1(sc * tanhf(o.x), h, l); u_xd0h[(size_t)n * Cc + c0] = h; u_xd0l[(size_t)n * Cc + c0] = l;
    split1(sc * tanhf(o.y), h, l); u_xd0h[(size_t)n * Cc + c1] = h; u_xd0l[(size_t)n * Cc + c1] = l;
}

__global__ void q0ln_k(const float* __restrict__ g, const float* __restrict__ b)
{
    __shared__ float red[8];
    int n = blockIdx.x, tid = threadIdx.x;
    int s = n >> 3;
    int c0 = tid, c1 = tid + 256;
    float p0 = (s > 0) ? g_prev[(size_t)(n - Bb) * Cc + c0] : 0.f;
    float p1 = (s > 0) ? g_prev[(size_t)(n - Bb) * Cc + c1] : 0.f;
    float x0 = p0 + g_pe[c0 * CHK + 0];
    float x1 = p1 + g_pe[c1 * CHK + 0];
    float2 y = block_ln2(x0, x1, c0, c1, g, b, red);
    g_q0[(size_t)n * Cc + c0] = y.x;
    g_q0[(size_t)n * Cc + c1] = y.y;
    u16 h, l;
    split1(y.x, h, l); u_q0h[(size_t)n * Cc + c0] = h; u_q0l[(size_t)n * Cc + c0] = l;
    split1(y.y, h, l); u_q0h[(size_t)n * Cc + c1] = h; u_q0l[(size_t)n * Cc + c1] = l;
}

__global__ void __launch_bounds__(256) scatterA2_k(const float* __restrict__ zhat,
                                                   float* __restrict__ out)
{
    __shared__ float tile[16][513];
    int blk = blockIdx.x, tid = threadIdx.x;
    int s = blk >> 3, bb = blk & 7;
    int n0 = s * 128 + bb * 16;
#pragma unroll
    for (int l = 0; l < 32; l++) {
        int e = tid + l * 256;
        int t = e >> 9, c = e & 511;
        float v = zhat[((size_t)(n0 + t)) * Cc + c];
        tile[t][c] = v;
        if (t == 15) g_prev[(size_t)(s * 8 + bb) * Cc + c] = v;
    }
    __syncthreads();
#pragma unroll
    for (int l = 0; l < 8; l++) {
        int e = tid + l * 256;
        int c = e >> 2, seg = e & 3;
        float4 v = make_float4(tile[seg * 4 + 0][c], tile[seg * 4 + 1][c],
                               tile[seg * 4 + 2][c], tile[seg * 4 + 3][c]);
        *(float4*)(out + ((size_t)(bb * Cc + c)) * Tt + s * CHK + seg * 4) = v;
    }
}

__global__ void scatterB_k(const float* __restrict__ zh0, float* __restrict__ out)
{
    int idx = blockIdx.x * 256 + threadIdx.x;
    int n = idx >> 9, c = idx & 511;
    int s = n >> 3, bb = n & 7;
    out[((size_t)(bb * Cc + c)) * Tt + s * CHK] = zh0[(size_t)idx];
}

// ---------------- split-bf16 GEMM: cp.async staging + ldmatrix frags ----------------
#define GB_SMEM (2 * 40960)

__device__ __forceinline__ void gb_stage(uint32_t sbase,
    const u16* __restrict__ Ah, const u16* __restrict__ Al,
    const u16* __restrict__ Bh, const u16* __restrict__ Bl,
    int m0, int n0, int M, int N, int K, int k0, int tid)
{
#pragma unroll
    for (int l = 0; l < 2; l++) {
        int e = tid + l * 256;
        int row = e >> 2, seg = e & 3;
        uint32_t d = sbase + row * 80 + seg * 16;
        size_t oa = (size_t)(m0 + row) * K + k0 + seg * 8;
        int szA = (m0 + row < M) ? 16 : 0;
        cpa16(d,         Ah + oa, szA);
        cpa16(d + 10240, Al + oa, szA);
        size_t ob = (size_t)(n0 + row) * K + k0 + seg * 8;
        int szB = (n0 + row < N) ? 16 : 0;
        cpa16(d + 20480, Bh + ob, szB);
        cpa16(d + 30720, Bl + ob, szB);
    }
    asm volatile("cp.async.commit_group;" ::: "memory");
}

__global__ void __launch_bounds__(256) gemm_b_k(
    const u16* __restrict__ Ah, const u16* __restrict__ Al,
    const u16* __restrict__ Bh, const u16* __restrict__ Bl,
    float* __restrict__ Cm, u16* __restrict__ Chi, u16* __restrict__ Clo,
    const float* __restrict__ bias, const float* __restrict__ resid,
    int M, int N, int K, int act, int rmode)
{
    extern __shared__ char smem[];
    uint32_t sb = smem_u32(smem);
    int tid = threadIdx.x, wid = tid >> 5, lane = tid & 31;
    int g = lane >> 2, tg = lane & 3;
    int wm = (wid >> 2) * 64, wn = (wid & 3) * 32;
    int m0 = blockIdx.y * 128, n0 = blockIdx.x * 128;

    float acc[4][4][4];
#pragma unroll
    for (int i = 0; i < 4; i++)
#pragma unroll
        for (int j = 0; j < 4; j++)
#pragma unroll
            for (int r = 0; r < 4; r++) acc[i][j][r] = 0.f;

    uint32_t aOffH = (uint32_t)(wm + (lane & 15)) * 80 + ((lane >> 4) & 1) * 16;
    uint32_t aOffL = aOffH + 10240;
    uint32_t bOffH = 20480u + (uint32_t)(wn + ((lane >> 4) & 1) * 8 + (lane & 7)) * 80
                   + ((lane >> 3) & 1) * 16;
    uint32_t bOffL = bOffH + 10240;

    int nch = K >> 5;
    gb_stage(sb, Ah, Al, Bh, Bl, m0, n0, M, N, K, 0, tid);

    for (int c = 0; c < nch; c++) {
        asm volatile("cp.async.wait_group 0;" ::: "memory");
        __syncthreads();
        if (c + 1 < nch)
            gb_stage(sb + ((c + 1) & 1) * 40960, Ah, Al, Bh, Bl,
                     m0, n0, M, N, K, (c + 1) * 32, tid);

        uint32_t sbuf = sb + (c & 1) * 40960;
#pragma unroll
        for (int ks = 0; ks < 2; ks++) {
            uint32_t kb = ks * 32;
            uint32_t bh[4][2], bl[4][2];
#pragma unroll
            for (int nfp = 0; nfp < 2; nfp++) {
                ldsm4(bh[2*nfp][0], bh[2*nfp][1], bh[2*nfp+1][0], bh[2*nfp+1][1],
                      sbuf + bOffH + nfp * 1280 + kb);
                ldsm4(bl[2*nfp][0], bl[2*nfp][1], bl[2*nfp+1][0], bl[2*nfp+1][1],
                      sbuf + bOffL + nfp * 1280 + kb);
            }
#pragma unroll
            for (int mf = 0; mf < 4; mf++) {
                uint32_t ah[4], al[4];
                ldsm4(ah[0], ah[1], ah[2], ah[3], sbuf + aOffH + mf * 1280 + kb);
                ldsm4(al[0], al[1], al[2], al[3], sbuf + aOffL + mf * 1280 + kb);
#pragma unroll
                for (int nf = 0; nf < 4; nf++) {
                    mma_bf16(acc[mf][nf], ah, bl[nf]);
                    mma_bf16(acc[mf][nf], al, bh[nf]);
                    mma_bf16(acc[mf][nf], ah, bh[nf]);
                }
            }
        }
        // NOTE: no trailing __syncthreads needed — next iteration's
        // wait_group+__syncthreads orders buffer reuse.
    }

#pragma unroll
    for (int mf = 0; mf < 4; mf++) {
        int mA = m0 + wm + mf * 16 + g;
#pragma unroll
        for (int nf = 0; nf < 4; nf++) {
            int nc = n0 + wn + nf * 8 + 2 * tg;
#pragma unroll
            for (int half = 0; half < 2; half++) {
                int m = mA + half * 8;
                if (m >= M) continue;
#pragma unroll
                for (int jj = 0; jj < 2; jj++) {
                    int nn = nc + jj;
                    if (nn >= N) continue;
                    float v = acc[mf][nf][half * 2 + jj];
                    if (bias)  v += bias[nn];
                    if (rmode == 1) v += resid[(size_t)m * N + nn];
                    else if (rmode == 2) v += resid[(size_t)(m & 15) * 512 + nn];
                    if (act == 1) v = geluf(v);
                    if (Chi) {
                        u16 h, l; split1(v, h, l);
                        Chi[(size_t)m * N + nn] = h;
                        Clo[(size_t)m * N + nn] = l;
                    } else {
                        Cm[(size_t)m * N + nn] = v;
                    }
                }
            }
        }
    }
}

// ---------------- attention ----------------
__global__ void __launch_bounds__(256) attnA_k(const float* __restrict__ Kmat,
                                               const float* __restrict__ Vmat)
{
    __shared__ float sKV[16][514];
    __shared__ float sS[16 * 8 * 16];
    int blk = blockIdx.x, tid = threadIdx.x;
    size_t n0 = (size_t)blk * CHK;

    for (int e = tid; e < 16 * 512; e += 256)
        sKV[e >> 9][e & 511] = Kmat[n0 * Cc + (size_t)(e >> 9) * Cc + (e & 511)];
    __syncthreads();
    {
        int t = tid >> 4, k = tid & 15;
        const float* qrow = g_Qc + t * Cc;
#pragma unroll
        for (int h = 0; h < 8; h++) {
            float s = 0.f;
            const float* kp = &sKV[k][h * 64];
            const float* qp = qrow + h * 64;
#pragma unroll 16
            for (int d = 0; d < 64; d++) s = fmaf(qp[d], kp[d], s);
            sS[(t * 8 + h) * 16 + k] = s * 0.125f;
        }
    }
    __syncthreads();
    if (tid < 128) {
        float* p = &sS[tid * 16];
        float m = p[0];
#pragma unroll
        for (int k = 1; k < 16; k++) m = fmaxf(m, p[k]);
        float sum = 0.f;
#pragma unroll
        for (int k = 0; k < 16; k++) { float e = expf(p[k] - m); p[k] = e; sum += e; }
        float inv = 1.0f / sum;
#pragma unroll
        for (int k = 0; k < 16; k++) p[k] *= inv;
    }
    __syncthreads();
    for (int e = tid; e < 16 * 512; e += 256)
        sKV[e >> 9][e & 511] = Vmat[n0 * Cc + (size_t)(e >> 9) * Cc + (e & 511)];
    __syncthreads();
#pragma unroll
    for (int cc = 0; cc < 2; cc++) {
        int c = tid + cc * 256;
        int h = c >> 6;
#pragma unroll
        for (int t = 0; t < 16; t++) {
            float a = 0.f;
            const float* at = &sS[(t * 8 + h) * 16];
#pragma unroll
            for (int k = 0; k < 16; k++) a = fmaf(at[k], sKV[k][c], a);
            u16 hh, ll; split1(a, hh, ll);
            u_ctxh[(n0 + t) * Cc + c] = hh;
            u_ctxl[(n0 + t) * Cc + c] = ll;
        }
    }
}

__global__ void __launch_bounds__(256) attnB_k(const float* __restrict__ Kmat,
                                               const float* __restrict__ Vmat)
{
    __shared__ float sKV[16][514];
    __shared__ float sS[8 * 16];
    int blk = blockIdx.x, tid = threadIdx.x;
    size_t n0 = (size_t)blk * CHK;

    for (int e = tid; e < 16 * 512; e += 256)
        sKV[e >> 9][e & 511] = Kmat[n0 * Cc + (size_t)(e >> 9) * Cc + (e & 511)];
    __syncthreads();
    if (tid < 128) {
        int h = tid >> 4, k = tid & 15;
        const float* qp = g_Q0 + (size_t)blk * Cc + h * 64;
        const float* kp = &sKV[k][h * 64];
        float s = 0.f;
#pragma unroll 16
        for (int d = 0; d < 64; d++) s = fmaf(qp[d], kp[d], s);
        sS[h * 16 + k] = s * 0.125f;
    }
    __syncthreads();
    if (tid < 8) {
        float* p = &sS[tid * 16];
        float m = p[0];
#pragma unroll
        for (int k = 1; k < 16; k++) m = fmaxf(m, p[k]);
        float sum = 0.f;
#pragma unroll
        for (int k = 0; k < 16; k++) { float e = expf(p[k] - m); p[k] = e; sum += e; }
        float inv = 1.0f / sum;
#pragma unroll
        for (int k = 0; k < 16; k++) p[k] *= inv;
    }
    __syncthreads();
    for (int e = tid; e < 16 * 512; e += 256)
        sKV[e >> 9][e & 511] = Vmat[n0 * Cc + (size_t)(e >> 9) * Cc + (e & 511)];
    __syncthreads();
#pragma unroll
    for (int cc = 0; cc < 2; cc++) {
        int c = tid + cc * 256;
        int h = c >> 6;
        float a = 0.f;
        const float* at = &sS[h * 16];
#pragma unroll
        for (int k = 0; k < 16; k++) a = fmaf(at[k], sKV[k][c], a);
        u16 hh, ll; split1(a, hh, ll);
        u_ctx0h[(size_t)blk * Cc + c] = hh;
        u_ctx0l[(size_t)blk * Cc + c] = ll;
    }
}

// ---------------- residual VQ: tensor-core scoring, double-buffered book tiles ----------------
// smem layout (byte offsets):
//  0       sRes fp32 [64][97]             24832
//  24832   sAh  [64 rows x 208B]          13312
//  38144   sAl                            13312
//  51456   sBh0 [64 codes x 208B]         13312
//  64768   sBl0                           13312
//  78080   sBh1                           13312
//  91392   sBl1                           13312
//  104704  sHN fp32 [2][64]               512
//  105216  sScore fp32 [64][8]            2048
//  107264  sIdx int [64][8]               2048
//  109312  sBest int [64]                 256
#define RVQ_SMEM 109568

__device__ __forceinline__ void rvq_prefetch(uint32_t sb, uint32_t dBh, uint32_t dBl,
    const u16* __restrict__ bkh, const u16* __restrict__ bkl,
    float* sHNbuf, int k, int ct, int tid)
{
    const u16* srcH = bkh + ((size_t)k * NEMB + ct * 64) * CD;
    const u16* srcL = bkl + ((size_t)k * NEMB + ct * 64) * CD;
#pragma unroll
    for (int l = 0; l < 3; l++) {
        int e = tid + l * 256;          // 0..767 : code*12 + seg
        int c = e / 12, s2 = e - c * 12;
        cpa16(sb + dBh + c * 208 + s2 * 16, srcH + c * 96 + s2 * 8, 16);
        cpa16(sb + dBl + c * 208 + s2 * 16, srcL + c * 96 + s2 * 8, 16);
    }
    asm volatile("cp.async.commit_group;" ::: "memory");
    if (tid < 64) sHNbuf[tid] = g_cnorm[k * NEMB + ct * 64 + tid];
}

__global__ void __launch_bounds__(256) rvq_k(const float* __restrict__ rD,
                                             u16* __restrict__ qh, u16* __restrict__ ql,
                                             const float* __restrict__ books,
                                             const u16* __restrict__ bkh,
                                             const u16* __restrict__ bkl)
{
    extern __shared__ char sm[];
    float* sRes  = (float*)sm;
    uint32_t sb  = smem_u32(sm);
    const uint32_t oAh = 24832, oAl = 38144;
    const uint32_t oBhArr[2] = { 51456, 78080 };
    const uint32_t oBlArr[2] = { 64768, 91392 };
    float* sHN    = (float*)(sm + 104704);   // [2][64]
    float* sScore = (float*)(sm + 105216);
    int*   sIdx   = (int*)  (sm + 107264);
    int*   sBest  = (int*)  (sm + 109312);

    int tid = threadIdx.x, wid = tid >> 5, lane = tid & 31;
    int g = lane >> 2, tg = lane & 3;
    int m0 = blockIdx.x * 64;

    for (int e = tid; e < 64 * 96; e += 256) {
        int r = e / 96, d = e - r * 96;
        sRes[r * 97 + d] = rD[(size_t)(m0 + r) * CD + d];
    }

    uint32_t aoff = (uint32_t)(lane & 15) * 208 + ((lane >> 4) & 1) * 16;
    uint32_t boff = (uint32_t)(wid * 8 + (lane & 7)) * 208 + ((lane >> 3) & 3) * 16;

    for (int k = 0; k < NBOOK; k++) {
        __syncthreads();
        // prefetch tile 0 of this book into buf0 (overlaps the residual split)
        rvq_prefetch(sb, oBhArr[0], oBlArr[0], bkh, bkl, sHN + 0, k, 0, tid);
        // split residual to bf16 hi/lo (A operand)
        for (int e = tid; e < 64 * 48; e += 256) {
            int r = e / 48, w = e - r * 48;
            float v0 = sRes[r * 97 + 2 * w], v1 = sRes[r * 97 + 2 * w + 1];
            uint32_t hi, lo; split2(v0, v1, hi, lo);
            *(uint32_t*)(sm + oAh + r * 208 + w * 4) = hi;
            *(uint32_t*)(sm + oAl + r * 208 + w * 4) = lo;
        }
        float best[8]; int bidx[8];
#pragma unroll
        for (int s = 0; s < 8; s++) { best[s] = -3.0e38f; bidx[s] = 0x7fffffff; }

        for (int ct = 0; ct < 16; ct++) {
            int buf = ct & 1;
            if (ct + 1 < 16) {
                rvq_prefetch(sb, oBhArr[buf ^ 1], oBlArr[buf ^ 1], bkh, bkl,
                             sHN + 64 * (buf ^ 1), k, ct + 1, tid);
                asm volatile("cp.async.wait_group 1;" ::: "memory");
            } else {
                asm volatile("cp.async.wait_group 0;" ::: "memory");
            }
            __syncthreads();

            const uint32_t oBh = oBhArr[buf], oBl = oBlArr[buf];
            const float* sHNb = sHN + 64 * buf;

            float acc[4][4];
#pragma unroll
            for (int i = 0; i < 4; i++)
#pragma unroll
                for (int j = 0; j < 4; j++) acc[i][j] = 0.f;

#pragma unroll
            for (int kcp = 0; kcp < 3; kcp++) {
                uint32_t bhv[4], blv[4];
                ldsm4(bhv[0], bhv[1], bhv[2], bhv[3], sb + oBh + boff + kcp * 64);
                ldsm4(blv[0], blv[1], blv[2], blv[3], sb + oBl + boff + kcp * 64);
#pragma unroll
                for (int sub = 0; sub < 2; sub++) {
                    uint32_t bh2[2] = { bhv[sub * 2], bhv[sub * 2 + 1] };
                    uint32_t bl2[2] = { blv[sub * 2], blv[sub * 2 + 1] };
                    uint32_t ka = (uint32_t)(kcp * 2 + sub) * 32;
#pragma unroll
                    for (int mf = 0; mf < 4; mf++) {
                        uint32_t ah4[4], al4[4];
                        ldsm4(ah4[0], ah4[1], ah4[2], ah4[3],
                              sb + oAh + aoff + (uint32_t)mf * 16 * 208 + ka);
                        ldsm4(al4[0], al4[1], al4[2], al4[3],
                              sb + oAl + aoff + (uint32_t)mf * 16 * 208 + ka);
                        mma_bf16(acc[mf], ah4, bl2);
                        mma_bf16(acc[mf], al4, bh2);
                        mma_bf16(acc[mf], ah4, bh2);
                    }
                }
            }
#pragma unroll
            for (int mf = 0; mf < 4; mf++)
#pragma unroll
                for (int h = 0; h < 2; h++) {
                    int s = mf * 2 + h;
#pragma unroll
                    for (int j = 0; j < 2; j++) {
                        int cl = wid * 8 + 2 * tg + j;
                        float sc = acc[mf][h * 2 + j] - sHNb[cl];
                        int code = ct * 64 + cl;
                        if (sc > best[s] || (sc == best[s] && code < bidx[s])) {
                            best[s] = sc; bidx[s] = code;
                        }
                    }
                }
            __syncthreads();   // protect buf (and sHN slot) before next prefetch overwrites
        }
        // reduce across tg lanes (same rows)
#pragma unroll
        for (int s = 0; s < 8; s++) {
#pragma unroll
            for (int off = 1; off <= 2; off <<= 1) {
                float os = __shfl_xor_sync(0xffffffffu, best[s], off);
                int   oi = __shfl_xor_sync(0xffffffffu, bidx[s], off);
                if (os > best[s] || (os == best[s] && oi < bidx[s])) {
                    best[s] = os; bidx[s] = oi;
                }
            }
        }
        if (tg == 0) {
#pragma unroll
            for (int mf = 0; mf < 4; mf++)
#pragma unroll
                for (int h = 0; h < 2; h++) {
                    int r = mf * 16 + 8 * h + g;
                    sScore[r * 8 + wid] = best[mf * 2 + h];
                    sIdx[r * 8 + wid]   = bidx[mf * 2 + h];
                }
        }
        __syncthreads();
        if (tid < 64) {
            float bs = -3.0e38f; int bi = 0x7fffffff;
#pragma unroll
            for (int w = 0; w < 8; w++) {
                float s2 = sScore[tid * 8 + w]; int ii = sIdx[tid * 8 + w];
                if (s2 > bs || (s2 == bs && ii < bi)) { bs = s2; bi = ii; }
            }
            sBest[tid] = bi;
        }
        __syncthreads();
        const float* bkb = books + (size_t)k * NEMB * CD;
        for (int e = tid; e < 64 * 96; e += 256) {
            int r = e / 96, d = e - r * 96;
            sRes[r * 97 + d] -= bkb[(size_t)sBest[r] * CD + d];
        }
    }
    __syncthreads();
    for (int e = tid; e < 64 * 96; e += 256) {
        int r = e / 96, d = e - r * 96;
        float v = rD[(size_t)(m0 + r) * CD + d] - sRes[r * 97 + d];
        u16 h, l; split1(v, h, l);
        qh[(size_t)(m0 + r) * CD + d] = h;
        ql[(size_t)(m0 + r) * CD + d] = l;
    }
}

// ---------------- host side ----------------
template<typename T>
static T* sym(const void* s) { void* p = nullptr; cudaGetSymbolAddress(&p, s); return (T*)p; }

static void gemmb(const u16* Ah, const u16* Al, const u16* Bh, const u16* Bl,
                  float* Cm, u16* Chi, u16* Clo,
                  const float* bias, const float* resid,
                  int M, int N, int K, int act, int rmode)
{
    static bool attr = false;
    if (!attr) {
        cudaFuncSetAttribute(gemm_b_k, cudaFuncAttributeMaxDynamicSharedMemorySize, GB_SMEM);
        attr = true;
    }
    dim3 grid((N + 127) / 128, (M + 127) / 128);
    gemm_b_k<<<grid, 256, GB_SMEM>>>(Ah, Al, Bh, Bl, Cm, Chi, Clo, bias, resid,
                                     M, N, K, act, rmode);
}

extern "C" void kernel_launch(void* const* d_in, const int* in_sizes, int n_in,
                              void* d_out, int out_size)
{
    const float* qa    = (const float*)d_in[0];
    const float* zt    = (const float*)d_in[1];
    const float* lnq_g = (const float*)d_in[2];
    const float* lnq_b = (const float*)d_in[3];
    const float* lnkv_g= (const float*)d_in[4];
    const float* lnkv_b= (const float*)d_in[5];
    const float* Wq    = (const float*)d_in[6];
    const float* Wk    = (const float*)d_in[7];
    const float* Wv    = (const float*)d_in[8];
    const float* Wo    = (const float*)d_in[9];
    const float* ffn_g = (const float*)d_in[10];
    const float* ffn_b = (const float*)d_in[11];
    const float* W1    = (const float*)d_in[12];
    const float* b1    = (const float*)d_in[13];
    const float* W2    = (const float*)d_in[14];
    const float* b2    = (const float*)d_in[15];
    const float* tn_g  = (const float*)d_in[16];
    const float* tn_b  = (const float*)d_in[17];
    const float* scale = (const float*)d_in[18];
    const float* Wd    = (const float*)d_in[19];
    const float* bd    = (const float*)d_in[20];
    const float* Wu    = (const float*)d_in[21];
    const float* bu    = (const float*)d_in[22];
    const float* books = (const float*)d_in[23];
    float* out = (float*)d_out;

    float* p_Qc  = sym<float>(g_Qc);
    float* p_K   = sym<float>(g_K);
    float* p_V   = sym<float>(g_V);
    float* p_y   = sym<float>(g_y);
    float* p_rD  = sym<float>(g_rD);
    float* p_zh  = sym<float>(g_zhat);
    float* p_qln = sym<float>(g_qln);
    float* p_q0  = sym<float>(g_q0);
    float* p_Q0  = sym<float>(g_Q0);
    float* p_y0  = sym<float>(g_y0);
    float* p_rD0 = sym<float>(g_rD0);
    float* p_zh0 = sym<float>(g_zh0);

    u16* qlh = sym<u16>(u_qlnh); u16* qll = sym<u16>(u_qlnl);
    u16* kvh = sym<u16>(u_kvh);  u16* kvl = sym<u16>(u_kvl);
    u16* cth = sym<u16>(u_ctxh); u16* ctl = sym<u16>(u_ctxl);
    u16* lnh = sym<u16>(u_lnh);  u16* lnl = sym<u16>(u_lnl);
    u16* hh  = sym<u16>(u_hh);   u16* hl  = sym<u16>(u_hl);
    u16* xdh = sym<u16>(u_xdh);  u16* xdl = sym<u16>(u_xdl);
    u16* qdh = sym<u16>(u_qdh);  u16* qdl = sym<u16>(u_qdl);
    u16* q0h = sym<u16>(u_q0h);  u16* q0l = sym<u16>(u_q0l);
    u16* c0h = sym<u16>(u_ctx0h);u16* c0l = sym<u16>(u_ctx0l);
    u16* l0h = sym<u16>(u_ln0h); u16* l0l = sym<u16>(u_ln0l);
    u16* h0h = sym<u16>(u_h0h);  u16* h0l = sym<u16>(u_h0l);
    u16* x0h = sym<u16>(u_xd0h); u16* x0l = sym<u16>(u_xd0l);
    u16* d0h = sym<u16>(u_qd0h); u16* d0l = sym<u16>(u_qd0l);

    u16* wqh = sym<u16>(w_qh); u16* wql = sym<u16>(w_ql);
    u16* wkh = sym<u16>(w_kh); u16* wkl = sym<u16>(w_kl);
    u16* wvh = sym<u16>(w_vh); u16* wvl = sym<u16>(w_vl);
    u16* woh = sym<u16>(w_oh); u16* wol = sym<u16>(w_ol);
    u16* w1h = sym<u16>(w_1h); u16* w1l = sym<u16>(w_1l);
    u16* w2h = sym<u16>(w_2h); u16* w2l = sym<u16>(w_2l);
    u16* wdh = sym<u16>(w_dh); u16* wdl = sym<u16>(w_dl);
    u16* wuh = sym<u16>(w_uh); u16* wul = sym<u16>(w_ul);
    u16* bkh = sym<u16>(bk_h); u16* bkl = sym<u16>(bk_l);

    cudaFuncSetAttribute(rvq_k, cudaFuncAttributeMaxDynamicSharedMemorySize, RVQ_SMEM);

    // ---- weight / book prep ----
    wsplit4T_k<<<4096, 256>>>(Wq, Wk, Wv, Wo, wqh, wql, wkh, wkl, wvh, wvl, woh, wol);
    wsplitT_k<<<(512 * 1024 + 255) / 256, 256>>>(W1, w1h, w1l, 512, 1024);
    wsplitT_k<<<(1024 * 512 + 255) / 256, 256>>>(W2, w2h, w2l, 1024, 512);
    wsplit_k<<<(96 * 512 + 255) / 256, 256>>>(Wd, wdh, wdl, 96 * 512);
    wsplit_k<<<(512 * 96 + 255) / 256, 256>>>(Wu, wuh, wul, 512 * 96);
    wsplit_k<<<(NBOOK * NEMB * CD + 255) / 256, 256>>>(books, bkh, bkl, NBOOK * NEMB * CD);

    // ---- prep ----
    prep_pe_qln_k<<<16, 256>>>(lnq_g, lnq_b);
    prep_cnorm_k<<<32, 256>>>(books);
    kvln2_k<<<M2, 256>>>(qa, lnkv_g, lnkv_b);

    // ---- pass A ----
    gemmb(qlh, qll, wqh, wql, p_Qc, nullptr, nullptr, nullptr, nullptr, 16, 512, 512, 0, 0);
    gemmb(kvh, kvl, wkh, wkl, p_K, nullptr, nullptr, nullptr, nullptr, MR, 512, 512, 0, 0);
    gemmb(kvh, kvl, wvh, wvl, p_V, nullptr, nullptr, nullptr, nullptr, MR, 512, 512, 0, 0);
    attnA_k<<<M2, 256>>>(p_K, p_V);
    gemmb(cth, ctl, woh, wol, p_y, nullptr, nullptr, nullptr, p_qln, MR, 512, 512, 0, 2);
    ln_rows_k<<<MR, 256>>>(p_y, lnh, lnl, ffn_g, ffn_b);
    gemmb(lnh, lnl, w1h, w1l, nullptr, hh, hl, b1, nullptr, MR, 1024, 512, 1, 0);
    gemmb(hh, hl, w2h, w2l, p_y, nullptr, nullptr, b2, p_y, MR, 512, 1024, 0, 1);
    residA2_k<<<M2, 256>>>(zt, p_y, tn_g, tn_b, scale);
    gemmb(xdh, xdl, wdh, wdl, p_rD, nullptr, nullptr, bd, nullptr, MR, 96, 512, 0, 0);
    rvq_k<<<MR / 64, 256, RVQ_SMEM>>>(p_rD, qdh, qdl, books, bkh, bkl);
    gemmb(qdh, qdl, wuh, wul, p_zh, nullptr, nullptr, bu, p_y, MR, 512, 96, 0, 1);
    scatterA2_k<<<M2, 256>>>(p_zh, out);

    // ---- pass B ----
    q0ln_k<<<M2, 256>>>(lnq_g, lnq_b);
    gemmb(q0h, q0l, wqh, wql, p_Q0, nullptr, nullptr, nullptr, nullptr, M2, 512, 512, 0, 0);
    attnB_k<<<M2, 256>>>(p_K, p_V);
    gemmb(c0h, c0l, woh, wol, p_y0, nullptr, nullptr, nullptr, p_q0, M2, 512, 512, 0, 1);
    ln_rows_k<<<M2, 256>>>(p_y0, l0h, l0l, ffn_g, ffn_b);
    gemmb(l0h, l0l, w1h, w1l, nullptr, h0h, h0l, b1, nullptr, M2, 1024, 512, 1, 0);
    gemmb(h0h, h0l, w2h, w2l, p_y0, nullptr, nullptr, b2, p_y0, M2, 512, 1024, 0, 1);
    residB_k<<<M2, 256>>>(zt, p_y0, tn_g, tn_b, scale);
    gemmb(x0h, x0l, wdh, wdl, p_rD0, nullptr, nullptr, bd, nullptr, M2, 96, 512, 0, 0);
    rvq_k<<<M2 / 64, 256, RVQ_SMEM>>>(p_rD0, d0h, d0l, books, bkh, bkl);
    gemmb(d0h, d0l, wuh, wul, p_zh0, nullptr, nullptr, bu, p_y0, M2, 512, 96, 0, 1);
    scatterB_k<<<M2 * Cc / 256, 256>>>(p_zh0, out);
}